// round 6
// baseline (speedup 1.0000x reference)
#include <cuda_runtime.h>
#include <mma.h>
using namespace nvcuda;

// Problem constants: B=8, H=W=128, C=256, NUM_HEADS=8, HD=32, WINDOW=8
#define TOKENS 131072

// Scratch (allocation-free rule: device globals)
__device__ float g_qkv[100663296u];  // [token][3][head][32]
__device__ float g_att[33554432u];   // xt (pre-GEMM1) then att [token][256]
__device__ float g_wq[196608];       // tf32-rounded W_qkv
__device__ float g_wp[65536];        // tf32-rounded W_proj

__device__ __forceinline__ float t32(float x) { return wmma::__float_to_tf32(x); }

__device__ __forceinline__ void cp_async16(void* smem, const void* gmem) {
    unsigned s = (unsigned)__cvta_generic_to_shared(smem);
    asm volatile("cp.async.cg.shared.global [%0], [%1], 16;\n" :: "r"(s), "l"(gmem));
}
__device__ __forceinline__ void cp_commit() { asm volatile("cp.async.commit_group;\n"); }
__device__ __forceinline__ void cp_wait1()  { asm volatile("cp.async.wait_group 1;\n"); }
__device__ __forceinline__ void cp_wait0()  { asm volatile("cp.async.wait_group 0;\n"); }

// ---------------------------------------------------------------------------
// Pre-round inputs to tf32 (RN) once: x -> xt, weights -> g_wq/g_wp.
// ---------------------------------------------------------------------------
__global__ void cvt_inputs(const float* __restrict__ x,
                           const float* __restrict__ wq,
                           const float* __restrict__ wp,
                           float* __restrict__ xt,
                           float* __restrict__ wqt,
                           float* __restrict__ wpt)
{
    const int stride = gridDim.x * blockDim.x;
    const int tid0 = blockIdx.x * blockDim.x + threadIdx.x;
    for (int i = tid0; i < 33554432 / 4; i += stride) {
        float4 v = ((const float4*)x)[i];
        v.x = t32(v.x); v.y = t32(v.y); v.z = t32(v.z); v.w = t32(v.w);
        ((float4*)xt)[i] = v;
    }
    for (int i = tid0; i < (196608 + 65536) / 4; i += stride) {
        if (i < 49152) {
            float4 v = ((const float4*)wq)[i];
            v.x = t32(v.x); v.y = t32(v.y); v.z = t32(v.z); v.w = t32(v.w);
            ((float4*)wqt)[i] = v;
        } else {
            float4 v = ((const float4*)wp)[i - 49152];
            v.x = t32(v.x); v.y = t32(v.y); v.z = t32(v.z); v.w = t32(v.w);
            ((float4*)wpt)[i - 49152] = v;
        }
    }
}

// ---------------------------------------------------------------------------
// TF32 GEMM: C[M,N]=A[M,256]@B[256,N] (+bias). Inputs pre-rounded: NO CVTs.
// BM=BN=128, BK=32, 3-stage cp.async. 8 warps, 64x32 warp tile.
// ---------------------------------------------------------------------------
__global__ __launch_bounds__(256, 2) void gemm_wmma(
    const float* __restrict__ A, const float* __restrict__ B,
    const float* __restrict__ bias, float* __restrict__ C, int N)
{
    extern __shared__ float sm[];
    const int tid  = threadIdx.x;
    const int warp = tid >> 5;
    const int lane = tid & 31;
    const int wm = warp >> 2, wn = warp & 3;
    const int bn = blockIdx.x * 128;   // fast dim = cols -> A L2 reuse
    const int bm = blockIdx.y * 128;

    wmma::fragment<wmma::accumulator, 16, 16, 8, float> acc[4][2];
#pragma unroll
    for (int i = 0; i < 4; i++)
#pragma unroll
        for (int j = 0; j < 2; j++) wmma::fill_fragment(acc[i][j], 0.f);

    auto load_tile = [&](int s, int k0) {
        float* As = sm + s * 8832;
        float* Bs = As + 4608;
#pragma unroll
        for (int t = 0; t < 4; t++) {
            int idx = tid + t * 256;                 // 0..1023
            int ar = idx >> 3, ac = (idx & 7) * 4;   // A: 128x32
            cp_async16(&As[ar * 36 + ac], A + (size_t)(bm + ar) * 256 + k0 + ac);
            int br = idx >> 5, bc = (idx & 31) * 4;  // B: 32x128
            cp_async16(&Bs[br * 132 + bc], B + (size_t)(k0 + br) * N + bn + bc);
        }
        cp_commit();
    };

    load_tile(0, 0);
    load_tile(1, 32);
    const int NK = 8;  // 256/32
    for (int kt = 0; kt < NK; kt++) {
        if (kt == NK - 1) cp_wait0(); else cp_wait1();
        __syncthreads();
        if (kt + 2 < NK) load_tile((kt + 2) % 3, (kt + 2) * 32);
        const float* As = sm + (kt % 3) * 8832;
        const float* Bs = As + 4608;
#pragma unroll
        for (int kk = 0; kk < 32; kk += 8) {
            wmma::fragment<wmma::matrix_a, 16, 16, 8, wmma::precision::tf32,
                           wmma::row_major> af[4];
            wmma::fragment<wmma::matrix_b, 16, 16, 8, wmma::precision::tf32,
                           wmma::row_major> bf[2];
#pragma unroll
            for (int i = 0; i < 4; i++)
                wmma::load_matrix_sync(af[i], &As[(wm * 64 + i * 16) * 36 + kk], 36);
#pragma unroll
            for (int j = 0; j < 2; j++)
                wmma::load_matrix_sync(bf[j], &Bs[kk * 132 + wn * 32 + j * 16], 132);
#pragma unroll
            for (int i = 0; i < 4; i++)
#pragma unroll
                for (int j = 0; j < 2; j++)
                    wmma::mma_sync(acc[i][j], af[i], bf[j], acc[i][j]);
        }
    }
    __syncthreads();

    // Epilogue via private smem strip
    float* wb = sm + warp * 320;   // 16 x 20
    const int r = lane >> 1, c0 = (lane & 1) * 8;
#pragma unroll
    for (int i = 0; i < 4; i++) {
#pragma unroll
        for (int j = 0; j < 2; j++) {
            wmma::store_matrix_sync(wb, acc[i][j], 20, wmma::mem_row_major);
            __syncwarp();
            float4 v0 = *(float4*)&wb[r * 20 + c0];
            float4 v1 = *(float4*)&wb[r * 20 + c0 + 4];
            int grow = bm + wm * 64 + i * 16 + r;
            int gcol = bn + wn * 32 + j * 16 + c0;
            if (bias) {
                v0.x += bias[gcol + 0]; v0.y += bias[gcol + 1];
                v0.z += bias[gcol + 2]; v0.w += bias[gcol + 3];
                v1.x += bias[gcol + 4]; v1.y += bias[gcol + 5];
                v1.z += bias[gcol + 6]; v1.w += bias[gcol + 7];
            }
            *(float4*)&C[(size_t)grow * N + gcol]     = v0;
            *(float4*)&C[(size_t)grow * N + gcol + 4] = v1;
            __syncwarp();
        }
    }
}

// ---------------------------------------------------------------------------
// Local window attention (heads 0..3). CTA = 1 window x 2 heads. 256 thr.
// ---------------------------------------------------------------------------
__global__ __launch_bounds__(256, 2) void attn_local_tc(
    const float* __restrict__ qkv, float* __restrict__ att)
{
    extern __shared__ float sm[];
    const int wid = blockIdx.x;
    const int b = wid >> 8, wy = (wid >> 4) & 15, wx = wid & 15;
    const int tid = threadIdx.x;
    const int warp = tid >> 5;
    const int hh = warp >> 2, wl = warp & 3;
    const float scale = 0.17677669529663687f;

#pragma unroll
    for (int i = 0; i < 4; i++) {
        int idx = tid + i * 256;           // 0..1023
        int h2 = idx >> 9;
        int r  = (idx >> 3) & 63;
        int c  = (idx & 7) * 4;
        int hg = (int)blockIdx.y * 2 + h2;
        size_t token = ((size_t)(b * 128 + wy * 8 + (r >> 3))) * 128 + wx * 8 + (r & 7);
        const float* base = qkv + token * 768 + hg * 32 + c;
        float4 q4 = *(const float4*)base;
        float4 k4 = *(const float4*)(base + 256);
        float4 v4 = *(const float4*)(base + 512);
        float* Q = sm + h2 * 11200;
        float* Kt = Q + 2304;
        float* V = Q + 4480;
        Q[r * 36 + c + 0] = t32(q4.x * scale);
        Q[r * 36 + c + 1] = t32(q4.y * scale);
        Q[r * 36 + c + 2] = t32(q4.z * scale);
        Q[r * 36 + c + 3] = t32(q4.w * scale);
        Kt[(c + 0) * 68 + r] = t32(k4.x);
        Kt[(c + 1) * 68 + r] = t32(k4.y);
        Kt[(c + 2) * 68 + r] = t32(k4.z);
        Kt[(c + 3) * 68 + r] = t32(k4.w);
        V[r * 36 + c + 0] = t32(v4.x);
        V[r * 36 + c + 1] = t32(v4.y);
        V[r * 36 + c + 2] = t32(v4.z);
        V[r * 36 + c + 3] = t32(v4.w);
    }
    __syncthreads();

    float* Qh  = sm + hh * 11200;
    float* Kth = Qh + 2304;
    float* Vh  = Qh + 4480;
    float* Sh  = Qh + 6784;

    {   // S = Q @ K^T  (64x64, k=32)
        wmma::fragment<wmma::accumulator, 16, 16, 8, float> accS[4];
#pragma unroll
        for (int j = 0; j < 4; j++) wmma::fill_fragment(accS[j], 0.f);
#pragma unroll
        for (int kk = 0; kk < 32; kk += 8) {
            wmma::fragment<wmma::matrix_a, 16, 16, 8, wmma::precision::tf32,
                           wmma::row_major> af;
            wmma::load_matrix_sync(af, &Qh[(wl * 16) * 36 + kk], 36);
#pragma unroll
            for (int j = 0; j < 4; j++) {
                wmma::fragment<wmma::matrix_b, 16, 16, 8, wmma::precision::tf32,
                               wmma::row_major> bf;
                wmma::load_matrix_sync(bf, &Kth[kk * 68 + j * 16], 68);
                wmma::mma_sync(accS[j], af, bf, accS[j]);
            }
        }
#pragma unroll
        for (int j = 0; j < 4; j++)
            wmma::store_matrix_sync(&Sh[(wl * 16) * 68 + j * 16], accS[j], 68,
                                    wmma::mem_row_major);
    }
    __syncthreads();

    {   // softmax: 2 thr/row
        int h2 = tid >> 7, local = tid & 127;
        int row = local >> 1, half = local & 1;
        float* S = sm + h2 * 11200 + 6784 + row * 68 + half * 32;
        float m = -3.0e38f;
#pragma unroll
        for (int e = 0; e < 32; e++) m = fmaxf(m, S[e]);
        m = fmaxf(m, __shfl_xor_sync(0xffffffffu, m, 1));
        float sum = 0.f;
#pragma unroll
        for (int e = 0; e < 32; e++) {
            float p = __expf(S[e] - m);
            S[e] = t32(p);
            sum += p;
        }
        sum += __shfl_xor_sync(0xffffffffu, sum, 1);
        if (half == 0) (sm + h2 * 11200 + 11136)[row] = 1.f / sum;
    }
    __syncthreads();

    {   // O = P @ V  (64x32, k=64)
        wmma::fragment<wmma::accumulator, 16, 16, 8, float> accO[2];
#pragma unroll
        for (int j = 0; j < 2; j++) wmma::fill_fragment(accO[j], 0.f);
#pragma unroll
        for (int kk = 0; kk < 64; kk += 8) {
            wmma::fragment<wmma::matrix_a, 16, 16, 8, wmma::precision::tf32,
                           wmma::row_major> af;
            wmma::load_matrix_sync(af, &Sh[(wl * 16) * 68 + kk], 68);
#pragma unroll
            for (int j = 0; j < 2; j++) {
                wmma::fragment<wmma::matrix_b, 16, 16, 8, wmma::precision::tf32,
                               wmma::row_major> bf;
                wmma::load_matrix_sync(bf, &Vh[kk * 36 + j * 16], 36);
                wmma::mma_sync(accO[j], af, bf, accO[j]);
            }
        }
#pragma unroll
        for (int j = 0; j < 2; j++)
            wmma::store_matrix_sync(&Qh[(wl * 16) * 36 + j * 16], accO[j], 36,
                                    wmma::mem_row_major);
    }
    __syncthreads();

#pragma unroll
    for (int i = 0; i < 4; i++) {
        int idx = tid + i * 256;
        int h2 = idx >> 9;
        int r  = (idx >> 3) & 63;
        int c  = (idx & 7) * 4;
        int hg = (int)blockIdx.y * 2 + h2;
        float* Q = sm + h2 * 11200;
        float inv = (sm + h2 * 11200 + 11136)[r];
        float4 o = make_float4(t32(Q[r * 36 + c] * inv), t32(Q[r * 36 + c + 1] * inv),
                               t32(Q[r * 36 + c + 2] * inv), t32(Q[r * 36 + c + 3] * inv));
        size_t token = ((size_t)(b * 128 + wy * 8 + (r >> 3))) * 128 + wx * 8 + (r & 7);
        *(float4*)&att[token * 256 + hg * 32 + c] = o;
    }
}

// ---------------------------------------------------------------------------
// Grid (dilated) attention (heads 4..7). CTA = (cell, head), 512 threads
// (16 warps). K/V staged once; 4 query tiles looped. O=PV k-split across
// warp pairs with smem reduction.
// smem floats: K[256][36]@0, V[256][36]@9216, Q[64][36]@18432,
//              S[64][260]@20736, il[64]@37376, Op[2][64][36]@37440
//              -> 42048 fl = 168192 B.
// ---------------------------------------------------------------------------
__global__ __launch_bounds__(512, 1) void attn_grid_tc(
    const float* __restrict__ qkv, float* __restrict__ att)
{
    extern __shared__ float sm[];
    float* K  = sm;
    float* V  = sm + 9216;
    float* Q  = sm + 18432;
    float* S  = sm + 20736;
    float* il = sm + 37376;
    float* Op = sm + 37440;   // [2][64][36]

    const int cid = blockIdx.x;
    const int b = cid >> 6, s1 = (cid >> 3) & 7, s2 = cid & 7;
    const int h = 4 + (int)blockIdx.y;
    const int tid = threadIdx.x;
    const int warp = tid >> 5;
    const float scale = 0.17677669529663687f;

    // Stage K, V once (256 keys x 32 dims = 2048 float4)
#pragma unroll
    for (int i = 0; i < 4; i++) {
        int idx = tid + i * 512;           // 0..2047
        int rk = idx >> 3, c = (idx & 7) * 4;
        size_t ktok = ((size_t)(b * 128 + (rk >> 4) * 8 + s1)) * 128 + (rk & 15) * 8 + s2;
        const float* base = qkv + ktok * 768 + h * 32 + c;
        float4 k4 = *(const float4*)(base + 256);
        float4 v4 = *(const float4*)(base + 512);
        K[rk * 36 + c + 0] = t32(k4.x);
        K[rk * 36 + c + 1] = t32(k4.y);
        K[rk * 36 + c + 2] = t32(k4.z);
        K[rk * 36 + c + 3] = t32(k4.w);
        V[rk * 36 + c + 0] = t32(v4.x);
        V[rk * 36 + c + 1] = t32(v4.y);
        V[rk * 36 + c + 2] = t32(v4.z);
        V[rk * 36 + c + 3] = t32(v4.w);
    }

    for (int qt = 0; qt < 4; qt++) {
        __syncthreads();   // K/V staged (qt=0); prev writeout done (qt>0)
        // Stage Q tile (64 queries = 512 float4, one per thread)
        {
            int r = tid >> 3, c = (tid & 7) * 4;
            int qq = qt * 64 + r;
            size_t token = ((size_t)(b * 128 + (qq >> 4) * 8 + s1)) * 128 + (qq & 15) * 8 + s2;
            float4 q4 = *(const float4*)(qkv + token * 768 + h * 32 + c);
            Q[r * 36 + c + 0] = t32(q4.x * scale);
            Q[r * 36 + c + 1] = t32(q4.y * scale);
            Q[r * 36 + c + 2] = t32(q4.z * scale);
            Q[r * 36 + c + 3] = t32(q4.w * scale);
        }
        __syncthreads();

        // S = Q @ K^T (64x256, k=32): 64 warp-tiles over 16 warps (4 each)
        {
            const int wl = warp & 3;        // row tile
            const int wc = warp >> 2;       // col group (0..3), 4 tiles each
            wmma::fragment<wmma::matrix_a, 16, 16, 8, wmma::precision::tf32,
                           wmma::row_major> af[4];
#pragma unroll
            for (int ki = 0; ki < 4; ki++)
                wmma::load_matrix_sync(af[ki], &Q[(wl * 16) * 36 + ki * 8], 36);
#pragma unroll
            for (int jj = 0; jj < 4; jj++) {
                int j = wc * 4 + jj;
                wmma::fragment<wmma::accumulator, 16, 16, 8, float> acc;
                wmma::fill_fragment(acc, 0.f);
#pragma unroll
                for (int ki = 0; ki < 4; ki++) {
                    wmma::fragment<wmma::matrix_b, 16, 16, 8, wmma::precision::tf32,
                                   wmma::col_major> bf;
                    wmma::load_matrix_sync(bf, &K[(j * 16) * 36 + ki * 8], 36);
                    wmma::mma_sync(acc, af[ki], bf, acc);
                }
                wmma::store_matrix_sync(&S[(wl * 16) * 260 + j * 16], acc, 260,
                                        wmma::mem_row_major);
            }
        }
        __syncthreads();

        // Softmax: 8 thr/row, 32 elems each
        {
            int row = tid >> 3, oct = tid & 7;
            float* Sp = S + row * 260 + oct * 32;
            float m = -3.0e38f;
#pragma unroll
            for (int e = 0; e < 32; e++) m = fmaxf(m, Sp[e]);
            m = fmaxf(m, __shfl_xor_sync(0xffffffffu, m, 1));
            m = fmaxf(m, __shfl_xor_sync(0xffffffffu, m, 2));
            m = fmaxf(m, __shfl_xor_sync(0xffffffffu, m, 4));
            float sum = 0.f;
#pragma unroll
            for (int e = 0; e < 32; e++) {
                float p = __expf(Sp[e] - m);
                Sp[e] = t32(p);
                sum += p;
            }
            sum += __shfl_xor_sync(0xffffffffu, sum, 1);
            sum += __shfl_xor_sync(0xffffffffu, sum, 2);
            sum += __shfl_xor_sync(0xffffffffu, sum, 4);
            if (oct == 0) il[row] = 1.f / sum;
        }
        __syncthreads();

        // O = P @ V (64x32, k=256): 8 output tiles x 2 k-halves = 16 warps
        {
            const int wl = warp & 3;            // row tile
            const int wc = (warp >> 2) & 1;     // col tile
            const int kh = warp >> 3;           // k half (0..1)
            wmma::fragment<wmma::accumulator, 16, 16, 8, float> acc;
            wmma::fill_fragment(acc, 0.f);
#pragma unroll
            for (int ks = 0; ks < 16; ks++) {
                int kk = kh * 128 + ks * 8;
                wmma::fragment<wmma::matrix_a, 16, 16, 8, wmma::precision::tf32,
                               wmma::row_major> af;
                wmma::fragment<wmma::matrix_b, 16, 16, 8, wmma::precision::tf32,
                               wmma::row_major> bf;
                wmma::load_matrix_sync(af, &S[(wl * 16) * 260 + kk], 260);
                wmma::load_matrix_sync(bf, &V[kk * 36 + wc * 16], 36);
                wmma::mma_sync(acc, af, bf, acc);
            }
            wmma::store_matrix_sync(&Op[kh * 2304 + (wl * 16) * 36 + wc * 16],
                                    acc, 36, wmma::mem_row_major);
        }
        __syncthreads();

        // Writeout: combine k-halves, normalize, tf32-round
        {
            int r = tid >> 3, c = (tid & 7) * 4;
            float inv = il[r];
            float4 a = *(float4*)&Op[r * 36 + c];
            float4 bq = *(float4*)&Op[2304 + r * 36 + c];
            float4 o = make_float4(t32((a.x + bq.x) * inv), t32((a.y + bq.y) * inv),
                                   t32((a.z + bq.z) * inv), t32((a.w + bq.w) * inv));
            int qq = qt * 64 + r;
            size_t token = ((size_t)(b * 128 + (qq >> 4) * 8 + s1)) * 128 + (qq & 15) * 8 + s2;
            *(float4*)&att[token * 256 + h * 32 + c] = o;
        }
    }
}

// ---------------------------------------------------------------------------
extern "C" void kernel_launch(void* const* d_in, const int* in_sizes, int n_in,
                              void* d_out, int out_size)
{
    (void)in_sizes; (void)n_in; (void)out_size;
    const float* x     = (const float*)d_in[0];
    const float* Wqkv  = (const float*)d_in[1];
    const float* Wproj = (const float*)d_in[2];
    const float* bproj = (const float*)d_in[3];
    float* out = (float*)d_out;

    float *qkv = nullptr, *att = nullptr, *wq = nullptr, *wp = nullptr;
    cudaGetSymbolAddress((void**)&qkv, g_qkv);
    cudaGetSymbolAddress((void**)&att, g_att);
    cudaGetSymbolAddress((void**)&wq,  g_wq);
    cudaGetSymbolAddress((void**)&wp,  g_wp);

    cudaFuncSetAttribute(gemm_wmma, cudaFuncAttributeMaxDynamicSharedMemorySize, 105984);
    cudaFuncSetAttribute(attn_local_tc, cudaFuncAttributeMaxDynamicSharedMemorySize, 89600);
    cudaFuncSetAttribute(attn_grid_tc, cudaFuncAttributeMaxDynamicSharedMemorySize, 168192);

    // 0) pre-round x (into g_att, free until attention) and weights to tf32
    cvt_inputs<<<4096, 256>>>(x, Wqkv, Wproj, att, wq, wp);
    // 1) QKV = xt @ W_qkv
    gemm_wmma<<<dim3(6, 1024), 256, 105984>>>(att, wq, nullptr, qkv, 768);
    // 2) local window attention (heads 0..3) — overwrites g_att with att
    attn_local_tc<<<dim3(2048, 2), 256, 89600>>>(qkv, att);
    // 3) dilated grid attention (heads 4..7)
    attn_grid_tc<<<dim3(512, 4), 512, 168192>>>(qkv, att);
    // 4) out = att @ W_proj + b_proj
    gemm_wmma<<<dim3(2, 1024), 256, 105984>>>(att, wp, bproj, out, 256);
}

// round 7
// speedup vs baseline: 1.0555x; 1.0555x over previous
#include <cuda_runtime.h>
#include <mma.h>
using namespace nvcuda;

// Problem constants: B=8, H=W=128, C=256, NUM_HEADS=8, HD=32, WINDOW=8
#define TOKENS 131072

// Scratch (allocation-free rule: device globals)
__device__ float g_qkv[100663296u];  // [token][3][head][32]
__device__ float g_att[33554432u];   // xt (pre-GEMM1) then att [token][256]
__device__ float g_wq[196608];       // tf32-rounded W_qkv
__device__ float g_wp[65536];        // tf32-rounded W_proj

__device__ __forceinline__ float t32(float x) { return wmma::__float_to_tf32(x); }

__device__ __forceinline__ void cp_async16(void* smem, const void* gmem) {
    unsigned s = (unsigned)__cvta_generic_to_shared(smem);
    asm volatile("cp.async.cg.shared.global [%0], [%1], 16;\n" :: "r"(s), "l"(gmem));
}
__device__ __forceinline__ void cp_commit() { asm volatile("cp.async.commit_group;\n"); }
__device__ __forceinline__ void cp_wait1()  { asm volatile("cp.async.wait_group 1;\n"); }
__device__ __forceinline__ void cp_wait0()  { asm volatile("cp.async.wait_group 0;\n"); }

// ---------------------------------------------------------------------------
// Pre-round inputs to tf32 (RN) once: x -> xt, weights -> g_wq/g_wp.
// ---------------------------------------------------------------------------
__global__ void cvt_inputs(const float* __restrict__ x,
                           const float* __restrict__ wq,
                           const float* __restrict__ wp,
                           float* __restrict__ xt,
                           float* __restrict__ wqt,
                           float* __restrict__ wpt)
{
    const int stride = gridDim.x * blockDim.x;
    const int tid0 = blockIdx.x * blockDim.x + threadIdx.x;
    for (int i = tid0; i < 33554432 / 4; i += stride) {
        float4 v = ((const float4*)x)[i];
        v.x = t32(v.x); v.y = t32(v.y); v.z = t32(v.z); v.w = t32(v.w);
        ((float4*)xt)[i] = v;
    }
    for (int i = tid0; i < (196608 + 65536) / 4; i += stride) {
        if (i < 49152) {
            float4 v = ((const float4*)wq)[i];
            v.x = t32(v.x); v.y = t32(v.y); v.z = t32(v.z); v.w = t32(v.w);
            ((float4*)wqt)[i] = v;
        } else {
            float4 v = ((const float4*)wp)[i - 49152];
            v.x = t32(v.x); v.y = t32(v.y); v.z = t32(v.z); v.w = t32(v.w);
            ((float4*)wpt)[i - 49152] = v;
        }
    }
}

// ---------------------------------------------------------------------------
// TF32 GEMM: C[M,N]=A[M,256]@B[256,N] (+bias). Inputs pre-rounded: NO CVTs.
// BM=BN=128, BK=32, 3-stage cp.async. 8 warps, 64x32 warp tile.
// ---------------------------------------------------------------------------
__global__ __launch_bounds__(256, 2) void gemm_wmma(
    const float* __restrict__ A, const float* __restrict__ B,
    const float* __restrict__ bias, float* __restrict__ C, int N)
{
    extern __shared__ float sm[];
    const int tid  = threadIdx.x;
    const int warp = tid >> 5;
    const int lane = tid & 31;
    const int wm = warp >> 2, wn = warp & 3;
    const int bn = blockIdx.x * 128;   // fast dim = cols -> A L2 reuse
    const int bm = blockIdx.y * 128;

    wmma::fragment<wmma::accumulator, 16, 16, 8, float> acc[4][2];
#pragma unroll
    for (int i = 0; i < 4; i++)
#pragma unroll
        for (int j = 0; j < 2; j++) wmma::fill_fragment(acc[i][j], 0.f);

    auto load_tile = [&](int s, int k0) {
        float* As = sm + s * 8832;
        float* Bs = As + 4608;
#pragma unroll
        for (int t = 0; t < 4; t++) {
            int idx = tid + t * 256;                 // 0..1023
            int ar = idx >> 3, ac = (idx & 7) * 4;   // A: 128x32
            cp_async16(&As[ar * 36 + ac], A + (size_t)(bm + ar) * 256 + k0 + ac);
            int br = idx >> 5, bc = (idx & 31) * 4;  // B: 32x128
            cp_async16(&Bs[br * 132 + bc], B + (size_t)(k0 + br) * N + bn + bc);
        }
        cp_commit();
    };

    load_tile(0, 0);
    load_tile(1, 32);
    const int NK = 8;  // 256/32
    for (int kt = 0; kt < NK; kt++) {
        if (kt == NK - 1) cp_wait0(); else cp_wait1();
        __syncthreads();
        if (kt + 2 < NK) load_tile((kt + 2) % 3, (kt + 2) * 32);
        const float* As = sm + (kt % 3) * 8832;
        const float* Bs = As + 4608;
#pragma unroll
        for (int kk = 0; kk < 32; kk += 8) {
            wmma::fragment<wmma::matrix_a, 16, 16, 8, wmma::precision::tf32,
                           wmma::row_major> af[4];
            wmma::fragment<wmma::matrix_b, 16, 16, 8, wmma::precision::tf32,
                           wmma::row_major> bf[2];
#pragma unroll
            for (int i = 0; i < 4; i++)
                wmma::load_matrix_sync(af[i], &As[(wm * 64 + i * 16) * 36 + kk], 36);
#pragma unroll
            for (int j = 0; j < 2; j++)
                wmma::load_matrix_sync(bf[j], &Bs[kk * 132 + wn * 32 + j * 16], 132);
#pragma unroll
            for (int i = 0; i < 4; i++)
#pragma unroll
                for (int j = 0; j < 2; j++)
                    wmma::mma_sync(acc[i][j], af[i], bf[j], acc[i][j]);
        }
    }
    __syncthreads();

    // Epilogue via private smem strip
    float* wb = sm + warp * 320;   // 16 x 20
    const int r = lane >> 1, c0 = (lane & 1) * 8;
#pragma unroll
    for (int i = 0; i < 4; i++) {
#pragma unroll
        for (int j = 0; j < 2; j++) {
            wmma::store_matrix_sync(wb, acc[i][j], 20, wmma::mem_row_major);
            __syncwarp();
            float4 v0 = *(float4*)&wb[r * 20 + c0];
            float4 v1 = *(float4*)&wb[r * 20 + c0 + 4];
            int grow = bm + wm * 64 + i * 16 + r;
            int gcol = bn + wn * 32 + j * 16 + c0;
            if (bias) {
                v0.x += bias[gcol + 0]; v0.y += bias[gcol + 1];
                v0.z += bias[gcol + 2]; v0.w += bias[gcol + 3];
                v1.x += bias[gcol + 4]; v1.y += bias[gcol + 5];
                v1.z += bias[gcol + 6]; v1.w += bias[gcol + 7];
            }
            *(float4*)&C[(size_t)grow * N + gcol]     = v0;
            *(float4*)&C[(size_t)grow * N + gcol + 4] = v1;
            __syncwarp();
        }
    }
}

// ---------------------------------------------------------------------------
// Local window attention (heads 0..3). CTA = 1 window x 2 heads. 256 thr.
// ---------------------------------------------------------------------------
__global__ __launch_bounds__(256, 2) void attn_local_tc(
    const float* __restrict__ qkv, float* __restrict__ att)
{
    extern __shared__ float sm[];
    const int wid = blockIdx.x;
    const int b = wid >> 8, wy = (wid >> 4) & 15, wx = wid & 15;
    const int tid = threadIdx.x;
    const int warp = tid >> 5;
    const int hh = warp >> 2, wl = warp & 3;
    const float scale = 0.17677669529663687f;

#pragma unroll
    for (int i = 0; i < 4; i++) {
        int idx = tid + i * 256;           // 0..1023
        int h2 = idx >> 9;
        int r  = (idx >> 3) & 63;
        int c  = (idx & 7) * 4;
        int hg = (int)blockIdx.y * 2 + h2;
        size_t token = ((size_t)(b * 128 + wy * 8 + (r >> 3))) * 128 + wx * 8 + (r & 7);
        const float* base = qkv + token * 768 + hg * 32 + c;
        float4 q4 = *(const float4*)base;
        float4 k4 = *(const float4*)(base + 256);
        float4 v4 = *(const float4*)(base + 512);
        float* Q = sm + h2 * 11200;
        float* Kt = Q + 2304;
        float* V = Q + 4480;
        Q[r * 36 + c + 0] = t32(q4.x * scale);
        Q[r * 36 + c + 1] = t32(q4.y * scale);
        Q[r * 36 + c + 2] = t32(q4.z * scale);
        Q[r * 36 + c + 3] = t32(q4.w * scale);
        Kt[(c + 0) * 68 + r] = t32(k4.x);
        Kt[(c + 1) * 68 + r] = t32(k4.y);
        Kt[(c + 2) * 68 + r] = t32(k4.z);
        Kt[(c + 3) * 68 + r] = t32(k4.w);
        V[r * 36 + c + 0] = t32(v4.x);
        V[r * 36 + c + 1] = t32(v4.y);
        V[r * 36 + c + 2] = t32(v4.z);
        V[r * 36 + c + 3] = t32(v4.w);
    }
    __syncthreads();

    float* Qh  = sm + hh * 11200;
    float* Kth = Qh + 2304;
    float* Vh  = Qh + 4480;
    float* Sh  = Qh + 6784;

    {   // S = Q @ K^T  (64x64, k=32)
        wmma::fragment<wmma::accumulator, 16, 16, 8, float> accS[4];
#pragma unroll
        for (int j = 0; j < 4; j++) wmma::fill_fragment(accS[j], 0.f);
#pragma unroll
        for (int kk = 0; kk < 32; kk += 8) {
            wmma::fragment<wmma::matrix_a, 16, 16, 8, wmma::precision::tf32,
                           wmma::row_major> af;
            wmma::load_matrix_sync(af, &Qh[(wl * 16) * 36 + kk], 36);
#pragma unroll
            for (int j = 0; j < 4; j++) {
                wmma::fragment<wmma::matrix_b, 16, 16, 8, wmma::precision::tf32,
                               wmma::row_major> bf;
                wmma::load_matrix_sync(bf, &Kth[kk * 68 + j * 16], 68);
                wmma::mma_sync(accS[j], af, bf, accS[j]);
            }
        }
#pragma unroll
        for (int j = 0; j < 4; j++)
            wmma::store_matrix_sync(&Sh[(wl * 16) * 68 + j * 16], accS[j], 68,
                                    wmma::mem_row_major);
    }
    __syncthreads();

    {   // softmax: 2 thr/row
        int h2 = tid >> 7, local = tid & 127;
        int row = local >> 1, half = local & 1;
        float* S = sm + h2 * 11200 + 6784 + row * 68 + half * 32;
        float m = -3.0e38f;
#pragma unroll
        for (int e = 0; e < 32; e++) m = fmaxf(m, S[e]);
        m = fmaxf(m, __shfl_xor_sync(0xffffffffu, m, 1));
        float sum = 0.f;
#pragma unroll
        for (int e = 0; e < 32; e++) {
            float p = __expf(S[e] - m);
            S[e] = t32(p);
            sum += p;
        }
        sum += __shfl_xor_sync(0xffffffffu, sum, 1);
        if (half == 0) (sm + h2 * 11200 + 11136)[row] = 1.f / sum;
    }
    __syncthreads();

    {   // O = P @ V  (64x32, k=64)
        wmma::fragment<wmma::accumulator, 16, 16, 8, float> accO[2];
#pragma unroll
        for (int j = 0; j < 2; j++) wmma::fill_fragment(accO[j], 0.f);
#pragma unroll
        for (int kk = 0; kk < 64; kk += 8) {
            wmma::fragment<wmma::matrix_a, 16, 16, 8, wmma::precision::tf32,
                           wmma::row_major> af;
            wmma::load_matrix_sync(af, &Sh[(wl * 16) * 68 + kk], 68);
#pragma unroll
            for (int j = 0; j < 2; j++) {
                wmma::fragment<wmma::matrix_b, 16, 16, 8, wmma::precision::tf32,
                               wmma::row_major> bf;
                wmma::load_matrix_sync(bf, &Vh[kk * 36 + j * 16], 36);
                wmma::mma_sync(accO[j], af, bf, accO[j]);
            }
        }
#pragma unroll
        for (int j = 0; j < 2; j++)
            wmma::store_matrix_sync(&Qh[(wl * 16) * 36 + j * 16], accO[j], 36,
                                    wmma::mem_row_major);
    }
    __syncthreads();

#pragma unroll
    for (int i = 0; i < 4; i++) {
        int idx = tid + i * 256;
        int h2 = idx >> 9;
        int r  = (idx >> 3) & 63;
        int c  = (idx & 7) * 4;
        int hg = (int)blockIdx.y * 2 + h2;
        float* Q = sm + h2 * 11200;
        float inv = (sm + h2 * 11200 + 11136)[r];
        float4 o = make_float4(t32(Q[r * 36 + c] * inv), t32(Q[r * 36 + c + 1] * inv),
                               t32(Q[r * 36 + c + 2] * inv), t32(Q[r * 36 + c + 3] * inv));
        size_t token = ((size_t)(b * 128 + wy * 8 + (r >> 3))) * 128 + wx * 8 + (r & 7);
        *(float4*)&att[token * 256 + hg * 32 + c] = o;
    }
}

// ---------------------------------------------------------------------------
// Grid (dilated) attention (heads 4..7) — round-4 structure (best measured):
// CTA = (cell, head, 64-query tile), 256 thr. smem: Q[64][36]@0,
// Kt[32][260]@2304, V[256][36]@10624, S[64][260]@19840, il[64]@36480
// -> 36544 fl = 146176 B.
// ---------------------------------------------------------------------------
__global__ __launch_bounds__(256, 1) void attn_grid_tc(
    const float* __restrict__ qkv, float* __restrict__ att)
{
    extern __shared__ float sm[];
    const int cid = blockIdx.x;
    const int b = cid >> 6, s1 = (cid >> 3) & 7, s2 = cid & 7;
    const int hq = blockIdx.y;
    const int h = 4 + (hq >> 2), qt = hq & 3;
    const int tid = threadIdx.x;
    const int warp = tid >> 5;
    const int wl = warp & 3, wc = warp >> 2;
    const float scale = 0.17677669529663687f;

    float* Q  = sm;
    float* Kt = sm + 2304;
    float* V  = sm + 10624;
    float* S  = sm + 19840;
    float* il = sm + 36480;

    // Stage Q (64 rows of this qtile)
#pragma unroll
    for (int i = 0; i < 2; i++) {
        int idx = tid + i * 256;           // 0..511
        int r = idx >> 3, c = (idx & 7) * 4;
        int qq = qt * 64 + r;
        size_t token = ((size_t)(b * 128 + (qq >> 4) * 8 + s1)) * 128 + (qq & 15) * 8 + s2;
        float4 q4 = *(const float4*)(qkv + token * 768 + h * 32 + c);
        Q[r * 36 + c + 0] = t32(q4.x * scale);
        Q[r * 36 + c + 1] = t32(q4.y * scale);
        Q[r * 36 + c + 2] = t32(q4.z * scale);
        Q[r * 36 + c + 3] = t32(q4.w * scale);
    }
    // Stage K (transposed) and V (256 keys)
#pragma unroll
    for (int i = 0; i < 8; i++) {
        int idx = tid + i * 256;           // 0..2047
        int rk = idx >> 3, c = (idx & 7) * 4;
        size_t ktok = ((size_t)(b * 128 + (rk >> 4) * 8 + s1)) * 128 + (rk & 15) * 8 + s2;
        const float* base = qkv + ktok * 768 + h * 32 + c;
        float4 k4 = *(const float4*)(base + 256);
        float4 v4 = *(const float4*)(base + 512);
        Kt[(c + 0) * 260 + rk] = t32(k4.x);
        Kt[(c + 1) * 260 + rk] = t32(k4.y);
        Kt[(c + 2) * 260 + rk] = t32(k4.z);
        Kt[(c + 3) * 260 + rk] = t32(k4.w);
        V[rk * 36 + c + 0] = t32(v4.x);
        V[rk * 36 + c + 1] = t32(v4.y);
        V[rk * 36 + c + 2] = t32(v4.z);
        V[rk * 36 + c + 3] = t32(v4.w);
    }
    __syncthreads();

    // S = Q @ K^T (64 x 256, k=32); warp covers (row-tile wl, col tiles wc*8..+7)
    {
        wmma::fragment<wmma::matrix_a, 16, 16, 8, wmma::precision::tf32,
                       wmma::row_major> af[4];
#pragma unroll
        for (int ki = 0; ki < 4; ki++)
            wmma::load_matrix_sync(af[ki], &Q[(wl * 16) * 36 + ki * 8], 36);
        for (int j = wc * 8; j < wc * 8 + 8; j++) {
            wmma::fragment<wmma::accumulator, 16, 16, 8, float> acc;
            wmma::fill_fragment(acc, 0.f);
#pragma unroll
            for (int ki = 0; ki < 4; ki++) {
                wmma::fragment<wmma::matrix_b, 16, 16, 8, wmma::precision::tf32,
                               wmma::row_major> bf;
                wmma::load_matrix_sync(bf, &Kt[(ki * 8) * 260 + j * 16], 260);
                wmma::mma_sync(acc, af[ki], bf, acc);
            }
            wmma::store_matrix_sync(&S[(wl * 16) * 260 + j * 16], acc, 260,
                                    wmma::mem_row_major);
        }
    }
    __syncthreads();

    // Softmax: 4 thr/row, 64 elems each
    {
        int row = tid >> 2, quarter = tid & 3;
        float* Sp = S + row * 260 + quarter * 64;
        float m = -3.0e38f;
#pragma unroll
        for (int e = 0; e < 64; e++) m = fmaxf(m, Sp[e]);
        m = fmaxf(m, __shfl_xor_sync(0xffffffffu, m, 1));
        m = fmaxf(m, __shfl_xor_sync(0xffffffffu, m, 2));
        float sum = 0.f;
#pragma unroll
        for (int e = 0; e < 64; e++) {
            float p = __expf(Sp[e] - m);
            Sp[e] = t32(p);
            sum += p;
        }
        sum += __shfl_xor_sync(0xffffffffu, sum, 1);
        sum += __shfl_xor_sync(0xffffffffu, sum, 2);
        if (quarter == 0) il[row] = 1.f / sum;
    }
    __syncthreads();

    // O = P @ V (64x32, k=256); warp does (row-tile wl, col-tile wc)
    {
        wmma::fragment<wmma::accumulator, 16, 16, 8, float> acc;
        wmma::fill_fragment(acc, 0.f);
#pragma unroll 4
        for (int ks = 0; ks < 32; ks++) {
            int kk = ks * 8;
            wmma::fragment<wmma::matrix_a, 16, 16, 8, wmma::precision::tf32,
                           wmma::row_major> af;
            wmma::fragment<wmma::matrix_b, 16, 16, 8, wmma::precision::tf32,
                           wmma::row_major> bf;
            wmma::load_matrix_sync(af, &S[(wl * 16) * 260 + kk], 260);
            wmma::load_matrix_sync(bf, &V[kk * 36 + wc * 16], 36);
            wmma::mma_sync(acc, af, bf, acc);
        }
        wmma::store_matrix_sync(&Q[(wl * 16) * 36 + wc * 16], acc, 36,
                                wmma::mem_row_major);
    }
    __syncthreads();

    // Write out normalized, tf32-rounded
#pragma unroll
    for (int i = 0; i < 2; i++) {
        int idx = tid + i * 256;
        int r = idx >> 3, c = (idx & 7) * 4;
        float inv = il[r];
        float4 o = make_float4(t32(Q[r * 36 + c] * inv), t32(Q[r * 36 + c + 1] * inv),
                               t32(Q[r * 36 + c + 2] * inv), t32(Q[r * 36 + c + 3] * inv));
        int qq = qt * 64 + r;
        size_t token = ((size_t)(b * 128 + (qq >> 4) * 8 + s1)) * 128 + (qq & 15) * 8 + s2;
        *(float4*)&att[token * 256 + h * 32 + c] = o;
    }
}

// ---------------------------------------------------------------------------
extern "C" void kernel_launch(void* const* d_in, const int* in_sizes, int n_in,
                              void* d_out, int out_size)
{
    (void)in_sizes; (void)n_in; (void)out_size;
    const float* x     = (const float*)d_in[0];
    const float* Wqkv  = (const float*)d_in[1];
    const float* Wproj = (const float*)d_in[2];
    const float* bproj = (const float*)d_in[3];
    float* out = (float*)d_out;

    float *qkv = nullptr, *att = nullptr, *wq = nullptr, *wp = nullptr;
    cudaGetSymbolAddress((void**)&qkv, g_qkv);
    cudaGetSymbolAddress((void**)&att, g_att);
    cudaGetSymbolAddress((void**)&wq,  g_wq);
    cudaGetSymbolAddress((void**)&wp,  g_wp);

    cudaFuncSetAttribute(gemm_wmma, cudaFuncAttributeMaxDynamicSharedMemorySize, 105984);
    cudaFuncSetAttribute(attn_local_tc, cudaFuncAttributeMaxDynamicSharedMemorySize, 89600);
    cudaFuncSetAttribute(attn_grid_tc, cudaFuncAttributeMaxDynamicSharedMemorySize, 146176);

    // 0) pre-round x (into g_att, free until attention) and weights to tf32
    cvt_inputs<<<4096, 256>>>(x, Wqkv, Wproj, att, wq, wp);
    // 1) QKV = xt @ W_qkv
    gemm_wmma<<<dim3(6, 1024), 256, 105984>>>(att, wq, nullptr, qkv, 768);
    // 2) local window attention (heads 0..3) — overwrites g_att with att
    attn_local_tc<<<dim3(2048, 2), 256, 89600>>>(qkv, att);
    // 3) dilated grid attention (heads 4..7) — round-4 structure
    attn_grid_tc<<<dim3(512, 16), 256, 146176>>>(qkv, att);
    // 4) out = att @ W_proj + b_proj
    gemm_wmma<<<dim3(2, 1024), 256, 105984>>>(att, wp, bproj, out, 256);
}

// round 8
// speedup vs baseline: 1.1487x; 1.0883x over previous
#include <cuda_runtime.h>
#include <mma.h>
using namespace nvcuda;

// Problem constants: B=8, H=W=128, C=256, NUM_HEADS=8, HD=32, WINDOW=8
#define TOKENS 131072

// Scratch (allocation-free rule: device globals)
__device__ float g_qkv[100663296u];  // [token][3][head][32]
__device__ float g_att[33554432u];   // xt (pre-GEMM1) then att [token][256]
__device__ float g_wq[196608];       // tf32-rounded W_qkv
__device__ float g_wp[65536];        // tf32-rounded W_proj

__device__ __forceinline__ float t32(float x) { return wmma::__float_to_tf32(x); }

__device__ __forceinline__ void cp_async16(void* smem, const void* gmem) {
    unsigned s = (unsigned)__cvta_generic_to_shared(smem);
    asm volatile("cp.async.cg.shared.global [%0], [%1], 16;\n" :: "r"(s), "l"(gmem));
}
__device__ __forceinline__ void cp_commit() { asm volatile("cp.async.commit_group;\n"); }
__device__ __forceinline__ void cp_wait1()  { asm volatile("cp.async.wait_group 1;\n"); }
__device__ __forceinline__ void cp_wait0()  { asm volatile("cp.async.wait_group 0;\n"); }

// ---------------------------------------------------------------------------
// Pre-round inputs to tf32 (RN) once: x -> xt, weights -> g_wq/g_wp.
// ---------------------------------------------------------------------------
__global__ void cvt_inputs(const float* __restrict__ x,
                           const float* __restrict__ wq,
                           const float* __restrict__ wp,
                           float* __restrict__ xt,
                           float* __restrict__ wqt,
                           float* __restrict__ wpt)
{
    const int stride = gridDim.x * blockDim.x;
    const int tid0 = blockIdx.x * blockDim.x + threadIdx.x;
    for (int i = tid0; i < 33554432 / 4; i += stride) {
        float4 v = ((const float4*)x)[i];
        v.x = t32(v.x); v.y = t32(v.y); v.z = t32(v.z); v.w = t32(v.w);
        ((float4*)xt)[i] = v;
    }
    for (int i = tid0; i < (196608 + 65536) / 4; i += stride) {
        if (i < 49152) {
            float4 v = ((const float4*)wq)[i];
            v.x = t32(v.x); v.y = t32(v.y); v.z = t32(v.z); v.w = t32(v.w);
            ((float4*)wqt)[i] = v;
        } else {
            float4 v = ((const float4*)wp)[i - 49152];
            v.x = t32(v.x); v.y = t32(v.y); v.z = t32(v.z); v.w = t32(v.w);
            ((float4*)wpt)[i - 49152] = v;
        }
    }
}

// ---------------------------------------------------------------------------
// TF32 GEMM: C[M,N]=A[M,256]@B[256,N] (+bias). Inputs pre-rounded: NO CVTs.
// BM=BN=128, BK=32, 3-stage cp.async. 8 warps, 64x32 warp tile.
// ---------------------------------------------------------------------------
__global__ __launch_bounds__(256, 2) void gemm_wmma(
    const float* __restrict__ A, const float* __restrict__ B,
    const float* __restrict__ bias, float* __restrict__ C, int N)
{
    extern __shared__ float sm[];
    const int tid  = threadIdx.x;
    const int warp = tid >> 5;
    const int lane = tid & 31;
    const int wm = warp >> 2, wn = warp & 3;
    const int bn = blockIdx.x * 128;   // fast dim = cols -> A L2 reuse
    const int bm = blockIdx.y * 128;

    wmma::fragment<wmma::accumulator, 16, 16, 8, float> acc[4][2];
#pragma unroll
    for (int i = 0; i < 4; i++)
#pragma unroll
        for (int j = 0; j < 2; j++) wmma::fill_fragment(acc[i][j], 0.f);

    auto load_tile = [&](int s, int k0) {
        float* As = sm + s * 8832;
        float* Bs = As + 4608;
#pragma unroll
        for (int t = 0; t < 4; t++) {
            int idx = tid + t * 256;                 // 0..1023
            int ar = idx >> 3, ac = (idx & 7) * 4;   // A: 128x32
            cp_async16(&As[ar * 36 + ac], A + (size_t)(bm + ar) * 256 + k0 + ac);
            int br = idx >> 5, bc = (idx & 31) * 4;  // B: 32x128
            cp_async16(&Bs[br * 132 + bc], B + (size_t)(k0 + br) * N + bn + bc);
        }
        cp_commit();
    };

    load_tile(0, 0);
    load_tile(1, 32);
    const int NK = 8;  // 256/32
    for (int kt = 0; kt < NK; kt++) {
        if (kt == NK - 1) cp_wait0(); else cp_wait1();
        __syncthreads();
        if (kt + 2 < NK) load_tile((kt + 2) % 3, (kt + 2) * 32);
        const float* As = sm + (kt % 3) * 8832;
        const float* Bs = As + 4608;
#pragma unroll
        for (int kk = 0; kk < 32; kk += 8) {
            wmma::fragment<wmma::matrix_a, 16, 16, 8, wmma::precision::tf32,
                           wmma::row_major> af[4];
            wmma::fragment<wmma::matrix_b, 16, 16, 8, wmma::precision::tf32,
                           wmma::row_major> bf[2];
#pragma unroll
            for (int i = 0; i < 4; i++)
                wmma::load_matrix_sync(af[i], &As[(wm * 64 + i * 16) * 36 + kk], 36);
#pragma unroll
            for (int j = 0; j < 2; j++)
                wmma::load_matrix_sync(bf[j], &Bs[kk * 132 + wn * 32 + j * 16], 132);
#pragma unroll
            for (int i = 0; i < 4; i++)
#pragma unroll
                for (int j = 0; j < 2; j++)
                    wmma::mma_sync(acc[i][j], af[i], bf[j], acc[i][j]);
        }
    }
    __syncthreads();

    // Epilogue via private smem strip
    float* wb = sm + warp * 320;   // 16 x 20
    const int r = lane >> 1, c0 = (lane & 1) * 8;
#pragma unroll
    for (int i = 0; i < 4; i++) {
#pragma unroll
        for (int j = 0; j < 2; j++) {
            wmma::store_matrix_sync(wb, acc[i][j], 20, wmma::mem_row_major);
            __syncwarp();
            float4 v0 = *(float4*)&wb[r * 20 + c0];
            float4 v1 = *(float4*)&wb[r * 20 + c0 + 4];
            int grow = bm + wm * 64 + i * 16 + r;
            int gcol = bn + wn * 32 + j * 16 + c0;
            if (bias) {
                v0.x += bias[gcol + 0]; v0.y += bias[gcol + 1];
                v0.z += bias[gcol + 2]; v0.w += bias[gcol + 3];
                v1.x += bias[gcol + 4]; v1.y += bias[gcol + 5];
                v1.z += bias[gcol + 6]; v1.w += bias[gcol + 7];
            }
            *(float4*)&C[(size_t)grow * N + gcol]     = v0;
            *(float4*)&C[(size_t)grow * N + gcol + 4] = v1;
            __syncwarp();
        }
    }
}

// ---------------------------------------------------------------------------
// Local window attention (heads 0..3). CTA = 1 window x 2 heads. 256 thr.
// No-max softmax: exp applied to S accumulator registers; sum-only pass.
// ---------------------------------------------------------------------------
__global__ __launch_bounds__(256, 2) void attn_local_tc(
    const float* __restrict__ qkv, float* __restrict__ att)
{
    extern __shared__ float sm[];
    const int wid = blockIdx.x;
    const int b = wid >> 8, wy = (wid >> 4) & 15, wx = wid & 15;
    const int tid = threadIdx.x;
    const int warp = tid >> 5;
    const int hh = warp >> 2, wl = warp & 3;
    const float scale = 0.17677669529663687f;

#pragma unroll
    for (int i = 0; i < 4; i++) {
        int idx = tid + i * 256;           // 0..1023
        int h2 = idx >> 9;
        int r  = (idx >> 3) & 63;
        int c  = (idx & 7) * 4;
        int hg = (int)blockIdx.y * 2 + h2;
        size_t token = ((size_t)(b * 128 + wy * 8 + (r >> 3))) * 128 + wx * 8 + (r & 7);
        const float* base = qkv + token * 768 + hg * 32 + c;
        float4 q4 = *(const float4*)base;
        float4 k4 = *(const float4*)(base + 256);
        float4 v4 = *(const float4*)(base + 512);
        float* Q = sm + h2 * 11200;
        float* Kt = Q + 2304;
        float* V = Q + 4480;
        Q[r * 36 + c + 0] = t32(q4.x * scale);
        Q[r * 36 + c + 1] = t32(q4.y * scale);
        Q[r * 36 + c + 2] = t32(q4.z * scale);
        Q[r * 36 + c + 3] = t32(q4.w * scale);
        Kt[(c + 0) * 68 + r] = t32(k4.x);
        Kt[(c + 1) * 68 + r] = t32(k4.y);
        Kt[(c + 2) * 68 + r] = t32(k4.z);
        Kt[(c + 3) * 68 + r] = t32(k4.w);
        V[r * 36 + c + 0] = t32(v4.x);
        V[r * 36 + c + 1] = t32(v4.y);
        V[r * 36 + c + 2] = t32(v4.z);
        V[r * 36 + c + 3] = t32(v4.w);
    }
    __syncthreads();

    float* Qh  = sm + hh * 11200;
    float* Kth = Qh + 2304;
    float* Vh  = Qh + 4480;
    float* Sh  = Qh + 6784;

    {   // S = exp(Q @ K^T)  (64x64, k=32), exp on acc registers
        wmma::fragment<wmma::accumulator, 16, 16, 8, float> accS[4];
#pragma unroll
        for (int j = 0; j < 4; j++) wmma::fill_fragment(accS[j], 0.f);
#pragma unroll
        for (int kk = 0; kk < 32; kk += 8) {
            wmma::fragment<wmma::matrix_a, 16, 16, 8, wmma::precision::tf32,
                           wmma::row_major> af;
            wmma::load_matrix_sync(af, &Qh[(wl * 16) * 36 + kk], 36);
#pragma unroll
            for (int j = 0; j < 4; j++) {
                wmma::fragment<wmma::matrix_b, 16, 16, 8, wmma::precision::tf32,
                               wmma::row_major> bf;
                wmma::load_matrix_sync(bf, &Kth[kk * 68 + j * 16], 68);
                wmma::mma_sync(accS[j], af, bf, accS[j]);
            }
        }
#pragma unroll
        for (int j = 0; j < 4; j++) {
#pragma unroll
            for (int e = 0; e < accS[j].num_elements; e++)
                accS[j].x[e] = t32(__expf(accS[j].x[e]));
            wmma::store_matrix_sync(&Sh[(wl * 16) * 68 + j * 16], accS[j], 68,
                                    wmma::mem_row_major);
        }
    }
    __syncthreads();

    {   // row sums only (no max): 2 thr/row
        int h2 = tid >> 7, local = tid & 127;
        int row = local >> 1, half = local & 1;
        float* S = sm + h2 * 11200 + 6784 + row * 68 + half * 32;
        float sum = 0.f;
#pragma unroll
        for (int e = 0; e < 32; e++) sum += S[e];
        sum += __shfl_xor_sync(0xffffffffu, sum, 1);
        if (half == 0) (sm + h2 * 11200 + 11136)[row] = 1.f / sum;
    }

    {   // O = P @ V  (64x32, k=64) -> store into Q strip
        wmma::fragment<wmma::accumulator, 16, 16, 8, float> accO[2];
#pragma unroll
        for (int j = 0; j < 2; j++) wmma::fill_fragment(accO[j], 0.f);
#pragma unroll
        for (int kk = 0; kk < 64; kk += 8) {
            wmma::fragment<wmma::matrix_a, 16, 16, 8, wmma::precision::tf32,
                           wmma::row_major> af;
            wmma::load_matrix_sync(af, &Sh[(wl * 16) * 68 + kk], 68);
#pragma unroll
            for (int j = 0; j < 2; j++) {
                wmma::fragment<wmma::matrix_b, 16, 16, 8, wmma::precision::tf32,
                               wmma::row_major> bf;
                wmma::load_matrix_sync(bf, &Vh[kk * 36 + j * 16], 36);
                wmma::mma_sync(accO[j], af, bf, accO[j]);
            }
        }
#pragma unroll
        for (int j = 0; j < 2; j++)
            wmma::store_matrix_sync(&Qh[(wl * 16) * 36 + j * 16], accO[j], 36,
                                    wmma::mem_row_major);
    }
    __syncthreads();

#pragma unroll
    for (int i = 0; i < 4; i++) {
        int idx = tid + i * 256;
        int h2 = idx >> 9;
        int r  = (idx >> 3) & 63;
        int c  = (idx & 7) * 4;
        int hg = (int)blockIdx.y * 2 + h2;
        float* Q = sm + h2 * 11200;
        float inv = (sm + h2 * 11200 + 11136)[r];
        float4 o = make_float4(t32(Q[r * 36 + c] * inv), t32(Q[r * 36 + c + 1] * inv),
                               t32(Q[r * 36 + c + 2] * inv), t32(Q[r * 36 + c + 3] * inv));
        size_t token = ((size_t)(b * 128 + wy * 8 + (r >> 3))) * 128 + wx * 8 + (r & 7);
        *(float4*)&att[token * 256 + hg * 32 + c] = o;
    }
}

// ---------------------------------------------------------------------------
// Grid (dilated) attention (heads 4..7). CTA = (cell, head, 64-query tile),
// 256 thr. Keys chunked 4x64; no-max softmax; O kept in wmma accumulator
// registers across chunks. smem floats: Q[64][36]@0 (later O), Kt[32][68]@2304,
// V[64][36]@4480, S[64][68]@6784, l[64]@11136 -> 11200 fl = 44800 B, 2 CTA/SM.
// ---------------------------------------------------------------------------
__global__ __launch_bounds__(256, 2) void attn_grid_tc(
    const float* __restrict__ qkv, float* __restrict__ att)
{
    extern __shared__ float sm[];
    float* Q  = sm;          // 64x36 (reused for O at the end)
    float* Kt = sm + 2304;   // 32x68
    float* V  = sm + 4480;   // 64x36
    float* S  = sm + 6784;   // 64x68
    float* l  = sm + 11136;  // 64

    const int cid = blockIdx.x;
    const int b = cid >> 6, s1 = (cid >> 3) & 7, s2 = cid & 7;
    const int hq = blockIdx.y;
    const int h = 4 + (hq >> 2), qt = hq & 3;
    const int tid = threadIdx.x;
    const int warp = tid >> 5;
    const int wl = warp & 3;       // row tile
    const int wc = warp >> 2;      // 0..1: col tile for O, col pair for S
    const float scale = 0.17677669529663687f;

    // Stage Q (scaled, tf32) and zero l
#pragma unroll
    for (int i = 0; i < 2; i++) {
        int idx = tid + i * 256;       // 0..511
        int r = idx >> 3, c = (idx & 7) * 4;
        int qq = qt * 64 + r;
        size_t token = ((size_t)(b * 128 + (qq >> 4) * 8 + s1)) * 128 + (qq & 15) * 8 + s2;
        float4 q4 = *(const float4*)(qkv + token * 768 + h * 32 + c);
        Q[r * 36 + c + 0] = t32(q4.x * scale);
        Q[r * 36 + c + 1] = t32(q4.y * scale);
        Q[r * 36 + c + 2] = t32(q4.z * scale);
        Q[r * 36 + c + 3] = t32(q4.w * scale);
    }
    if (tid < 64) l[tid] = 0.f;

    // O accumulator (per-warp 16x16 tile), persists across key chunks
    wmma::fragment<wmma::accumulator, 16, 16, 8, float> accO;
    wmma::fill_fragment(accO, 0.f);

    for (int ck = 0; ck < 4; ck++) {
        __syncthreads();   // prev PV done (S,V free); Q/l staged on ck=0
        // Stage 64 keys: Kt (transposed) + V
#pragma unroll
        for (int i = 0; i < 2; i++) {
            int idx = tid + i * 256;   // 0..511
            int rk = idx >> 3, c = (idx & 7) * 4;
            int kk = ck * 64 + rk;
            size_t ktok = ((size_t)(b * 128 + (kk >> 4) * 8 + s1)) * 128 + (kk & 15) * 8 + s2;
            const float* base = qkv + ktok * 768 + h * 32 + c;
            float4 k4 = *(const float4*)(base + 256);
            float4 v4 = *(const float4*)(base + 512);
            Kt[(c + 0) * 68 + rk] = t32(k4.x);
            Kt[(c + 1) * 68 + rk] = t32(k4.y);
            Kt[(c + 2) * 68 + rk] = t32(k4.z);
            Kt[(c + 3) * 68 + rk] = t32(k4.w);
            V[rk * 36 + c + 0] = t32(v4.x);
            V[rk * 36 + c + 1] = t32(v4.y);
            V[rk * 36 + c + 2] = t32(v4.z);
            V[rk * 36 + c + 3] = t32(v4.w);
        }
        __syncthreads();

        // S = exp(Q @ Kc^T) (64x64, k=32): 16 tiles, 2 per warp; exp on regs
        {
            wmma::fragment<wmma::matrix_a, 16, 16, 8, wmma::precision::tf32,
                           wmma::row_major> af[4];
#pragma unroll
            for (int ki = 0; ki < 4; ki++)
                wmma::load_matrix_sync(af[ki], &Q[(wl * 16) * 36 + ki * 8], 36);
#pragma unroll
            for (int jj = 0; jj < 2; jj++) {
                int j = wc * 2 + jj;
                wmma::fragment<wmma::accumulator, 16, 16, 8, float> accS;
                wmma::fill_fragment(accS, 0.f);
#pragma unroll
                for (int ki = 0; ki < 4; ki++) {
                    wmma::fragment<wmma::matrix_b, 16, 16, 8, wmma::precision::tf32,
                                   wmma::row_major> bf;
                    wmma::load_matrix_sync(bf, &Kt[(ki * 8) * 68 + j * 16], 68);
                    wmma::mma_sync(accS, af[ki], bf, accS);
                }
#pragma unroll
                for (int e = 0; e < accS.num_elements; e++)
                    accS.x[e] = t32(__expf(accS.x[e]));
                wmma::store_matrix_sync(&S[(wl * 16) * 68 + j * 16], accS, 68,
                                        wmma::mem_row_major);
            }
        }
        __syncthreads();

        // Row-sum accumulation (no max): 4 thr/row, 16 elems each
        {
            int row = tid >> 2, q4 = tid & 3;
            const float* Sp = S + row * 68 + q4 * 16;
            float sum = 0.f;
#pragma unroll
            for (int e = 0; e < 16; e++) sum += Sp[e];
            sum += __shfl_xor_sync(0xffffffffu, sum, 1);
            sum += __shfl_xor_sync(0xffffffffu, sum, 2);
            if (q4 == 0) l[row] += sum;
        }

        // O += P @ Vc (64x32, k=64): warp tile (wl, wc)
#pragma unroll
        for (int ks = 0; ks < 8; ks++) {
            int kk = ks * 8;
            wmma::fragment<wmma::matrix_a, 16, 16, 8, wmma::precision::tf32,
                           wmma::row_major> af;
            wmma::fragment<wmma::matrix_b, 16, 16, 8, wmma::precision::tf32,
                           wmma::row_major> bf;
            wmma::load_matrix_sync(af, &S[(wl * 16) * 68 + kk], 68);
            wmma::load_matrix_sync(bf, &V[kk * 36 + wc * 16], 36);
            wmma::mma_sync(accO, af, bf, accO);
        }
    }
    __syncthreads();

    // Store O acc into Q strip, then normalized writeout
    wmma::store_matrix_sync(&Q[(wl * 16) * 36 + wc * 16], accO, 36,
                            wmma::mem_row_major);
    __syncthreads();

#pragma unroll
    for (int i = 0; i < 2; i++) {
        int idx = tid + i * 256;
        int r = idx >> 3, c = (idx & 7) * 4;
        float inv = 1.f / l[r];
        float4 o = make_float4(t32(Q[r * 36 + c] * inv), t32(Q[r * 36 + c + 1] * inv),
                               t32(Q[r * 36 + c + 2] * inv), t32(Q[r * 36 + c + 3] * inv));
        int qq = qt * 64 + r;
        size_t token = ((size_t)(b * 128 + (qq >> 4) * 8 + s1)) * 128 + (qq & 15) * 8 + s2;
        *(float4*)&att[token * 256 + h * 32 + c] = o;
    }
}

// ---------------------------------------------------------------------------
extern "C" void kernel_launch(void* const* d_in, const int* in_sizes, int n_in,
                              void* d_out, int out_size)
{
    (void)in_sizes; (void)n_in; (void)out_size;
    const float* x     = (const float*)d_in[0];
    const float* Wqkv  = (const float*)d_in[1];
    const float* Wproj = (const float*)d_in[2];
    const float* bproj = (const float*)d_in[3];
    float* out = (float*)d_out;

    float *qkv = nullptr, *att = nullptr, *wq = nullptr, *wp = nullptr;
    cudaGetSymbolAddress((void**)&qkv, g_qkv);
    cudaGetSymbolAddress((void**)&att, g_att);
    cudaGetSymbolAddress((void**)&wq,  g_wq);
    cudaGetSymbolAddress((void**)&wp,  g_wp);

    cudaFuncSetAttribute(gemm_wmma, cudaFuncAttributeMaxDynamicSharedMemorySize, 105984);
    cudaFuncSetAttribute(attn_local_tc, cudaFuncAttributeMaxDynamicSharedMemorySize, 89600);
    cudaFuncSetAttribute(attn_grid_tc, cudaFuncAttributeMaxDynamicSharedMemorySize, 44800);

    // 0) pre-round x (into g_att, free until attention) and weights to tf32
    cvt_inputs<<<4096, 256>>>(x, Wqkv, Wproj, att, wq, wp);
    // 1) QKV = xt @ W_qkv
    gemm_wmma<<<dim3(6, 1024), 256, 105984>>>(att, wq, nullptr, qkv, 768);
    // 2) local window attention (heads 0..3) — overwrites g_att with att
    attn_local_tc<<<dim3(2048, 2), 256, 89600>>>(qkv, att);
    // 3) dilated grid attention (heads 4..7) — chunked, register O acc
    attn_grid_tc<<<dim3(512, 16), 256, 44800>>>(qkv, att);
    // 4) out = att @ W_proj + b_proj
    gemm_wmma<<<dim3(2, 1024), 256, 105984>>>(att, wp, bproj, out, 256);
}

// round 9
// speedup vs baseline: 1.2001x; 1.0447x over previous
#include <cuda_runtime.h>
#include <mma.h>
using namespace nvcuda;

// Problem constants: B=8, H=W=128, C=256, NUM_HEADS=8, HD=32, WINDOW=8
#define TOKENS 131072

// Scratch (allocation-free rule: device globals)
__device__ float g_qkv[100663296u];  // [token][3][head][32]  (tf32-rounded)
__device__ float g_att[33554432u];   // xt (pre-GEMM1) then att [token][256]
__device__ float g_wq[196608];       // tf32-rounded W_qkv
__device__ float g_wp[65536];        // tf32-rounded W_proj

__device__ __forceinline__ float t32(float x) { return wmma::__float_to_tf32(x); }

__device__ __forceinline__ void cp_async16(void* smem, const void* gmem) {
    unsigned s = (unsigned)__cvta_generic_to_shared(smem);
    asm volatile("cp.async.cg.shared.global [%0], [%1], 16;\n" :: "r"(s), "l"(gmem));
}
__device__ __forceinline__ void cp_commit() { asm volatile("cp.async.commit_group;\n"); }
__device__ __forceinline__ void cp_wait1()  { asm volatile("cp.async.wait_group 1;\n"); }
__device__ __forceinline__ void cp_wait0()  { asm volatile("cp.async.wait_group 0;\n"); }

// ---------------------------------------------------------------------------
// Pre-round inputs to tf32 (RN) once: x -> xt, weights -> g_wq/g_wp.
// ---------------------------------------------------------------------------
__global__ void cvt_inputs(const float* __restrict__ x,
                           const float* __restrict__ wq,
                           const float* __restrict__ wp,
                           float* __restrict__ xt,
                           float* __restrict__ wqt,
                           float* __restrict__ wpt)
{
    const int stride = gridDim.x * blockDim.x;
    const int tid0 = blockIdx.x * blockDim.x + threadIdx.x;
    for (int i = tid0; i < 33554432 / 4; i += stride) {
        float4 v = ((const float4*)x)[i];
        v.x = t32(v.x); v.y = t32(v.y); v.z = t32(v.z); v.w = t32(v.w);
        ((float4*)xt)[i] = v;
    }
    for (int i = tid0; i < (196608 + 65536) / 4; i += stride) {
        if (i < 49152) {
            float4 v = ((const float4*)wq)[i];
            v.x = t32(v.x); v.y = t32(v.y); v.z = t32(v.z); v.w = t32(v.w);
            ((float4*)wqt)[i] = v;
        } else {
            float4 v = ((const float4*)wp)[i - 49152];
            v.x = t32(v.x); v.y = t32(v.y); v.z = t32(v.z); v.w = t32(v.w);
            ((float4*)wpt)[i - 49152] = v;
        }
    }
}

// ---------------------------------------------------------------------------
// TF32 GEMM: C[M,N]=A[M,256]@B[256,N] (+bias). Inputs pre-rounded: NO CVTs.
// BM=BN=128, BK=32, 3-stage cp.async. round_out=1 -> tf32-round the output.
// ---------------------------------------------------------------------------
__global__ __launch_bounds__(256, 2) void gemm_wmma(
    const float* __restrict__ A, const float* __restrict__ B,
    const float* __restrict__ bias, float* __restrict__ C, int N, int round_out)
{
    extern __shared__ float sm[];
    const int tid  = threadIdx.x;
    const int warp = tid >> 5;
    const int lane = tid & 31;
    const int wm = warp >> 2, wn = warp & 3;
    const int bn = blockIdx.x * 128;   // fast dim = cols -> A L2 reuse
    const int bm = blockIdx.y * 128;

    wmma::fragment<wmma::accumulator, 16, 16, 8, float> acc[4][2];
#pragma unroll
    for (int i = 0; i < 4; i++)
#pragma unroll
        for (int j = 0; j < 2; j++) wmma::fill_fragment(acc[i][j], 0.f);

    auto load_tile = [&](int s, int k0) {
        float* As = sm + s * 8832;
        float* Bs = As + 4608;
#pragma unroll
        for (int t = 0; t < 4; t++) {
            int idx = tid + t * 256;                 // 0..1023
            int ar = idx >> 3, ac = (idx & 7) * 4;   // A: 128x32
            cp_async16(&As[ar * 36 + ac], A + (size_t)(bm + ar) * 256 + k0 + ac);
            int br = idx >> 5, bc = (idx & 31) * 4;  // B: 32x128
            cp_async16(&Bs[br * 132 + bc], B + (size_t)(k0 + br) * N + bn + bc);
        }
        cp_commit();
    };

    load_tile(0, 0);
    load_tile(1, 32);
    const int NK = 8;  // 256/32
    for (int kt = 0; kt < NK; kt++) {
        if (kt == NK - 1) cp_wait0(); else cp_wait1();
        __syncthreads();
        if (kt + 2 < NK) load_tile((kt + 2) % 3, (kt + 2) * 32);
        const float* As = sm + (kt % 3) * 8832;
        const float* Bs = As + 4608;
#pragma unroll
        for (int kk = 0; kk < 32; kk += 8) {
            wmma::fragment<wmma::matrix_a, 16, 16, 8, wmma::precision::tf32,
                           wmma::row_major> af[4];
            wmma::fragment<wmma::matrix_b, 16, 16, 8, wmma::precision::tf32,
                           wmma::row_major> bf[2];
#pragma unroll
            for (int i = 0; i < 4; i++)
                wmma::load_matrix_sync(af[i], &As[(wm * 64 + i * 16) * 36 + kk], 36);
#pragma unroll
            for (int j = 0; j < 2; j++)
                wmma::load_matrix_sync(bf[j], &Bs[kk * 132 + wn * 32 + j * 16], 132);
#pragma unroll
            for (int i = 0; i < 4; i++)
#pragma unroll
                for (int j = 0; j < 2; j++)
                    wmma::mma_sync(acc[i][j], af[i], bf[j], acc[i][j]);
        }
    }
    __syncthreads();

    // Epilogue via private smem strip
    float* wb = sm + warp * 320;   // 16 x 20
    const int r = lane >> 1, c0 = (lane & 1) * 8;
#pragma unroll
    for (int i = 0; i < 4; i++) {
#pragma unroll
        for (int j = 0; j < 2; j++) {
            wmma::store_matrix_sync(wb, acc[i][j], 20, wmma::mem_row_major);
            __syncwarp();
            float4 v0 = *(float4*)&wb[r * 20 + c0];
            float4 v1 = *(float4*)&wb[r * 20 + c0 + 4];
            int grow = bm + wm * 64 + i * 16 + r;
            int gcol = bn + wn * 32 + j * 16 + c0;
            if (bias) {
                v0.x += bias[gcol + 0]; v0.y += bias[gcol + 1];
                v0.z += bias[gcol + 2]; v0.w += bias[gcol + 3];
                v1.x += bias[gcol + 4]; v1.y += bias[gcol + 5];
                v1.z += bias[gcol + 6]; v1.w += bias[gcol + 7];
            }
            if (round_out) {
                v0.x = t32(v0.x); v0.y = t32(v0.y); v0.z = t32(v0.z); v0.w = t32(v0.w);
                v1.x = t32(v1.x); v1.y = t32(v1.y); v1.z = t32(v1.z); v1.w = t32(v1.w);
            }
            *(float4*)&C[(size_t)grow * N + gcol]     = v0;
            *(float4*)&C[(size_t)grow * N + gcol + 4] = v1;
            __syncwarp();
        }
    }
}

// ---------------------------------------------------------------------------
// Local window attention (heads 0..3). CTA = 1 window x 2 heads. 256 thr.
// qkv pre-rounded -> pure cp.async staging; K natural layout (col_major B);
// scale folded into exp. Per-head smem: Q[64][36], K[64][36], V[64][36],
// S[64][68], l[64] = 11328 fl; x2 heads = 90624 B. 2 CTA/SM.
// ---------------------------------------------------------------------------
__global__ __launch_bounds__(256, 2) void attn_local_tc(
    const float* __restrict__ qkv, float* __restrict__ att)
{
    extern __shared__ float sm[];
    const int wid = blockIdx.x;
    const int b = wid >> 8, wy = (wid >> 4) & 15, wx = wid & 15;
    const int tid = threadIdx.x;
    const int warp = tid >> 5;
    const int hh = warp >> 2, wl = warp & 3;
    const float scale = 0.17677669529663687f;

    // Stage Q, K, V via cp.async (no conversion needed)
#pragma unroll
    for (int i = 0; i < 4; i++) {
        int idx = tid + i * 256;           // 0..1023
        int h2 = idx >> 9;
        int r  = (idx >> 3) & 63;
        int seg = (idx & 7) * 4;
        int hg = (int)blockIdx.y * 2 + h2;
        size_t token = ((size_t)(b * 128 + wy * 8 + (r >> 3))) * 128 + wx * 8 + (r & 7);
        const float* base = qkv + token * 768 + hg * 32 + seg;
        float* hb = sm + h2 * 11328;
        cp_async16(&hb[r * 36 + seg], base);                 // Q
        cp_async16(&hb[2304 + r * 36 + seg], base + 256);    // K
        cp_async16(&hb[4608 + r * 36 + seg], base + 512);    // V
    }
    cp_commit();
    cp_wait0();
    __syncthreads();

    float* Qh = sm + hh * 11328;
    float* Kh = Qh + 2304;
    float* Vh = Qh + 4608;
    float* Sh = Qh + 6912;
    float* lh = Qh + 11264;

    {   // S = exp(scale * Q @ K^T)  (64x64, k=32), exp+scale on acc registers
        wmma::fragment<wmma::matrix_a, 16, 16, 8, wmma::precision::tf32,
                       wmma::row_major> af[4];
#pragma unroll
        for (int ki = 0; ki < 4; ki++)
            wmma::load_matrix_sync(af[ki], &Qh[(wl * 16) * 36 + ki * 8], 36);
#pragma unroll
        for (int j = 0; j < 4; j++) {
            wmma::fragment<wmma::accumulator, 16, 16, 8, float> accS;
            wmma::fill_fragment(accS, 0.f);
#pragma unroll
            for (int ki = 0; ki < 4; ki++) {
                wmma::fragment<wmma::matrix_b, 16, 16, 8, wmma::precision::tf32,
                               wmma::col_major> bf;
                wmma::load_matrix_sync(bf, &Kh[(j * 16) * 36 + ki * 8], 36);
                wmma::mma_sync(accS, af[ki], bf, accS);
            }
#pragma unroll
            for (int e = 0; e < accS.num_elements; e++)
                accS.x[e] = t32(__expf(accS.x[e] * scale));
            wmma::store_matrix_sync(&Sh[(wl * 16) * 68 + j * 16], accS, 68,
                                    wmma::mem_row_major);
        }
    }
    __syncthreads();

    {   // row sums only (no max): 2 thr/row
        int h2 = tid >> 7, local = tid & 127;
        int row = local >> 1, half = local & 1;
        float* S = sm + h2 * 11328 + 6912 + row * 68 + half * 32;
        float sum = 0.f;
#pragma unroll
        for (int e = 0; e < 32; e++) sum += S[e];
        sum += __shfl_xor_sync(0xffffffffu, sum, 1);
        if (half == 0) (sm + h2 * 11328 + 11264)[row] = 1.f / sum;
    }

    {   // O = P @ V  (64x32, k=64) -> store into Q strip
        wmma::fragment<wmma::accumulator, 16, 16, 8, float> accO[2];
#pragma unroll
        for (int j = 0; j < 2; j++) wmma::fill_fragment(accO[j], 0.f);
#pragma unroll
        for (int kk = 0; kk < 64; kk += 8) {
            wmma::fragment<wmma::matrix_a, 16, 16, 8, wmma::precision::tf32,
                           wmma::row_major> af;
            wmma::load_matrix_sync(af, &Sh[(wl * 16) * 68 + kk], 68);
#pragma unroll
            for (int j = 0; j < 2; j++) {
                wmma::fragment<wmma::matrix_b, 16, 16, 8, wmma::precision::tf32,
                               wmma::row_major> bf;
                wmma::load_matrix_sync(bf, &Vh[kk * 36 + j * 16], 36);
                wmma::mma_sync(accO[j], af, bf, accO[j]);
            }
        }
#pragma unroll
        for (int j = 0; j < 2; j++)
            wmma::store_matrix_sync(&Qh[(wl * 16) * 36 + j * 16], accO[j], 36,
                                    wmma::mem_row_major);
    }
    __syncthreads();

#pragma unroll
    for (int i = 0; i < 4; i++) {
        int idx = tid + i * 256;
        int h2 = idx >> 9;
        int r  = (idx >> 3) & 63;
        int c  = (idx & 7) * 4;
        int hg = (int)blockIdx.y * 2 + h2;
        float* Q = sm + h2 * 11328;
        float inv = (sm + h2 * 11328 + 11264)[r];
        float4 o = make_float4(t32(Q[r * 36 + c] * inv), t32(Q[r * 36 + c + 1] * inv),
                               t32(Q[r * 36 + c + 2] * inv), t32(Q[r * 36 + c + 3] * inv));
        size_t token = ((size_t)(b * 128 + wy * 8 + (r >> 3))) * 128 + wx * 8 + (r & 7);
        *(float4*)&att[token * 256 + hg * 32 + c] = o;
    }
}

// ---------------------------------------------------------------------------
// Grid (dilated) attention (heads 4..7). CTA = (cell, head, 64-query tile),
// 256 thr. 4x64-key chunks; double-buffered cp.async K/V prefetch; no-max
// softmax; O in wmma accumulators. smem floats: Q[64][36]@0, K2[2][64][36]@2304,
// V2[2][64][36]@6912, S[64][68]@11520, l[64]@15872 -> 15936 fl = 63744 B.
// ---------------------------------------------------------------------------
__global__ __launch_bounds__(256, 2) void attn_grid_tc(
    const float* __restrict__ qkv, float* __restrict__ att)
{
    extern __shared__ float sm[];
    float* Q = sm;            // 64x36 (reused for O at the end)
    float* S = sm + 11520;    // 64x68
    float* l = sm + 15872;    // 64

    const int cid = blockIdx.x;
    const int b = cid >> 6, s1 = (cid >> 3) & 7, s2 = cid & 7;
    const int hq = blockIdx.y;
    const int h = 4 + (hq >> 2), qt = hq & 3;
    const int tid = threadIdx.x;
    const int warp = tid >> 5;
    const int wl = warp & 3;       // row tile
    const int wc = warp >> 2;      // 0..1: col tile for O, col pair for S
    const float scale = 0.17677669529663687f;

    auto stage = [&](int ck) {
        float* Kd = sm + 2304 + (ck & 1) * 2304;
        float* Vd = sm + 6912 + (ck & 1) * 2304;
#pragma unroll
        for (int i = 0; i < 2; i++) {
            int idx = tid + i * 256;   // 0..511
            int rk = idx >> 3, seg = (idx & 7) * 4;
            int kk = ck * 64 + rk;
            size_t ktok = ((size_t)(b * 128 + (kk >> 4) * 8 + s1)) * 128 + (kk & 15) * 8 + s2;
            const float* base = qkv + ktok * 768 + h * 32 + seg;
            cp_async16(&Kd[rk * 36 + seg], base + 256);
            cp_async16(&Vd[rk * 36 + seg], base + 512);
        }
        cp_commit();
    };

    // Stage Q (cp.async) + first K/V chunk (committed together in stage(0))
#pragma unroll
    for (int i = 0; i < 2; i++) {
        int idx = tid + i * 256;       // 0..511
        int r = idx >> 3, seg = (idx & 7) * 4;
        int qq = qt * 64 + r;
        size_t token = ((size_t)(b * 128 + (qq >> 4) * 8 + s1)) * 128 + (qq & 15) * 8 + s2;
        cp_async16(&Q[r * 36 + seg], qkv + token * 768 + h * 32 + seg);
    }
    if (tid < 64) l[tid] = 0.f;
    stage(0);

    // O accumulator (per-warp 16x16 tile), persists across key chunks
    wmma::fragment<wmma::accumulator, 16, 16, 8, float> accO;
    wmma::fill_fragment(accO, 0.f);

    for (int ck = 0; ck < 4; ck++) {
        cp_wait0();
        __syncthreads();               // data visible; prev compute finished
        if (ck < 3) stage(ck + 1);     // prefetch overlaps this chunk's compute

        const float* K = sm + 2304 + (ck & 1) * 2304;
        const float* V = sm + 6912 + (ck & 1) * 2304;

        // S = exp(scale * Q @ Kc^T) (64x64, k=32): 16 tiles, 2 per warp
        {
            wmma::fragment<wmma::matrix_a, 16, 16, 8, wmma::precision::tf32,
                           wmma::row_major> af[4];
#pragma unroll
            for (int ki = 0; ki < 4; ki++)
                wmma::load_matrix_sync(af[ki], &Q[(wl * 16) * 36 + ki * 8], 36);
#pragma unroll
            for (int jj = 0; jj < 2; jj++) {
                int j = wc * 2 + jj;
                wmma::fragment<wmma::accumulator, 16, 16, 8, float> accS;
                wmma::fill_fragment(accS, 0.f);
#pragma unroll
                for (int ki = 0; ki < 4; ki++) {
                    wmma::fragment<wmma::matrix_b, 16, 16, 8, wmma::precision::tf32,
                                   wmma::col_major> bf;
                    wmma::load_matrix_sync(bf, &K[(j * 16) * 36 + ki * 8], 36);
                    wmma::mma_sync(accS, af[ki], bf, accS);
                }
#pragma unroll
                for (int e = 0; e < accS.num_elements; e++)
                    accS.x[e] = t32(__expf(accS.x[e] * scale));
                wmma::store_matrix_sync(&S[(wl * 16) * 68 + j * 16], accS, 68,
                                        wmma::mem_row_major);
            }
        }
        __syncthreads();

        // Row-sum accumulation (no max): 4 thr/row, 16 elems each
        {
            int row = tid >> 2, q4 = tid & 3;
            const float* Sp = S + row * 68 + q4 * 16;
            float sum = 0.f;
#pragma unroll
            for (int e = 0; e < 16; e++) sum += Sp[e];
            sum += __shfl_xor_sync(0xffffffffu, sum, 1);
            sum += __shfl_xor_sync(0xffffffffu, sum, 2);
            if (q4 == 0) l[row] += sum;
        }

        // O += P @ Vc (64x32, k=64): warp tile (wl, wc)
#pragma unroll
        for (int ks = 0; ks < 8; ks++) {
            int kk = ks * 8;
            wmma::fragment<wmma::matrix_a, 16, 16, 8, wmma::precision::tf32,
                           wmma::row_major> af;
            wmma::fragment<wmma::matrix_b, 16, 16, 8, wmma::precision::tf32,
                           wmma::row_major> bf;
            wmma::load_matrix_sync(af, &S[(wl * 16) * 68 + kk], 68);
            wmma::load_matrix_sync(bf, &V[kk * 36 + wc * 16], 36);
            wmma::mma_sync(accO, af, bf, accO);
        }
    }
    __syncthreads();

    // Store O acc into Q strip, then normalized writeout
    wmma::store_matrix_sync(&Q[(wl * 16) * 36 + wc * 16], accO, 36,
                            wmma::mem_row_major);
    __syncthreads();

#pragma unroll
    for (int i = 0; i < 2; i++) {
        int idx = tid + i * 256;
        int r = idx >> 3, c = (idx & 7) * 4;
        float inv = 1.f / l[r];
        float4 o = make_float4(t32(Q[r * 36 + c] * inv), t32(Q[r * 36 + c + 1] * inv),
                               t32(Q[r * 36 + c + 2] * inv), t32(Q[r * 36 + c + 3] * inv));
        int qq = qt * 64 + r;
        size_t token = ((size_t)(b * 128 + (qq >> 4) * 8 + s1)) * 128 + (qq & 15) * 8 + s2;
        *(float4*)&att[token * 256 + h * 32 + c] = o;
    }
}

// ---------------------------------------------------------------------------
extern "C" void kernel_launch(void* const* d_in, const int* in_sizes, int n_in,
                              void* d_out, int out_size)
{
    (void)in_sizes; (void)n_in; (void)out_size;
    const float* x     = (const float*)d_in[0];
    const float* Wqkv  = (const float*)d_in[1];
    const float* Wproj = (const float*)d_in[2];
    const float* bproj = (const float*)d_in[3];
    float* out = (float*)d_out;

    float *qkv = nullptr, *att = nullptr, *wq = nullptr, *wp = nullptr;
    cudaGetSymbolAddress((void**)&qkv, g_qkv);
    cudaGetSymbolAddress((void**)&att, g_att);
    cudaGetSymbolAddress((void**)&wq,  g_wq);
    cudaGetSymbolAddress((void**)&wp,  g_wp);

    cudaFuncSetAttribute(gemm_wmma, cudaFuncAttributeMaxDynamicSharedMemorySize, 105984);
    cudaFuncSetAttribute(attn_local_tc, cudaFuncAttributeMaxDynamicSharedMemorySize, 90624);
    cudaFuncSetAttribute(attn_grid_tc, cudaFuncAttributeMaxDynamicSharedMemorySize, 63744);

    // 0) pre-round x (into g_att, free until attention) and weights to tf32
    cvt_inputs<<<4096, 256>>>(x, Wqkv, Wproj, att, wq, wp);
    // 1) QKV = xt @ W_qkv  (tf32-rounded output for cp.async attention staging)
    gemm_wmma<<<dim3(6, 1024), 256, 105984>>>(att, wq, nullptr, qkv, 768, 1);
    // 2) local window attention (heads 0..3) — overwrites g_att with att
    attn_local_tc<<<dim3(2048, 2), 256, 90624>>>(qkv, att);
    // 3) dilated grid attention (heads 4..7) — chunked, prefetch, register O
    attn_grid_tc<<<dim3(512, 16), 256, 63744>>>(qkv, att);
    // 4) out = att @ W_proj + b_proj (fp32 output)
    gemm_wmma<<<dim3(2, 1024), 256, 105984>>>(att, wp, bproj, out, 256, 0);
}

// round 10
// speedup vs baseline: 1.2533x; 1.0443x over previous
#include <cuda_runtime.h>
#include <mma.h>
using namespace nvcuda;

// Problem constants: B=8, H=W=128, C=256, NUM_HEADS=8, HD=32, WINDOW=8
#define TOKENS 131072

// Scratch (allocation-free rule: device globals)
__device__ float g_qkv[100663296u];  // [token][3][head][32]  (tf32-rounded)
__device__ float g_att[33554432u];   // xt (pre-GEMM1) then att [token][256]
__device__ float g_wq[196608];       // tf32-rounded W_qkv
__device__ float g_wp[65536];        // tf32-rounded W_proj

__device__ __forceinline__ float t32(float x) { return wmma::__float_to_tf32(x); }

__device__ __forceinline__ void cp_async16(void* smem, const void* gmem) {
    unsigned s = (unsigned)__cvta_generic_to_shared(smem);
    asm volatile("cp.async.cg.shared.global [%0], [%1], 16;\n" :: "r"(s), "l"(gmem));
}
__device__ __forceinline__ void cp_commit() { asm volatile("cp.async.commit_group;\n"); }
__device__ __forceinline__ void cp_wait1()  { asm volatile("cp.async.wait_group 1;\n"); }
__device__ __forceinline__ void cp_wait0()  { asm volatile("cp.async.wait_group 0;\n"); }

// ---------------------------------------------------------------------------
// Pre-round inputs to tf32 (RN) once: x -> xt, weights -> g_wq/g_wp.
// ---------------------------------------------------------------------------
__global__ void cvt_inputs(const float* __restrict__ x,
                           const float* __restrict__ wq,
                           const float* __restrict__ wp,
                           float* __restrict__ xt,
                           float* __restrict__ wqt,
                           float* __restrict__ wpt)
{
    const int stride = gridDim.x * blockDim.x;
    const int tid0 = blockIdx.x * blockDim.x + threadIdx.x;
    for (int i = tid0; i < 33554432 / 4; i += stride) {
        float4 v = ((const float4*)x)[i];
        v.x = t32(v.x); v.y = t32(v.y); v.z = t32(v.z); v.w = t32(v.w);
        ((float4*)xt)[i] = v;
    }
    for (int i = tid0; i < (196608 + 65536) / 4; i += stride) {
        if (i < 49152) {
            float4 v = ((const float4*)wq)[i];
            v.x = t32(v.x); v.y = t32(v.y); v.z = t32(v.z); v.w = t32(v.w);
            ((float4*)wqt)[i] = v;
        } else {
            float4 v = ((const float4*)wp)[i - 49152];
            v.x = t32(v.x); v.y = t32(v.y); v.z = t32(v.z); v.w = t32(v.w);
            ((float4*)wpt)[i - 49152] = v;
        }
    }
}

// ---------------------------------------------------------------------------
// TF32 GEMM: C[M,N]=A[M,256]@B[256,N] (+bias). Inputs pre-rounded: NO CVTs.
// BM=BN=128, BK=32, 3-stage cp.async. round_out=1 -> tf32-round the output.
// Epilogue: bulk per-warp 64x36 strip, single syncwarp, coalesced stores.
// ---------------------------------------------------------------------------
__global__ __launch_bounds__(256, 2) void gemm_wmma(
    const float* __restrict__ A, const float* __restrict__ B,
    const float* __restrict__ bias, float* __restrict__ C, int N, int round_out)
{
    extern __shared__ float sm[];
    const int tid  = threadIdx.x;
    const int warp = tid >> 5;
    const int lane = tid & 31;
    const int wm = warp >> 2, wn = warp & 3;
    const int bn = blockIdx.x * 128;   // fast dim = cols -> A L2 reuse
    const int bm = blockIdx.y * 128;

    wmma::fragment<wmma::accumulator, 16, 16, 8, float> acc[4][2];
#pragma unroll
    for (int i = 0; i < 4; i++)
#pragma unroll
        for (int j = 0; j < 2; j++) wmma::fill_fragment(acc[i][j], 0.f);

    auto load_tile = [&](int s, int k0) {
        float* As = sm + s * 8832;
        float* Bs = As + 4608;
#pragma unroll
        for (int t = 0; t < 4; t++) {
            int idx = tid + t * 256;                 // 0..1023
            int ar = idx >> 3, ac = (idx & 7) * 4;   // A: 128x32
            cp_async16(&As[ar * 36 + ac], A + (size_t)(bm + ar) * 256 + k0 + ac);
            int br = idx >> 5, bc = (idx & 31) * 4;  // B: 32x128
            cp_async16(&Bs[br * 132 + bc], B + (size_t)(k0 + br) * N + bn + bc);
        }
        cp_commit();
    };

    load_tile(0, 0);
    load_tile(1, 32);
    const int NK = 8;  // 256/32
    for (int kt = 0; kt < NK; kt++) {
        if (kt == NK - 1) cp_wait0(); else cp_wait1();
        __syncthreads();
        if (kt + 2 < NK) load_tile((kt + 2) % 3, (kt + 2) * 32);
        const float* As = sm + (kt % 3) * 8832;
        const float* Bs = As + 4608;
#pragma unroll
        for (int kk = 0; kk < 32; kk += 8) {
            wmma::fragment<wmma::matrix_a, 16, 16, 8, wmma::precision::tf32,
                           wmma::row_major> af[4];
            wmma::fragment<wmma::matrix_b, 16, 16, 8, wmma::precision::tf32,
                           wmma::row_major> bf[2];
#pragma unroll
            for (int i = 0; i < 4; i++)
                wmma::load_matrix_sync(af[i], &As[(wm * 64 + i * 16) * 36 + kk], 36);
#pragma unroll
            for (int j = 0; j < 2; j++)
                wmma::load_matrix_sync(bf[j], &Bs[kk * 132 + wn * 32 + j * 16], 132);
#pragma unroll
            for (int i = 0; i < 4; i++)
#pragma unroll
                for (int j = 0; j < 2; j++)
                    wmma::mma_sync(acc[i][j], af[i], bf[j], acc[i][j]);
        }
    }
    __syncthreads();

    // Epilogue: dump all tiles to per-warp 64x36 strip, then bulk writeout.
    float* wb = sm + warp * 2304;   // 8 warps x 2304 fl = 18432 <= 26496
#pragma unroll
    for (int i = 0; i < 4; i++)
#pragma unroll
        for (int j = 0; j < 2; j++)
            wmma::store_matrix_sync(&wb[(i * 16) * 36 + j * 16], acc[i][j], 36,
                                    wmma::mem_row_major);
    __syncwarp();
#pragma unroll
    for (int it = 0; it < 16; it++) {
        int idx = lane + it * 32;      // 0..511
        int r = idx >> 3;              // 0..63
        int c = (idx & 7) * 4;         // 0..28
        float4 v = *(float4*)&wb[r * 36 + c];
        int grow = bm + wm * 64 + r;
        int gcol = bn + wn * 32 + c;
        if (bias) {
            v.x += bias[gcol + 0]; v.y += bias[gcol + 1];
            v.z += bias[gcol + 2]; v.w += bias[gcol + 3];
        }
        if (round_out) {
            v.x = t32(v.x); v.y = t32(v.y); v.z = t32(v.z); v.w = t32(v.w);
        }
        *(float4*)&C[(size_t)grow * N + gcol] = v;
    }
}

// ---------------------------------------------------------------------------
// FUSED attention: blocks [0, 8192) = grid (dilated) heads 4..7,
//                  blocks [8192, 12288) = local windows heads 0..3.
// 256 thr, dyn smem 90624B (local needs it; grid uses 63744 of it). 2 CTA/SM.
// ---------------------------------------------------------------------------
__global__ __launch_bounds__(256, 2) void attn_fused(
    const float* __restrict__ qkv, float* __restrict__ att)
{
    extern __shared__ float sm[];
    const int tid = threadIdx.x;
    const int warp = tid >> 5;
    const float scale = 0.17677669529663687f;

    if (blockIdx.x < 8192) {
        // ================= GRID (dilated) attention =================
        float* Q = sm;            // 64x36 (reused for O at the end)
        float* S = sm + 11520;    // 64x68
        float* l = sm + 15872;    // 64

        const int bid = blockIdx.x;
        const int hq = bid & 15, cid = bid >> 4;    // adjacent CTAs share tokens
        const int b = cid >> 6, s1 = (cid >> 3) & 7, s2 = cid & 7;
        const int h = 4 + (hq >> 2), qt = hq & 3;
        const int wl = warp & 3;       // row tile
        const int wc = warp >> 2;      // 0..1

        auto stage = [&](int ck) {
            float* Kd = sm + 2304 + (ck & 1) * 2304;
            float* Vd = sm + 6912 + (ck & 1) * 2304;
#pragma unroll
            for (int i = 0; i < 2; i++) {
                int idx = tid + i * 256;   // 0..511
                int rk = idx >> 3, seg = (idx & 7) * 4;
                int kk = ck * 64 + rk;
                size_t ktok = ((size_t)(b * 128 + (kk >> 4) * 8 + s1)) * 128 + (kk & 15) * 8 + s2;
                const float* base = qkv + ktok * 768 + h * 32 + seg;
                cp_async16(&Kd[rk * 36 + seg], base + 256);
                cp_async16(&Vd[rk * 36 + seg], base + 512);
            }
            cp_commit();
        };

#pragma unroll
        for (int i = 0; i < 2; i++) {
            int idx = tid + i * 256;       // 0..511
            int r = idx >> 3, seg = (idx & 7) * 4;
            int qq = qt * 64 + r;
            size_t token = ((size_t)(b * 128 + (qq >> 4) * 8 + s1)) * 128 + (qq & 15) * 8 + s2;
            cp_async16(&Q[r * 36 + seg], qkv + token * 768 + h * 32 + seg);
        }
        if (tid < 64) l[tid] = 0.f;
        stage(0);

        wmma::fragment<wmma::accumulator, 16, 16, 8, float> accO;
        wmma::fill_fragment(accO, 0.f);

        for (int ck = 0; ck < 4; ck++) {
            cp_wait0();
            __syncthreads();
            if (ck < 3) stage(ck + 1);

            const float* K = sm + 2304 + (ck & 1) * 2304;
            const float* V = sm + 6912 + (ck & 1) * 2304;

            {   // S = exp(scale * Q @ Kc^T) (64x64, k=32): 2 tiles per warp
                wmma::fragment<wmma::matrix_a, 16, 16, 8, wmma::precision::tf32,
                               wmma::row_major> af[4];
#pragma unroll
                for (int ki = 0; ki < 4; ki++)
                    wmma::load_matrix_sync(af[ki], &Q[(wl * 16) * 36 + ki * 8], 36);
#pragma unroll
                for (int jj = 0; jj < 2; jj++) {
                    int j = wc * 2 + jj;
                    wmma::fragment<wmma::accumulator, 16, 16, 8, float> accS;
                    wmma::fill_fragment(accS, 0.f);
#pragma unroll
                    for (int ki = 0; ki < 4; ki++) {
                        wmma::fragment<wmma::matrix_b, 16, 16, 8, wmma::precision::tf32,
                                       wmma::col_major> bf;
                        wmma::load_matrix_sync(bf, &K[(j * 16) * 36 + ki * 8], 36);
                        wmma::mma_sync(accS, af[ki], bf, accS);
                    }
#pragma unroll
                    for (int e = 0; e < accS.num_elements; e++)
                        accS.x[e] = t32(__expf(accS.x[e] * scale));
                    wmma::store_matrix_sync(&S[(wl * 16) * 68 + j * 16], accS, 68,
                                            wmma::mem_row_major);
                }
            }
            __syncthreads();

            {   // Row-sum accumulation: 4 thr/row, 16 elems each
                int row = tid >> 2, q4 = tid & 3;
                const float* Sp = S + row * 68 + q4 * 16;
                float sum = 0.f;
#pragma unroll
                for (int e = 0; e < 16; e++) sum += Sp[e];
                sum += __shfl_xor_sync(0xffffffffu, sum, 1);
                sum += __shfl_xor_sync(0xffffffffu, sum, 2);
                if (q4 == 0) l[row] += sum;
            }

            // O += P @ Vc (64x32, k=64): warp tile (wl, wc)
#pragma unroll
            for (int ks = 0; ks < 8; ks++) {
                int kk = ks * 8;
                wmma::fragment<wmma::matrix_a, 16, 16, 8, wmma::precision::tf32,
                               wmma::row_major> af;
                wmma::fragment<wmma::matrix_b, 16, 16, 8, wmma::precision::tf32,
                               wmma::row_major> bf;
                wmma::load_matrix_sync(af, &S[(wl * 16) * 68 + kk], 68);
                wmma::load_matrix_sync(bf, &V[kk * 36 + wc * 16], 36);
                wmma::mma_sync(accO, af, bf, accO);
            }
        }
        __syncthreads();

        wmma::store_matrix_sync(&Q[(wl * 16) * 36 + wc * 16], accO, 36,
                                wmma::mem_row_major);
        __syncthreads();

#pragma unroll
        for (int i = 0; i < 2; i++) {
            int idx = tid + i * 256;
            int r = idx >> 3, c = (idx & 7) * 4;
            float inv = 1.f / l[r];
            float4 o = make_float4(t32(Q[r * 36 + c] * inv), t32(Q[r * 36 + c + 1] * inv),
                                   t32(Q[r * 36 + c + 2] * inv), t32(Q[r * 36 + c + 3] * inv));
            int qq = qt * 64 + r;
            size_t token = ((size_t)(b * 128 + (qq >> 4) * 8 + s1)) * 128 + (qq & 15) * 8 + s2;
            *(float4*)&att[token * 256 + h * 32 + c] = o;
        }
    } else {
        // ================= LOCAL window attention =================
        const int lb = blockIdx.x - 8192;           // 0..4095
        const int wid = lb >> 1, hp = lb & 1;       // adjacent CTAs share tokens
        const int b = wid >> 8, wy = (wid >> 4) & 15, wx = wid & 15;
        const int hh = warp >> 2, wl = warp & 3;

#pragma unroll
        for (int i = 0; i < 4; i++) {
            int idx = tid + i * 256;           // 0..1023
            int h2 = idx >> 9;
            int r  = (idx >> 3) & 63;
            int seg = (idx & 7) * 4;
            int hg = hp * 2 + h2;
            size_t token = ((size_t)(b * 128 + wy * 8 + (r >> 3))) * 128 + wx * 8 + (r & 7);
            const float* base = qkv + token * 768 + hg * 32 + seg;
            float* hb = sm + h2 * 11328;
            cp_async16(&hb[r * 36 + seg], base);                 // Q
            cp_async16(&hb[2304 + r * 36 + seg], base + 256);    // K
            cp_async16(&hb[4608 + r * 36 + seg], base + 512);    // V
        }
        cp_commit();
        cp_wait0();
        __syncthreads();

        float* Qh = sm + hh * 11328;
        float* Kh = Qh + 2304;
        float* Vh = Qh + 4608;
        float* Sh = Qh + 6912;

        {   // S = exp(scale * Q @ K^T)  (64x64, k=32)
            wmma::fragment<wmma::matrix_a, 16, 16, 8, wmma::precision::tf32,
                           wmma::row_major> af[4];
#pragma unroll
            for (int ki = 0; ki < 4; ki++)
                wmma::load_matrix_sync(af[ki], &Qh[(wl * 16) * 36 + ki * 8], 36);
#pragma unroll
            for (int j = 0; j < 4; j++) {
                wmma::fragment<wmma::accumulator, 16, 16, 8, float> accS;
                wmma::fill_fragment(accS, 0.f);
#pragma unroll
                for (int ki = 0; ki < 4; ki++) {
                    wmma::fragment<wmma::matrix_b, 16, 16, 8, wmma::precision::tf32,
                                   wmma::col_major> bf;
                    wmma::load_matrix_sync(bf, &Kh[(j * 16) * 36 + ki * 8], 36);
                    wmma::mma_sync(accS, af[ki], bf, accS);
                }
#pragma unroll
                for (int e = 0; e < accS.num_elements; e++)
                    accS.x[e] = t32(__expf(accS.x[e] * scale));
                wmma::store_matrix_sync(&Sh[(wl * 16) * 68 + j * 16], accS, 68,
                                        wmma::mem_row_major);
            }
        }
        __syncthreads();

        {   // row sums only: 2 thr/row
            int h2 = tid >> 7, local = tid & 127;
            int row = local >> 1, half = local & 1;
            float* S = sm + h2 * 11328 + 6912 + row * 68 + half * 32;
            float sum = 0.f;
#pragma unroll
            for (int e = 0; e < 32; e++) sum += S[e];
            sum += __shfl_xor_sync(0xffffffffu, sum, 1);
            if (half == 0) (sm + h2 * 11328 + 11264)[row] = 1.f / sum;
        }

        {   // O = P @ V  (64x32, k=64) -> store into Q strip
            wmma::fragment<wmma::accumulator, 16, 16, 8, float> accO[2];
#pragma unroll
            for (int j = 0; j < 2; j++) wmma::fill_fragment(accO[j], 0.f);
#pragma unroll
            for (int kk = 0; kk < 64; kk += 8) {
                wmma::fragment<wmma::matrix_a, 16, 16, 8, wmma::precision::tf32,
                               wmma::row_major> af;
                wmma::load_matrix_sync(af, &Sh[(wl * 16) * 68 + kk], 68);
#pragma unroll
                for (int j = 0; j < 2; j++) {
                    wmma::fragment<wmma::matrix_b, 16, 16, 8, wmma::precision::tf32,
                                   wmma::row_major> bf;
                    wmma::load_matrix_sync(bf, &Vh[kk * 36 + j * 16], 36);
                    wmma::mma_sync(accO[j], af, bf, accO[j]);
                }
            }
#pragma unroll
            for (int j = 0; j < 2; j++)
                wmma::store_matrix_sync(&Qh[(wl * 16) * 36 + j * 16], accO[j], 36,
                                        wmma::mem_row_major);
        }
        __syncthreads();

#pragma unroll
        for (int i = 0; i < 4; i++) {
            int idx = tid + i * 256;
            int h2 = idx >> 9;
            int r  = (idx >> 3) & 63;
            int c  = (idx & 7) * 4;
            int hg = hp * 2 + h2;
            float* Q = sm + h2 * 11328;
            float inv = (sm + h2 * 11328 + 11264)[r];
            float4 o = make_float4(t32(Q[r * 36 + c] * inv), t32(Q[r * 36 + c + 1] * inv),
                                   t32(Q[r * 36 + c + 2] * inv), t32(Q[r * 36 + c + 3] * inv));
            size_t token = ((size_t)(b * 128 + wy * 8 + (r >> 3))) * 128 + wx * 8 + (r & 7);
            *(float4*)&att[token * 256 + hg * 32 + c] = o;
        }
    }
}

// ---------------------------------------------------------------------------
extern "C" void kernel_launch(void* const* d_in, const int* in_sizes, int n_in,
                              void* d_out, int out_size)
{
    (void)in_sizes; (void)n_in; (void)out_size;
    const float* x     = (const float*)d_in[0];
    const float* Wqkv  = (const float*)d_in[1];
    const float* Wproj = (const float*)d_in[2];
    const float* bproj = (const float*)d_in[3];
    float* out = (float*)d_out;

    float *qkv = nullptr, *att = nullptr, *wq = nullptr, *wp = nullptr;
    cudaGetSymbolAddress((void**)&qkv, g_qkv);
    cudaGetSymbolAddress((void**)&att, g_att);
    cudaGetSymbolAddress((void**)&wq,  g_wq);
    cudaGetSymbolAddress((void**)&wp,  g_wp);

    cudaFuncSetAttribute(gemm_wmma, cudaFuncAttributeMaxDynamicSharedMemorySize, 105984);
    cudaFuncSetAttribute(attn_fused, cudaFuncAttributeMaxDynamicSharedMemorySize, 90624);

    // 0) pre-round x (into g_att, free until attention) and weights to tf32
    cvt_inputs<<<4096, 256>>>(x, Wqkv, Wproj, att, wq, wp);
    // 1) QKV = xt @ W_qkv  (tf32-rounded output for cp.async attention staging)
    gemm_wmma<<<dim3(6, 1024), 256, 105984>>>(att, wq, nullptr, qkv, 768, 1);
    // 2+3) fused local (heads 0..3) + grid (heads 4..7) attention
    attn_fused<<<12288, 256, 90624>>>(qkv, att);
    // 4) out = att @ W_proj + b_proj (fp32 output)
    gemm_wmma<<<dim3(2, 1024), 256, 105984>>>(att, wp, bproj, out, 256, 0);
}

// round 12
// speedup vs baseline: 2.8626x; 2.2841x over previous
#include <cuda_runtime.h>
#include <cuda_fp16.h>
#include <mma.h>
#include <cstdint>
using namespace nvcuda;

// Problem constants: B=8, H=W=128, C=256, NUM_HEADS=8, HD=32, WINDOW=8
#define TOKENS 131072

// Scratch (allocation-free rule: device globals)
__device__ __half g_qkv[100663296u];  // [token][3][head][32] fp16
__device__ __half g_att[33554432u];   // xt (pre-GEMM1) then att [token][256] fp16
__device__ __half g_wq[196608];       // fp16 W_qkv [256,768] row-major
__device__ __half g_wp[65536];        // fp16 W_proj [256,256] row-major

__device__ __forceinline__ void cp_async16(void* smem, const void* gmem) {
    unsigned s = (unsigned)__cvta_generic_to_shared(smem);
    asm volatile("cp.async.cg.shared.global [%0], [%1], 16;\n" :: "r"(s), "l"(gmem));
}
__device__ __forceinline__ void cp_commit() { asm volatile("cp.async.commit_group;\n"); }
__device__ __forceinline__ void cp_wait1()  { asm volatile("cp.async.wait_group 1;\n"); }
__device__ __forceinline__ void cp_wait0()  { asm volatile("cp.async.wait_group 0;\n"); }

// ---------------------------------------------------------------------------
// Convert inputs to fp16 once: x -> xt, weights -> g_wq/g_wp (same layout).
// ---------------------------------------------------------------------------
__global__ void cvt_inputs(const float* __restrict__ x,
                           const float* __restrict__ wq,
                           const float* __restrict__ wp,
                           __half* __restrict__ xt,
                           __half* __restrict__ wqt,
                           __half* __restrict__ wpt)
{
    const int stride = gridDim.x * blockDim.x;
    const int tid0 = blockIdx.x * blockDim.x + threadIdx.x;
    for (int i = tid0; i < 33554432 / 4; i += stride) {
        float4 v = ((const float4*)x)[i];
        __half2 h0 = __floats2half2_rn(v.x, v.y);
        __half2 h1 = __floats2half2_rn(v.z, v.w);
        ((__half2*)xt)[i * 2]     = h0;
        ((__half2*)xt)[i * 2 + 1] = h1;
    }
    for (int i = tid0; i < 196608 + 65536; i += stride) {
        if (i < 196608) wqt[i] = __float2half_rn(wq[i]);
        else            wpt[i - 196608] = __float2half_rn(wp[i - 196608]);
    }
}

// ---------------------------------------------------------------------------
// FP16 GEMM: C[M,N] = A[M,256] @ B[256,N] (+bias). fp32 accumulate.
// BM=BN=128, BK=32, 3-stage cp.async, 8 warps (2x4), warp tile 64x32.
// smem: stages 3 x (A 128x40h + B 32x136h) = 56832B; epilogue strip 73728B.
// half_out=1 -> emit fp16, else fp32 (+bias).
// ---------------------------------------------------------------------------
__global__ __launch_bounds__(256, 2) void gemm_h(
    const __half* __restrict__ A, const __half* __restrict__ B,
    const float* __restrict__ bias, void* Cout, int N, int half_out)
{
    extern __shared__ __half smh[];
    const int tid  = threadIdx.x;
    const int warp = tid >> 5;
    const int lane = tid & 31;
    const int wm = warp >> 2, wn = warp & 3;
    const int bn = blockIdx.x * 128;   // fast dim = cols -> A L2 reuse
    const int bm = blockIdx.y * 128;

    wmma::fragment<wmma::accumulator, 16, 16, 16, float> acc[4][2];
#pragma unroll
    for (int i = 0; i < 4; i++)
#pragma unroll
        for (int j = 0; j < 2; j++) wmma::fill_fragment(acc[i][j], 0.f);

    auto load_tile = [&](int s, int k0) {
        __half* As = smh + s * 9472;
        __half* Bs = As + 5120;
#pragma unroll
        for (int t = 0; t < 2; t++) {
            int idx = tid + t * 256;                 // 0..511
            int ar = idx >> 2, ac = (idx & 3) * 8;   // A: 128 x 32 halfs
            cp_async16(&As[ar * 40 + ac], A + (size_t)(bm + ar) * 256 + k0 + ac);
            int br = idx >> 4, bc = (idx & 15) * 8;  // B: 32 x 128 halfs
            cp_async16(&Bs[br * 136 + bc], B + (size_t)(k0 + br) * N + bn + bc);
        }
        cp_commit();
    };

    load_tile(0, 0);
    load_tile(1, 32);
    const int NK = 8;  // 256/32
    for (int kt = 0; kt < NK; kt++) {
        if (kt == NK - 1) cp_wait0(); else cp_wait1();
        __syncthreads();
        if (kt + 2 < NK) load_tile((kt + 2) % 3, (kt + 2) * 32);
        const __half* As = smh + (kt % 3) * 9472;
        const __half* Bs = As + 5120;
#pragma unroll
        for (int kk = 0; kk < 32; kk += 16) {
            wmma::fragment<wmma::matrix_a, 16, 16, 16, __half, wmma::row_major> af[4];
            wmma::fragment<wmma::matrix_b, 16, 16, 16, __half, wmma::row_major> bf[2];
#pragma unroll
            for (int i = 0; i < 4; i++)
                wmma::load_matrix_sync(af[i], &As[(wm * 64 + i * 16) * 40 + kk], 40);
#pragma unroll
            for (int j = 0; j < 2; j++)
                wmma::load_matrix_sync(bf[j], &Bs[kk * 136 + wn * 32 + j * 16], 136);
#pragma unroll
            for (int i = 0; i < 4; i++)
#pragma unroll
                for (int j = 0; j < 2; j++)
                    wmma::mma_sync(acc[i][j], af[i], bf[j], acc[i][j]);
        }
    }
    __syncthreads();

    // Epilogue: per-warp 64x36 fp32 strip, bulk coalesced writeout
    float* wb = (float*)smh + warp * 2304;
#pragma unroll
    for (int i = 0; i < 4; i++)
#pragma unroll
        for (int j = 0; j < 2; j++)
            wmma::store_matrix_sync(&wb[(i * 16) * 36 + j * 16], acc[i][j], 36,
                                    wmma::mem_row_major);
    __syncwarp();
#pragma unroll
    for (int it = 0; it < 16; it++) {
        int idx = lane + it * 32;      // 0..511
        int r = idx >> 3;
        int c = (idx & 7) * 4;
        float4 v = *(float4*)&wb[r * 36 + c];
        int grow = bm + wm * 64 + r;
        int gcol = bn + wn * 32 + c;
        if (bias) {
            v.x += bias[gcol + 0]; v.y += bias[gcol + 1];
            v.z += bias[gcol + 2]; v.w += bias[gcol + 3];
        }
        if (half_out) {
            __half* Ch = (__half*)Cout;
            __half2* d = (__half2*)&Ch[(size_t)grow * N + gcol];
            d[0] = __floats2half2_rn(v.x, v.y);
            d[1] = __floats2half2_rn(v.z, v.w);
        } else {
            float* Cf = (float*)Cout;
            *(float4*)&Cf[(size_t)grow * N + gcol] = v;
        }
    }
}

// ---------------------------------------------------------------------------
// FUSED attention (fp16 in, fp16 out, fp32 accum / softmax sums):
//   blocks [0, 8192) = grid (dilated) heads 4..7
//   blocks [8192, 12288) = local windows heads 0..3
// 256 thr. Grid smem 52480B, local 84480B -> dyn 84480B, 2 CTA/SM.
// ---------------------------------------------------------------------------
__global__ __launch_bounds__(256, 2) void attn_fused(
    const __half* __restrict__ qkv, __half* __restrict__ att)
{
    extern __shared__ __half smh[];
    const int tid = threadIdx.x;
    const int warp = tid >> 5;
    const float scale = 0.17677669529663687f;

    if (blockIdx.x < 8192) {
        // ================= GRID (dilated) attention =================
        __half* Q  = smh;                       // 64x40
        __half* Sh = smh + 12800;               // 64x72
        float*  Sf = (float*)(smh + 17408);     // 64x68
        float*  l  = (float*)(smh + 26112);     // 64

        const int bid = blockIdx.x;
        const int hq = bid & 15, cid = bid >> 4;
        const int b = cid >> 6, s1 = (cid >> 3) & 7, s2 = cid & 7;
        const int h = 4 + (hq >> 2), qt = hq & 3;
        const int wl = warp & 3;
        const int wc = warp >> 2;

        auto stage = [&](int ck) {
            __half* Kd = smh + 2560 + (ck & 1) * 2560;
            __half* Vd = smh + 7680 + (ck & 1) * 2560;
            int rk = tid >> 2, seg = (tid & 3) * 8;     // 64 rows x 4 chunks
            int kk = ck * 64 + rk;
            size_t ktok = ((size_t)(b * 128 + (kk >> 4) * 8 + s1)) * 128 + (kk & 15) * 8 + s2;
            const __half* base = qkv + ktok * 768 + h * 32 + seg;
            cp_async16(&Kd[rk * 40 + seg], base + 256);
            cp_async16(&Vd[rk * 40 + seg], base + 512);
            cp_commit();
        };

        {   // Stage Q
            int r = tid >> 2, seg = (tid & 3) * 8;
            int qq = qt * 64 + r;
            size_t token = ((size_t)(b * 128 + (qq >> 4) * 8 + s1)) * 128 + (qq & 15) * 8 + s2;
            cp_async16(&Q[r * 40 + seg], qkv + token * 768 + h * 32 + seg);
        }
        if (tid < 64) l[tid] = 0.f;
        stage(0);

        wmma::fragment<wmma::accumulator, 16, 16, 16, float> accO;
        wmma::fill_fragment(accO, 0.f);

        for (int ck = 0; ck < 4; ck++) {
            cp_wait0();
            __syncthreads();
            if (ck < 3) stage(ck + 1);

            const __half* K = smh + 2560 + (ck & 1) * 2560;
            const __half* V = smh + 7680 + (ck & 1) * 2560;

            {   // S = exp(scale * Q @ Kc^T) -> Sf (fp32): 2 col tiles per warp
                wmma::fragment<wmma::matrix_a, 16, 16, 16, __half, wmma::row_major> af[2];
#pragma unroll
                for (int ki = 0; ki < 2; ki++)
                    wmma::load_matrix_sync(af[ki], &Q[(wl * 16) * 40 + ki * 16], 40);
#pragma unroll
                for (int jj = 0; jj < 2; jj++) {
                    int j = wc * 2 + jj;
                    wmma::fragment<wmma::accumulator, 16, 16, 16, float> accS;
                    wmma::fill_fragment(accS, 0.f);
#pragma unroll
                    for (int ki = 0; ki < 2; ki++) {
                        wmma::fragment<wmma::matrix_b, 16, 16, 16, __half, wmma::col_major> bf;
                        wmma::load_matrix_sync(bf, &K[(j * 16) * 40 + ki * 16], 40);
                        wmma::mma_sync(accS, af[ki], bf, accS);
                    }
#pragma unroll
                    for (int e = 0; e < accS.num_elements; e++)
                        accS.x[e] = __expf(accS.x[e] * scale);
                    wmma::store_matrix_sync(&Sf[(wl * 16) * 68 + j * 16], accS, 68,
                                            wmma::mem_row_major);
                }
            }
            __syncthreads();

            {   // fused convert + row-sum: Sf -> Sh, l += rowsum. 4 thr/row.
                int row = tid >> 2, q4 = tid & 3;
                const float* Sp = Sf + row * 68 + q4 * 16;
                __half* Shp = Sh + row * 72 + q4 * 16;
                float sum = 0.f;
#pragma unroll
                for (int e = 0; e < 16; e++) {
                    float p = Sp[e];
                    sum += p;
                    Shp[e] = __float2half_rn(p);
                }
                sum += __shfl_xor_sync(0xffffffffu, sum, 1);
                sum += __shfl_xor_sync(0xffffffffu, sum, 2);
                if (q4 == 0) l[row] += sum;
            }
            __syncthreads();

            // O += P @ Vc (64x32, k=64): warp tile (wl, wc)
#pragma unroll
            for (int ks = 0; ks < 4; ks++) {
                int kk = ks * 16;
                wmma::fragment<wmma::matrix_a, 16, 16, 16, __half, wmma::row_major> af;
                wmma::fragment<wmma::matrix_b, 16, 16, 16, __half, wmma::row_major> bf;
                wmma::load_matrix_sync(af, &Sh[(wl * 16) * 72 + kk], 72);
                wmma::load_matrix_sync(bf, &V[kk * 40 + wc * 16], 40);
                wmma::mma_sync(accO, af, bf, accO);
            }
        }
        __syncthreads();

        wmma::store_matrix_sync(&Sf[(wl * 16) * 68 + wc * 16], accO, 68,
                                wmma::mem_row_major);
        __syncthreads();

#pragma unroll
        for (int i = 0; i < 2; i++) {
            int idx = tid + i * 256;       // 0..511 covering 64x32 in 4s
            int r = idx >> 3, c = (idx & 7) * 4;
            float inv = 1.f / l[r];
            int qq = qt * 64 + r;
            size_t token = ((size_t)(b * 128 + (qq >> 4) * 8 + s1)) * 128 + (qq & 15) * 8 + s2;
            __half2* d = (__half2*)&att[token * 256 + h * 32 + c];
            d[0] = __floats2half2_rn(Sf[r * 68 + c] * inv, Sf[r * 68 + c + 1] * inv);
            d[1] = __floats2half2_rn(Sf[r * 68 + c + 2] * inv, Sf[r * 68 + c + 3] * inv);
        }
    } else {
        // ================= LOCAL window attention =================
        const int lb = blockIdx.x - 8192;
        const int wid = lb >> 1, hp = lb & 1;
        const int b = wid >> 8, wy = (wid >> 4) & 15, wx = wid & 15;
        const int hh = warp >> 2, wl = warp & 3;

        // head strides (halfs): Q@0, K@2560, V@5120, Sh@7680, Sf@12288(f), l@20992(f)
#pragma unroll
        for (int i = 0; i < 2; i++) {
            int idx = tid + i * 256;            // 0..511
            int h2 = idx >> 8;
            int r  = (idx >> 2) & 63;
            int seg = (idx & 3) * 8;
            int hg = hp * 2 + h2;
            size_t token = ((size_t)(b * 128 + wy * 8 + (r >> 3))) * 128 + wx * 8 + (r & 7);
            const __half* base = qkv + token * 768 + hg * 32 + seg;
            __half* hb = smh + h2 * 21120;
            cp_async16(&hb[r * 40 + seg], base);                // Q
            cp_async16(&hb[2560 + r * 40 + seg], base + 256);   // K
            cp_async16(&hb[5120 + r * 40 + seg], base + 512);   // V
        }
        cp_commit();
        cp_wait0();
        __syncthreads();

        __half* Qh = smh + hh * 21120;
        __half* Kh = Qh + 2560;
        __half* Vh = Qh + 5120;
        __half* Shh = Qh + 7680;
        float*  Sf = (float*)(Qh + 12288);
        float*  lh = (float*)(Qh + 20992);

        {   // S = exp(scale * Q @ K^T) -> Sf: 4 col tiles per warp
            wmma::fragment<wmma::matrix_a, 16, 16, 16, __half, wmma::row_major> af[2];
#pragma unroll
            for (int ki = 0; ki < 2; ki++)
                wmma::load_matrix_sync(af[ki], &Qh[(wl * 16) * 40 + ki * 16], 40);
#pragma unroll
            for (int j = 0; j < 4; j++) {
                wmma::fragment<wmma::accumulator, 16, 16, 16, float> accS;
                wmma::fill_fragment(accS, 0.f);
#pragma unroll
                for (int ki = 0; ki < 2; ki++) {
                    wmma::fragment<wmma::matrix_b, 16, 16, 16, __half, wmma::col_major> bf;
                    wmma::load_matrix_sync(bf, &Kh[(j * 16) * 40 + ki * 16], 40);
                    wmma::mma_sync(accS, af[ki], bf, accS);
                }
#pragma unroll
                for (int e = 0; e < accS.num_elements; e++)
                    accS.x[e] = __expf(accS.x[e] * scale);
                wmma::store_matrix_sync(&Sf[(wl * 16) * 68 + j * 16], accS, 68,
                                        wmma::mem_row_major);
            }
        }
        __syncthreads();

        {   // fused convert + row-sum: 2 thr/row/head, 32 elems each
            int h2 = tid >> 7, local = tid & 127;
            int row = local >> 1, hf = local & 1;
            float* Sp = (float*)(smh + h2 * 21120 + 12288) + row * 68 + hf * 32;
            __half* Shp = smh + h2 * 21120 + 7680 + row * 72 + hf * 32;
            float sum = 0.f;
#pragma unroll
            for (int e = 0; e < 32; e++) {
                float p = Sp[e];
                sum += p;
                Shp[e] = __float2half_rn(p);
            }
            sum += __shfl_xor_sync(0xffffffffu, sum, 1);
            if (hf == 0) ((float*)(smh + h2 * 21120 + 20992))[row] = 1.f / sum;
        }
        __syncthreads();

        {   // O = P @ V (64x32, k=64) -> store into Sf
            wmma::fragment<wmma::accumulator, 16, 16, 16, float> accO[2];
#pragma unroll
            for (int j = 0; j < 2; j++) wmma::fill_fragment(accO[j], 0.f);
#pragma unroll
            for (int ks = 0; ks < 4; ks++) {
                int kk = ks * 16;
                wmma::fragment<wmma::matrix_a, 16, 16, 16, __half, wmma::row_major> af;
                wmma::load_matrix_sync(af, &Shh[(wl * 16) * 72 + kk], 72);
#pragma unroll
                for (int j = 0; j < 2; j++) {
                    wmma::fragment<wmma::matrix_b, 16, 16, 16, __half, wmma::row_major> bf;
                    wmma::load_matrix_sync(bf, &Vh[kk * 40 + j * 16], 40);
                    wmma::mma_sync(accO[j], af, bf, accO[j]);
                }
            }
#pragma unroll
            for (int j = 0; j < 2; j++)
                wmma::store_matrix_sync(&Sf[(wl * 16) * 68 + j * 16], accO[j], 68,
                                        wmma::mem_row_major);
        }
        __syncthreads();

#pragma unroll
        for (int i = 0; i < 4; i++) {
            int idx = tid + i * 256;        // 0..1023 covering 2 heads x 64x32 in 4s
            int h2 = idx >> 9;
            int r  = (idx >> 3) & 63;
            int c  = (idx & 7) * 4;
            int hg = hp * 2 + h2;
            float* Sp = (float*)(smh + h2 * 21120 + 12288);
            float inv = ((float*)(smh + h2 * 21120 + 20992))[r];
            size_t token = ((size_t)(b * 128 + wy * 8 + (r >> 3))) * 128 + wx * 8 + (r & 7);
            __half2* d = (__half2*)&att[token * 256 + hg * 32 + c];
            d[0] = __floats2half2_rn(Sp[r * 68 + c] * inv, Sp[r * 68 + c + 1] * inv);
            d[1] = __floats2half2_rn(Sp[r * 68 + c + 2] * inv, Sp[r * 68 + c + 3] * inv);
        }
    }
}

// ---------------------------------------------------------------------------
extern "C" void kernel_launch(void* const* d_in, const int* in_sizes, int n_in,
                              void* d_out, int out_size)
{
    (void)in_sizes; (void)n_in; (void)out_size;
    const float* x     = (const float*)d_in[0];
    const float* Wqkv  = (const float*)d_in[1];
    const float* Wproj = (const float*)d_in[2];
    const float* bproj = (const float*)d_in[3];
    float* out = (float*)d_out;

    __half *qkv = nullptr, *att = nullptr, *wq = nullptr, *wp = nullptr;
    cudaGetSymbolAddress((void**)&qkv, g_qkv);
    cudaGetSymbolAddress((void**)&att, g_att);
    cudaGetSymbolAddress((void**)&wq,  g_wq);
    cudaGetSymbolAddress((void**)&wp,  g_wp);

    cudaFuncSetAttribute(gemm_h, cudaFuncAttributeMaxDynamicSharedMemorySize, 73728);
    cudaFuncSetAttribute(attn_fused, cudaFuncAttributeMaxDynamicSharedMemorySize, 84480);

    // 0) convert x (into g_att, free until attention) and weights to fp16
    cvt_inputs<<<4096, 256>>>(x, Wqkv, Wproj, att, wq, wp);
    // 1) QKV = xt @ W_qkv  (fp16 out)
    gemm_h<<<dim3(6, 1024), 256, 73728>>>(att, wq, nullptr, qkv, 768, 1);
    // 2+3) fused local (heads 0..3) + grid (heads 4..7) attention (fp16 out)
    attn_fused<<<12288, 256, 84480>>>(qkv, att);
    // 4) out = att @ W_proj + b_proj (fp32 out)
    gemm_h<<<dim3(2, 1024), 256, 73728>>>(att, wp, bproj, out, 256, 0);
}

// round 13
// speedup vs baseline: 2.8648x; 1.0008x over previous
#include <cuda_runtime.h>
#include <cuda_fp16.h>
#include <mma.h>
#include <cstdint>
using namespace nvcuda;

// Problem constants: B=8, H=W=128, C=256, NUM_HEADS=8, HD=32, WINDOW=8
#define TOKENS 131072

// Scratch (allocation-free rule: device globals)
__device__ __half g_qkv[100663296u];  // [token][3][head][32] fp16
__device__ __half g_att[33554432u];   // xt (pre-GEMM1) then att [token][256] fp16
__device__ __half g_wq[196608];       // fp16 W_qkv [256,768] row-major
__device__ __half g_wp[65536];        // fp16 W_proj [256,256] row-major

__device__ __forceinline__ void cp_async16(void* smem, const void* gmem) {
    unsigned s = (unsigned)__cvta_generic_to_shared(smem);
    asm volatile("cp.async.cg.shared.global [%0], [%1], 16;\n" :: "r"(s), "l"(gmem));
}
__device__ __forceinline__ void cp_commit() { asm volatile("cp.async.commit_group;\n"); }
__device__ __forceinline__ void cp_wait1()  { asm volatile("cp.async.wait_group 1;\n"); }
__device__ __forceinline__ void cp_wait0()  { asm volatile("cp.async.wait_group 0;\n"); }

// ---------------------------------------------------------------------------
// Convert inputs to fp16 once: x -> xt, weights -> g_wq/g_wp (same layout).
// ---------------------------------------------------------------------------
__global__ void cvt_inputs(const float* __restrict__ x,
                           const float* __restrict__ wq,
                           const float* __restrict__ wp,
                           __half* __restrict__ xt,
                           __half* __restrict__ wqt,
                           __half* __restrict__ wpt)
{
    const int stride = gridDim.x * blockDim.x;
    const int tid0 = blockIdx.x * blockDim.x + threadIdx.x;
    for (int i = tid0; i < 33554432 / 4; i += stride) {
        float4 v = ((const float4*)x)[i];
        __half2 h0 = __floats2half2_rn(v.x, v.y);
        __half2 h1 = __floats2half2_rn(v.z, v.w);
        ((__half2*)xt)[i * 2]     = h0;
        ((__half2*)xt)[i * 2 + 1] = h1;
    }
    for (int i = tid0; i < 196608 + 65536; i += stride) {
        if (i < 196608) wqt[i] = __float2half_rn(wq[i]);
        else            wpt[i - 196608] = __float2half_rn(wp[i - 196608]);
    }
}

// ---------------------------------------------------------------------------
// FP16 GEMM: C[M,N] = A[M,256] @ B[256,N] (+bias). fp32 accumulate.
// BM=BN=128, BK=64, 2-stage cp.async, 8 warps (2x4), warp tile 64x32.
// 32 MMAs per barrier, 4 K-chunks total.
// smem: 2 stages x (A 128x72h + B 64x136h) = 71680B; epilogue 73728B.
// half_out=1 -> emit fp16, else fp32 (+bias).
// ---------------------------------------------------------------------------
__global__ __launch_bounds__(256, 2) void gemm_h(
    const __half* __restrict__ A, const __half* __restrict__ B,
    const float* __restrict__ bias, void* Cout, int N, int half_out)
{
    extern __shared__ __half smh[];
    const int tid  = threadIdx.x;
    const int warp = tid >> 5;
    const int lane = tid & 31;
    const int wm = warp >> 2, wn = warp & 3;
    const int bn = blockIdx.x * 128;   // fast dim = cols -> A L2 reuse
    const int bm = blockIdx.y * 128;

    wmma::fragment<wmma::accumulator, 16, 16, 16, float> acc[4][2];
#pragma unroll
    for (int i = 0; i < 4; i++)
#pragma unroll
        for (int j = 0; j < 2; j++) wmma::fill_fragment(acc[i][j], 0.f);

    auto load_tile = [&](int s, int k0) {
        __half* As = smh + s * 17920;
        __half* Bs = As + 9216;
#pragma unroll
        for (int t = 0; t < 4; t++) {
            int idx = tid + t * 256;                 // 0..1023
            int ar = idx >> 3, ac = (idx & 7) * 8;   // A: 128 x 64 halfs
            cp_async16(&As[ar * 72 + ac], A + (size_t)(bm + ar) * 256 + k0 + ac);
            int br = idx >> 4, bc = (idx & 15) * 8;  // B: 64 x 128 halfs
            cp_async16(&Bs[br * 136 + bc], B + (size_t)(k0 + br) * N + bn + bc);
        }
        cp_commit();
    };

    load_tile(0, 0);
    const int NK = 4;  // 256/64
    for (int kt = 0; kt < NK; kt++) {
        if (kt + 1 < NK) { load_tile((kt + 1) & 1, (kt + 1) * 64); cp_wait1(); }
        else             { cp_wait0(); }
        __syncthreads();
        const __half* As = smh + (kt & 1) * 17920;
        const __half* Bs = As + 9216;
#pragma unroll
        for (int kk = 0; kk < 64; kk += 16) {
            wmma::fragment<wmma::matrix_a, 16, 16, 16, __half, wmma::row_major> af[4];
            wmma::fragment<wmma::matrix_b, 16, 16, 16, __half, wmma::row_major> bf[2];
#pragma unroll
            for (int i = 0; i < 4; i++)
                wmma::load_matrix_sync(af[i], &As[(wm * 64 + i * 16) * 72 + kk], 72);
#pragma unroll
            for (int j = 0; j < 2; j++)
                wmma::load_matrix_sync(bf[j], &Bs[kk * 136 + wn * 32 + j * 16], 136);
#pragma unroll
            for (int i = 0; i < 4; i++)
#pragma unroll
                for (int j = 0; j < 2; j++)
                    wmma::mma_sync(acc[i][j], af[i], bf[j], acc[i][j]);
        }
        __syncthreads();
    }

    // Epilogue: per-warp 64x36 fp32 strip, bulk coalesced writeout
    float* wb = (float*)smh + warp * 2304;
#pragma unroll
    for (int i = 0; i < 4; i++)
#pragma unroll
        for (int j = 0; j < 2; j++)
            wmma::store_matrix_sync(&wb[(i * 16) * 36 + j * 16], acc[i][j], 36,
                                    wmma::mem_row_major);
    __syncwarp();
#pragma unroll
    for (int it = 0; it < 16; it++) {
        int idx = lane + it * 32;      // 0..511
        int r = idx >> 3;
        int c = (idx & 7) * 4;
        float4 v = *(float4*)&wb[r * 36 + c];
        int grow = bm + wm * 64 + r;
        int gcol = bn + wn * 32 + c;
        if (bias) {
            v.x += bias[gcol + 0]; v.y += bias[gcol + 1];
            v.z += bias[gcol + 2]; v.w += bias[gcol + 3];
        }
        if (half_out) {
            __half* Ch = (__half*)Cout;
            __half2* d = (__half2*)&Ch[(size_t)grow * N + gcol];
            d[0] = __floats2half2_rn(v.x, v.y);
            d[1] = __floats2half2_rn(v.z, v.w);
        } else {
            float* Cf = (float*)Cout;
            *(float4*)&Cf[(size_t)grow * N + gcol] = v;
        }
    }
}

// ---------------------------------------------------------------------------
// FUSED attention (fp16 in, fp16 out, fp32 accum / softmax sums):
//   blocks [0, 8192) = grid (dilated) heads 4..7
//   blocks [8192, 12288) = local windows heads 0..3
// 256 thr. Grid smem 52480B, local 84480B -> dyn 84480B, 2 CTA/SM.
// ---------------------------------------------------------------------------
__global__ __launch_bounds__(256, 2) void attn_fused(
    const __half* __restrict__ qkv, __half* __restrict__ att)
{
    extern __shared__ __half smh[];
    const int tid = threadIdx.x;
    const int warp = tid >> 5;
    const float scale = 0.17677669529663687f;

    if (blockIdx.x < 8192) {
        // ================= GRID (dilated) attention =================
        __half* Q  = smh;                       // 64x40
        __half* Sh = smh + 12800;               // 64x72
        float*  Sf = (float*)(smh + 17408);     // 64x68
        float*  l  = (float*)(smh + 26112);     // 64

        const int bid = blockIdx.x;
        const int hq = bid & 15, cid = bid >> 4;
        const int b = cid >> 6, s1 = (cid >> 3) & 7, s2 = cid & 7;
        const int h = 4 + (hq >> 2), qt = hq & 3;
        const int wl = warp & 3;
        const int wc = warp >> 2;

        auto stage = [&](int ck) {
            __half* Kd = smh + 2560 + (ck & 1) * 2560;
            __half* Vd = smh + 7680 + (ck & 1) * 2560;
            int rk = tid >> 2, seg = (tid & 3) * 8;     // 64 rows x 4 chunks
            int kk = ck * 64 + rk;
            size_t ktok = ((size_t)(b * 128 + (kk >> 4) * 8 + s1)) * 128 + (kk & 15) * 8 + s2;
            const __half* base = qkv + ktok * 768 + h * 32 + seg;
            cp_async16(&Kd[rk * 40 + seg], base + 256);
            cp_async16(&Vd[rk * 40 + seg], base + 512);
            cp_commit();
        };

        {   // Stage Q
            int r = tid >> 2, seg = (tid & 3) * 8;
            int qq = qt * 64 + r;
            size_t token = ((size_t)(b * 128 + (qq >> 4) * 8 + s1)) * 128 + (qq & 15) * 8 + s2;
            cp_async16(&Q[r * 40 + seg], qkv + token * 768 + h * 32 + seg);
        }
        if (tid < 64) l[tid] = 0.f;
        stage(0);

        wmma::fragment<wmma::accumulator, 16, 16, 16, float> accO;
        wmma::fill_fragment(accO, 0.f);

        for (int ck = 0; ck < 4; ck++) {
            cp_wait0();
            __syncthreads();
            if (ck < 3) stage(ck + 1);

            const __half* K = smh + 2560 + (ck & 1) * 2560;
            const __half* V = smh + 7680 + (ck & 1) * 2560;

            {   // S = exp(scale * Q @ Kc^T) -> Sf (fp32): 2 col tiles per warp
                wmma::fragment<wmma::matrix_a, 16, 16, 16, __half, wmma::row_major> af[2];
#pragma unroll
                for (int ki = 0; ki < 2; ki++)
                    wmma::load_matrix_sync(af[ki], &Q[(wl * 16) * 40 + ki * 16], 40);
#pragma unroll
                for (int jj = 0; jj < 2; jj++) {
                    int j = wc * 2 + jj;
                    wmma::fragment<wmma::accumulator, 16, 16, 16, float> accS;
                    wmma::fill_fragment(accS, 0.f);
#pragma unroll
                    for (int ki = 0; ki < 2; ki++) {
                        wmma::fragment<wmma::matrix_b, 16, 16, 16, __half, wmma::col_major> bf;
                        wmma::load_matrix_sync(bf, &K[(j * 16) * 40 + ki * 16], 40);
                        wmma::mma_sync(accS, af[ki], bf, accS);
                    }
#pragma unroll
                    for (int e = 0; e < accS.num_elements; e++)
                        accS.x[e] = __expf(accS.x[e] * scale);
                    wmma::store_matrix_sync(&Sf[(wl * 16) * 68 + j * 16], accS, 68,
                                            wmma::mem_row_major);
                }
            }
            __syncthreads();

            {   // fused convert + row-sum: Sf -> Sh, l += rowsum. 4 thr/row.
                int row = tid >> 2, q4 = tid & 3;
                const float* Sp = Sf + row * 68 + q4 * 16;
                __half* Shp = Sh + row * 72 + q4 * 16;
                float sum = 0.f;
#pragma unroll
                for (int e = 0; e < 16; e++) {
                    float p = Sp[e];
                    sum += p;
                    Shp[e] = __float2half_rn(p);
                }
                sum += __shfl_xor_sync(0xffffffffu, sum, 1);
                sum += __shfl_xor_sync(0xffffffffu, sum, 2);
                if (q4 == 0) l[row] += sum;
            }
            __syncthreads();

            // O += P @ Vc (64x32, k=64): warp tile (wl, wc)
#pragma unroll
            for (int ks = 0; ks < 4; ks++) {
                int kk = ks * 16;
                wmma::fragment<wmma::matrix_a, 16, 16, 16, __half, wmma::row_major> af;
                wmma::fragment<wmma::matrix_b, 16, 16, 16, __half, wmma::row_major> bf;
                wmma::load_matrix_sync(af, &Sh[(wl * 16) * 72 + kk], 72);
                wmma::load_matrix_sync(bf, &V[kk * 40 + wc * 16], 40);
                wmma::mma_sync(accO, af, bf, accO);
            }
        }
        __syncthreads();

        wmma::store_matrix_sync(&Sf[(wl * 16) * 68 + wc * 16], accO, 68,
                                wmma::mem_row_major);
        __syncthreads();

#pragma unroll
        for (int i = 0; i < 2; i++) {
            int idx = tid + i * 256;       // 0..511 covering 64x32 in 4s
            int r = idx >> 3, c = (idx & 7) * 4;
            float inv = 1.f / l[r];
            int qq = qt * 64 + r;
            size_t token = ((size_t)(b * 128 + (qq >> 4) * 8 + s1)) * 128 + (qq & 15) * 8 + s2;
            __half2* d = (__half2*)&att[token * 256 + h * 32 + c];
            d[0] = __floats2half2_rn(Sf[r * 68 + c] * inv, Sf[r * 68 + c + 1] * inv);
            d[1] = __floats2half2_rn(Sf[r * 68 + c + 2] * inv, Sf[r * 68 + c + 3] * inv);
        }
    } else {
        // ================= LOCAL window attention =================
        const int lb = blockIdx.x - 8192;
        const int wid = lb >> 1, hp = lb & 1;
        const int b = wid >> 8, wy = (wid >> 4) & 15, wx = wid & 15;
        const int hh = warp >> 2, wl = warp & 3;

        // head strides (halfs): Q@0, K@2560, V@5120, Sh@7680, Sf@12288(f), l@20992(f)
#pragma unroll
        for (int i = 0; i < 2; i++) {
            int idx = tid + i * 256;            // 0..511
            int h2 = idx >> 8;
            int r  = (idx >> 2) & 63;
            int seg = (idx & 3) * 8;
            int hg = hp * 2 + h2;
            size_t token = ((size_t)(b * 128 + wy * 8 + (r >> 3))) * 128 + wx * 8 + (r & 7);
            const __half* base = qkv + token * 768 + hg * 32 + seg;
            __half* hb = smh + h2 * 21120;
            cp_async16(&hb[r * 40 + seg], base);                // Q
            cp_async16(&hb[2560 + r * 40 + seg], base + 256);   // K
            cp_async16(&hb[5120 + r * 40 + seg], base + 512);   // V
        }
        cp_commit();
        cp_wait0();
        __syncthreads();

        __half* Qh = smh + hh * 21120;
        __half* Kh = Qh + 2560;
        __half* Vh = Qh + 5120;
        __half* Shh = Qh + 7680;
        float*  Sf = (float*)(Qh + 12288);

        {   // S = exp(scale * Q @ K^T) -> Sf: 4 col tiles per warp
            wmma::fragment<wmma::matrix_a, 16, 16, 16, __half, wmma::row_major> af[2];
#pragma unroll
            for (int ki = 0; ki < 2; ki++)
                wmma::load_matrix_sync(af[ki], &Qh[(wl * 16) * 40 + ki * 16], 40);
#pragma unroll
            for (int j = 0; j < 4; j++) {
                wmma::fragment<wmma::accumulator, 16, 16, 16, float> accS;
                wmma::fill_fragment(accS, 0.f);
#pragma unroll
                for (int ki = 0; ki < 2; ki++) {
                    wmma::fragment<wmma::matrix_b, 16, 16, 16, __half, wmma::col_major> bf;
                    wmma::load_matrix_sync(bf, &Kh[(j * 16) * 40 + ki * 16], 40);
                    wmma::mma_sync(accS, af[ki], bf, accS);
                }
#pragma unroll
                for (int e = 0; e < accS.num_elements; e++)
                    accS.x[e] = __expf(accS.x[e] * scale);
                wmma::store_matrix_sync(&Sf[(wl * 16) * 68 + j * 16], accS, 68,
                                        wmma::mem_row_major);
            }
        }
        __syncthreads();

        {   // fused convert + row-sum: 2 thr/row/head, 32 elems each
            int h2 = tid >> 7, local = tid & 127;
            int row = local >> 1, hf = local & 1;
            float* Sp = (float*)(smh + h2 * 21120 + 12288) + row * 68 + hf * 32;
            __half* Shp = smh + h2 * 21120 + 7680 + row * 72 + hf * 32;
            float sum = 0.f;
#pragma unroll
            for (int e = 0; e < 32; e++) {
                float p = Sp[e];
                sum += p;
                Shp[e] = __float2half_rn(p);
            }
            sum += __shfl_xor_sync(0xffffffffu, sum, 1);
            if (hf == 0) ((float*)(smh + h2 * 21120 + 20992))[row] = 1.f / sum;
        }
        __syncthreads();

        {   // O = P @ V (64x32, k=64) -> store into Sf
            wmma::fragment<wmma::accumulator, 16, 16, 16, float> accO[2];
#pragma unroll
            for (int j = 0; j < 2; j++) wmma::fill_fragment(accO[j], 0.f);
#pragma unroll
            for (int ks = 0; ks < 4; ks++) {
                int kk = ks * 16;
                wmma::fragment<wmma::matrix_a, 16, 16, 16, __half, wmma::row_major> af;
                wmma::load_matrix_sync(af, &Shh[(wl * 16) * 72 + kk], 72);
#pragma unroll
                for (int j = 0; j < 2; j++) {
                    wmma::fragment<wmma::matrix_b, 16, 16, 16, __half, wmma::row_major> bf;
                    wmma::load_matrix_sync(bf, &Vh[kk * 40 + j * 16], 40);
                    wmma::mma_sync(accO[j], af, bf, accO[j]);
                }
            }
#pragma unroll
            for (int j = 0; j < 2; j++)
                wmma::store_matrix_sync(&Sf[(wl * 16) * 68 + j * 16], accO[j], 68,
                                        wmma::mem_row_major);
        }
        __syncthreads();

#pragma unroll
        for (int i = 0; i < 4; i++) {
            int idx = tid + i * 256;        // 0..1023 covering 2 heads x 64x32 in 4s
            int h2 = idx >> 9;
            int r  = (idx >> 3) & 63;
            int c  = (idx & 7) * 4;
            int hg = hp * 2 + h2;
            float* Sp = (float*)(smh + h2 * 21120 + 12288);
            float inv = ((float*)(smh + h2 * 21120 + 20992))[r];
            size_t token = ((size_t)(b * 128 + wy * 8 + (r >> 3))) * 128 + wx * 8 + (r & 7);
            __half2* d = (__half2*)&att[token * 256 + hg * 32 + c];
            d[0] = __floats2half2_rn(Sp[r * 68 + c] * inv, Sp[r * 68 + c + 1] * inv);
            d[1] = __floats2half2_rn(Sp[r * 68 + c + 2] * inv, Sp[r * 68 + c + 3] * inv);
        }
    }
}

// ---------------------------------------------------------------------------
extern "C" void kernel_launch(void* const* d_in, const int* in_sizes, int n_in,
                              void* d_out, int out_size)
{
    (void)in_sizes; (void)n_in; (void)out_size;
    const float* x     = (const float*)d_in[0];
    const float* Wqkv  = (const float*)d_in[1];
    const float* Wproj = (const float*)d_in[2];
    const float* bproj = (const float*)d_in[3];
    float* out = (float*)d_out;

    __half *qkv = nullptr, *att = nullptr, *wq = nullptr, *wp = nullptr;
    cudaGetSymbolAddress((void**)&qkv, g_qkv);
    cudaGetSymbolAddress((void**)&att, g_att);
    cudaGetSymbolAddress((void**)&wq,  g_wq);
    cudaGetSymbolAddress((void**)&wp,  g_wp);

    cudaFuncSetAttribute(gemm_h, cudaFuncAttributeMaxDynamicSharedMemorySize, 73728);
    cudaFuncSetAttribute(attn_fused, cudaFuncAttributeMaxDynamicSharedMemorySize, 84480);

    // 0) convert x (into g_att, free until attention) and weights to fp16
    cvt_inputs<<<4096, 256>>>(x, Wqkv, Wproj, att, wq, wp);
    // 1) QKV = xt @ W_qkv  (fp16 out)
    gemm_h<<<dim3(6, 1024), 256, 73728>>>(att, wq, nullptr, qkv, 768, 1);
    // 2+3) fused local (heads 0..3) + grid (heads 4..7) attention (fp16 out)
    attn_fused<<<12288, 256, 84480>>>(qkv, att);
    // 4) out = att @ W_proj + b_proj (fp32 out)
    gemm_h<<<dim3(2, 1024), 256, 73728>>>(att, wp, bproj, out, 256, 0);
}

// round 14
// speedup vs baseline: 3.5044x; 1.2233x over previous
#include <cuda_runtime.h>
#include <cuda_fp16.h>
#include <mma.h>
#include <cstdint>
using namespace nvcuda;

// Problem constants: B=8, H=W=128, C=256, NUM_HEADS=8, HD=32, WINDOW=8
#define TOKENS 131072

// Scratch (allocation-free rule: device globals)
__device__ __half g_qkv[100663296u];  // [token][3][head][32] fp16
__device__ __half g_att[33554432u];   // xt (pre-GEMM1) then att [token][256] fp16
__device__ __half g_wq[196608];       // fp16 W_qkv [256,768] row-major
__device__ __half g_wp[65536];        // fp16 W_proj [256,256] row-major

__device__ __forceinline__ void cp_async16(void* smem, const void* gmem) {
    unsigned s = (unsigned)__cvta_generic_to_shared(smem);
    asm volatile("cp.async.cg.shared.global [%0], [%1], 16;\n" :: "r"(s), "l"(gmem));
}
__device__ __forceinline__ void cp_commit() { asm volatile("cp.async.commit_group;\n"); }
__device__ __forceinline__ void cp_wait1()  { asm volatile("cp.async.wait_group 1;\n"); }
__device__ __forceinline__ void cp_wait0()  { asm volatile("cp.async.wait_group 0;\n"); }

// ---------------------------------------------------------------------------
// Convert inputs to fp16 once: x -> xt, weights -> g_wq/g_wp (same layout).
// ---------------------------------------------------------------------------
__global__ void cvt_inputs(const float* __restrict__ x,
                           const float* __restrict__ wq,
                           const float* __restrict__ wp,
                           __half* __restrict__ xt,
                           __half* __restrict__ wqt,
                           __half* __restrict__ wpt)
{
    const int stride = gridDim.x * blockDim.x;
    const int tid0 = blockIdx.x * blockDim.x + threadIdx.x;
    for (int i = tid0; i < 33554432 / 4; i += stride) {
        float4 v = ((const float4*)x)[i];
        __half2 h0 = __floats2half2_rn(v.x, v.y);
        __half2 h1 = __floats2half2_rn(v.z, v.w);
        ((__half2*)xt)[i * 2]     = h0;
        ((__half2*)xt)[i * 2 + 1] = h1;
    }
    for (int i = tid0; i < 196608 + 65536; i += stride) {
        if (i < 196608) wqt[i] = __float2half_rn(wq[i]);
        else            wpt[i - 196608] = __float2half_rn(wp[i - 196608]);
    }
}

// ---------------------------------------------------------------------------
// FP16 GEMM: C[M,N] = A[M,256] @ B[256,N] (+bias). fp32 accumulate.
// BM=BN=128, BK=64, 2-stage cp.async, 8 warps (2x4), warp tile 64x32.
// ---------------------------------------------------------------------------
__global__ __launch_bounds__(256, 2) void gemm_h(
    const __half* __restrict__ A, const __half* __restrict__ B,
    const float* __restrict__ bias, void* Cout, int N, int half_out)
{
    extern __shared__ __half smh[];
    const int tid  = threadIdx.x;
    const int warp = tid >> 5;
    const int lane = tid & 31;
    const int wm = warp >> 2, wn = warp & 3;
    const int bn = blockIdx.x * 128;   // fast dim = cols -> A L2 reuse
    const int bm = blockIdx.y * 128;

    wmma::fragment<wmma::accumulator, 16, 16, 16, float> acc[4][2];
#pragma unroll
    for (int i = 0; i < 4; i++)
#pragma unroll
        for (int j = 0; j < 2; j++) wmma::fill_fragment(acc[i][j], 0.f);

    auto load_tile = [&](int s, int k0) {
        __half* As = smh + s * 17920;
        __half* Bs = As + 9216;
#pragma unroll
        for (int t = 0; t < 4; t++) {
            int idx = tid + t * 256;                 // 0..1023
            int ar = idx >> 3, ac = (idx & 7) * 8;   // A: 128 x 64 halfs
            cp_async16(&As[ar * 72 + ac], A + (size_t)(bm + ar) * 256 + k0 + ac);
            int br = idx >> 4, bc = (idx & 15) * 8;  // B: 64 x 128 halfs
            cp_async16(&Bs[br * 136 + bc], B + (size_t)(k0 + br) * N + bn + bc);
        }
        cp_commit();
    };

    load_tile(0, 0);
    const int NK = 4;  // 256/64
    for (int kt = 0; kt < NK; kt++) {
        if (kt + 1 < NK) { load_tile((kt + 1) & 1, (kt + 1) * 64); cp_wait1(); }
        else             { cp_wait0(); }
        __syncthreads();
        const __half* As = smh + (kt & 1) * 17920;
        const __half* Bs = As + 9216;
#pragma unroll
        for (int kk = 0; kk < 64; kk += 16) {
            wmma::fragment<wmma::matrix_a, 16, 16, 16, __half, wmma::row_major> af[4];
            wmma::fragment<wmma::matrix_b, 16, 16, 16, __half, wmma::row_major> bf[2];
#pragma unroll
            for (int i = 0; i < 4; i++)
                wmma::load_matrix_sync(af[i], &As[(wm * 64 + i * 16) * 72 + kk], 72);
#pragma unroll
            for (int j = 0; j < 2; j++)
                wmma::load_matrix_sync(bf[j], &Bs[kk * 136 + wn * 32 + j * 16], 136);
#pragma unroll
            for (int i = 0; i < 4; i++)
#pragma unroll
                for (int j = 0; j < 2; j++)
                    wmma::mma_sync(acc[i][j], af[i], bf[j], acc[i][j]);
        }
        __syncthreads();
    }

    // Epilogue: per-warp 64x36 fp32 strip, bulk coalesced writeout
    float* wb = (float*)smh + warp * 2304;
#pragma unroll
    for (int i = 0; i < 4; i++)
#pragma unroll
        for (int j = 0; j < 2; j++)
            wmma::store_matrix_sync(&wb[(i * 16) * 36 + j * 16], acc[i][j], 36,
                                    wmma::mem_row_major);
    __syncwarp();
#pragma unroll
    for (int it = 0; it < 16; it++) {
        int idx = lane + it * 32;      // 0..511
        int r = idx >> 3;
        int c = (idx & 7) * 4;
        float4 v = *(float4*)&wb[r * 36 + c];
        int grow = bm + wm * 64 + r;
        int gcol = bn + wn * 32 + c;
        if (bias) {
            v.x += bias[gcol + 0]; v.y += bias[gcol + 1];
            v.z += bias[gcol + 2]; v.w += bias[gcol + 3];
        }
        if (half_out) {
            __half* Ch = (__half*)Cout;
            __half2* d = (__half2*)&Ch[(size_t)grow * N + gcol];
            d[0] = __floats2half2_rn(v.x, v.y);
            d[1] = __floats2half2_rn(v.z, v.w);
        } else {
            float* Cf = (float*)Cout;
            *(float4*)&Cf[(size_t)grow * N + gcol] = v;
        }
    }
}

// ---------------------------------------------------------------------------
// FUSED attention v2 (fp16): blocks [0,4096) = grid heads 4..7 (2 qtiles/CTA),
//                            blocks [4096,8192) = local windows heads 0..3.
// Shared smem layout (halfs), total 42240 h = 84480 B, 2 CTA/SM:
//   grid : Q[128][40]@0, K2[2][64][40]@5120, V2[2][64][40]@10240,
//          Sh[2][64][72]@15360, strips 8x[16][68]f @24576, l[128]f @41984
//   local: per-head {Q,K,V}[64][40]@h2*7680, Sh[2][64][72]@15360,
//          strips @24576, l[128]f @41984
// ---------------------------------------------------------------------------
__global__ __launch_bounds__(256, 2) void attn_fused(
    const __half* __restrict__ qkv, __half* __restrict__ att)
{
    extern __shared__ __half smh[];
    const int tid = threadIdx.x;
    const int warp = tid >> 5;
    const int lane = tid & 31;
    const float scale = 0.17677669529663687f;
    float* strip = (float*)(smh + 24576) + warp * 1088;   // 16x68 fp32
    float* l = (float*)(smh + 41984);                     // 128 fp32

    if (blockIdx.x < 4096) {
        // ================= GRID (dilated), 2 query tiles per CTA ============
        const int bid = blockIdx.x;
        const int low = bid & 7, cid = bid >> 3;
        const int b = cid >> 6, s1 = (cid >> 3) & 7, s2 = cid & 7;
        const int h = 4 + (low >> 1), qtp = low & 1;   // query rows qtp*128..+127
        const int qh = warp >> 2;      // 0..1 : query tile within pair
        const int wl = warp & 3;       // row tile

        auto stage = [&](int ck) {
            __half* Kd = smh + 5120  + (ck & 1) * 2560;
            __half* Vd = smh + 10240 + (ck & 1) * 2560;
            int rk = tid >> 2, seg = (tid & 3) * 8;     // 64 rows x 4 chunks
            int kk = ck * 64 + rk;
            size_t ktok = ((size_t)(b * 128 + (kk >> 4) * 8 + s1)) * 128 + (kk & 15) * 8 + s2;
            const __half* base = qkv + ktok * 768 + h * 32 + seg;
            cp_async16(&Kd[rk * 40 + seg], base + 256);
            cp_async16(&Vd[rk * 40 + seg], base + 512);
            cp_commit();
        };

        // Stage both Q tiles (128 rows) + first K/V chunk
#pragma unroll
        for (int i = 0; i < 2; i++) {
            int idx = tid + i * 256;           // 0..511
            int qrow = idx >> 2, seg = (idx & 3) * 8;
            int qq = qtp * 128 + qrow;
            size_t token = ((size_t)(b * 128 + (qq >> 4) * 8 + s1)) * 128 + (qq & 15) * 8 + s2;
            cp_async16(&smh[qrow * 40 + seg], qkv + token * 768 + h * 32 + seg);
        }
        if (tid < 128) l[tid] = 0.f;
        stage(0);

        wmma::fragment<wmma::accumulator, 16, 16, 16, float> accO[2];
#pragma unroll
        for (int j = 0; j < 2; j++) wmma::fill_fragment(accO[j], 0.f);

        for (int ck = 0; ck < 4; ck++) {
            cp_wait0();
            __syncthreads();
            if (ck < 3) stage(ck + 1);

            const __half* K = smh + 5120  + (ck & 1) * 2560;
            const __half* V = smh + 10240 + (ck & 1) * 2560;

            {   // S = exp(scale*Q@K^T) for this warp's 16 rows x 64 chunk cols
                wmma::fragment<wmma::matrix_a, 16, 16, 16, __half, wmma::row_major> af[2];
#pragma unroll
                for (int ki = 0; ki < 2; ki++)
                    wmma::load_matrix_sync(af[ki],
                        &smh[qh * 2560 + (wl * 16) * 40 + ki * 16], 40);
#pragma unroll
                for (int j = 0; j < 4; j++) {
                    wmma::fragment<wmma::accumulator, 16, 16, 16, float> accS;
                    wmma::fill_fragment(accS, 0.f);
#pragma unroll
                    for (int ki = 0; ki < 2; ki++) {
                        wmma::fragment<wmma::matrix_b, 16, 16, 16, __half, wmma::col_major> bf;
                        wmma::load_matrix_sync(bf, &K[(j * 16) * 40 + ki * 16], 40);
                        wmma::mma_sync(accS, af[ki], bf, accS);
                    }
#pragma unroll
                    for (int e = 0; e < accS.num_elements; e++)
                        accS.x[e] = __expf(accS.x[e] * scale);
                    wmma::store_matrix_sync(&strip[j * 16], accS, 68, wmma::mem_row_major);
                }
                __syncwarp();
                // convert own strip (16x64 fp32) -> Sh fp16
                int r = lane >> 1, cs = (lane & 1) * 32;
                const float* sp = strip + r * 68 + cs;
                __half2 hv[16];
#pragma unroll
                for (int e = 0; e < 16; e++)
                    hv[e] = __floats2half2_rn(sp[2 * e], sp[2 * e + 1]);
                uint4* dst = (uint4*)&smh[15360 + qh * 4608 + (wl * 16 + r) * 72 + cs];
#pragma unroll
                for (int u = 0; u < 4; u++) dst[u] = ((uint4*)hv)[u];
            }
            __syncthreads();

            {   // row-sum from Sh (does NOT gate PV): 2 thr/row over 128 rows
                int row = tid >> 1, hf = tid & 1;
                const __half2* sp = (const __half2*)
                    &smh[15360 + (row >> 6) * 4608 + (row & 63) * 72 + hf * 32];
                float s = 0.f;
#pragma unroll
                for (int e = 0; e < 16; e++) {
                    float2 f = __half22float2(sp[e]);
                    s += f.x + f.y;
                }
                s += __shfl_xor_sync(0xffffffffu, s, 1);
                if (hf == 0) l[row] += s;
            }

            // O += P @ V (both 16-col tiles per warp)
#pragma unroll
            for (int ks = 0; ks < 4; ks++) {
                int kk = ks * 16;
                wmma::fragment<wmma::matrix_a, 16, 16, 16, __half, wmma::row_major> af;
                wmma::load_matrix_sync(af,
                    &smh[15360 + qh * 4608 + (wl * 16) * 72 + kk], 72);
#pragma unroll
                for (int j = 0; j < 2; j++) {
                    wmma::fragment<wmma::matrix_b, 16, 16, 16, __half, wmma::row_major> bf;
                    wmma::load_matrix_sync(bf, &V[kk * 40 + j * 16], 40);
                    wmma::mma_sync(accO[j], af, bf, accO[j]);
                }
            }
        }

        // Store O to own strip; final sync for l; per-warp writeout
#pragma unroll
        for (int j = 0; j < 2; j++)
            wmma::store_matrix_sync(&strip[j * 16], accO[j], 68, wmma::mem_row_major);
        __syncthreads();
        {
            int r = lane >> 1, c0 = (lane & 1) * 16;
            float inv = 1.f / l[qh * 64 + wl * 16 + r];
            const float* sp = strip + r * 68 + c0;
            int qq = qtp * 128 + qh * 64 + wl * 16 + r;
            size_t token = ((size_t)(b * 128 + (qq >> 4) * 8 + s1)) * 128 + (qq & 15) * 8 + s2;
            __half2 o[8];
#pragma unroll
            for (int e = 0; e < 8; e++)
                o[e] = __floats2half2_rn(sp[2 * e] * inv, sp[2 * e + 1] * inv);
            uint4* d = (uint4*)&att[token * 256 + h * 32 + c0];
            d[0] = ((uint4*)o)[0];
            d[1] = ((uint4*)o)[1];
        }
    } else {
        // ================= LOCAL window attention (2 heads per CTA) =========
        const int lb = blockIdx.x - 4096;
        const int wid = lb >> 1, hp = lb & 1;
        const int b = wid >> 8, wy = (wid >> 4) & 15, wx = wid & 15;
        const int hh = warp >> 2, wl = warp & 3;

#pragma unroll
        for (int i = 0; i < 2; i++) {
            int idx = tid + i * 256;            // 0..511
            int h2 = idx >> 8;
            int r  = (idx >> 2) & 63;
            int seg = (idx & 3) * 8;
            int hg = hp * 2 + h2;
            size_t token = ((size_t)(b * 128 + wy * 8 + (r >> 3))) * 128 + wx * 8 + (r & 7);
            const __half* base = qkv + token * 768 + hg * 32 + seg;
            __half* hb = smh + h2 * 7680;
            cp_async16(&hb[r * 40 + seg], base);                // Q
            cp_async16(&hb[2560 + r * 40 + seg], base + 256);   // K
            cp_async16(&hb[5120 + r * 40 + seg], base + 512);   // V
        }
        cp_commit();
        cp_wait0();
        __syncthreads();

        const __half* Qh = smh + hh * 7680;
        const __half* Kh = Qh + 2560;
        const __half* Vh = Qh + 5120;

        {   // S = exp(scale*Q@K^T): 16 rows x 64 cols per warp -> Sh
            wmma::fragment<wmma::matrix_a, 16, 16, 16, __half, wmma::row_major> af[2];
#pragma unroll
            for (int ki = 0; ki < 2; ki++)
                wmma::load_matrix_sync(af[ki], &Qh[(wl * 16) * 40 + ki * 16], 40);
#pragma unroll
            for (int j = 0; j < 4; j++) {
                wmma::fragment<wmma::accumulator, 16, 16, 16, float> accS;
                wmma::fill_fragment(accS, 0.f);
#pragma unroll
                for (int ki = 0; ki < 2; ki++) {
                    wmma::fragment<wmma::matrix_b, 16, 16, 16, __half, wmma::col_major> bf;
                    wmma::load_matrix_sync(bf, &Kh[(j * 16) * 40 + ki * 16], 40);
                    wmma::mma_sync(accS, af[ki], bf, accS);
                }
#pragma unroll
                for (int e = 0; e < accS.num_elements; e++)
                    accS.x[e] = __expf(accS.x[e] * scale);
                wmma::store_matrix_sync(&strip[j * 16], accS, 68, wmma::mem_row_major);
            }
            __syncwarp();
            int r = lane >> 1, cs = (lane & 1) * 32;
            const float* sp = strip + r * 68 + cs;
            __half2 hv[16];
#pragma unroll
            for (int e = 0; e < 16; e++)
                hv[e] = __floats2half2_rn(sp[2 * e], sp[2 * e + 1]);
            uint4* dst = (uint4*)&smh[15360 + hh * 4608 + (wl * 16 + r) * 72 + cs];
#pragma unroll
            for (int u = 0; u < 4; u++) dst[u] = ((uint4*)hv)[u];
        }
        __syncthreads();

        {   // row inv-sum from Sh: 2 thr/row over 128 rows (2 heads x 64)
            int row = tid >> 1, hf = tid & 1;
            const __half2* sp = (const __half2*)
                &smh[15360 + (row >> 6) * 4608 + (row & 63) * 72 + hf * 32];
            float s = 0.f;
#pragma unroll
            for (int e = 0; e < 16; e++) {
                float2 f = __half22float2(sp[e]);
                s += f.x + f.y;
            }
            s += __shfl_xor_sync(0xffffffffu, s, 1);
            if (hf == 0) l[row] = 1.f / s;
        }

        {   // O = P @ V -> own strip
            wmma::fragment<wmma::accumulator, 16, 16, 16, float> accO[2];
#pragma unroll
            for (int j = 0; j < 2; j++) wmma::fill_fragment(accO[j], 0.f);
#pragma unroll
            for (int ks = 0; ks < 4; ks++) {
                int kk = ks * 16;
                wmma::fragment<wmma::matrix_a, 16, 16, 16, __half, wmma::row_major> af;
                wmma::load_matrix_sync(af,
                    &smh[15360 + hh * 4608 + (wl * 16) * 72 + kk], 72);
#pragma unroll
                for (int j = 0; j < 2; j++) {
                    wmma::fragment<wmma::matrix_b, 16, 16, 16, __half, wmma::row_major> bf;
                    wmma::load_matrix_sync(bf, &Vh[kk * 40 + j * 16], 40);
                    wmma::mma_sync(accO[j], af, bf, accO[j]);
                }
            }
#pragma unroll
            for (int j = 0; j < 2; j++)
                wmma::store_matrix_sync(&strip[j * 16], accO[j], 68, wmma::mem_row_major);
        }
        __syncthreads();

        {   // per-warp writeout of its 16x32 block
            int r = lane >> 1, c0 = (lane & 1) * 16;
            float inv = l[hh * 64 + wl * 16 + r];
            const float* sp = strip + r * 68 + c0;
            int rg = wl * 16 + r;
            int hg = hp * 2 + hh;
            size_t token = ((size_t)(b * 128 + wy * 8 + (rg >> 3))) * 128 + wx * 8 + (rg & 7);
            __half2 o[8];
#pragma unroll
            for (int e = 0; e < 8; e++)
                o[e] = __floats2half2_rn(sp[2 * e] * inv, sp[2 * e + 1] * inv);
            uint4* d = (uint4*)&att[token * 256 + hg * 32 + c0];
            d[0] = ((uint4*)o)[0];
            d[1] = ((uint4*)o)[1];
        }
    }
}

// ---------------------------------------------------------------------------
extern "C" void kernel_launch(void* const* d_in, const int* in_sizes, int n_in,
                              void* d_out, int out_size)
{
    (void)in_sizes; (void)n_in; (void)out_size;
    const float* x     = (const float*)d_in[0];
    const float* Wqkv  = (const float*)d_in[1];
    const float* Wproj = (const float*)d_in[2];
    const float* bproj = (const float*)d_in[3];
    float* out = (float*)d_out;

    __half *qkv = nullptr, *att = nullptr, *wq = nullptr, *wp = nullptr;
    cudaGetSymbolAddress((void**)&qkv, g_qkv);
    cudaGetSymbolAddress((void**)&att, g_att);
    cudaGetSymbolAddress((void**)&wq,  g_wq);
    cudaGetSymbolAddress((void**)&wp,  g_wp);

    cudaFuncSetAttribute(gemm_h, cudaFuncAttributeMaxDynamicSharedMemorySize, 73728);
    cudaFuncSetAttribute(attn_fused, cudaFuncAttributeMaxDynamicSharedMemorySize, 84480);

    // 0) convert x (into g_att, free until attention) and weights to fp16
    cvt_inputs<<<4096, 256>>>(x, Wqkv, Wproj, att, wq, wp);
    // 1) QKV = xt @ W_qkv  (fp16 out)
    gemm_h<<<dim3(6, 1024), 256, 73728>>>(att, wq, nullptr, qkv, 768, 1);
    // 2+3) fused attention v2: grid [0,4096) + local [4096,8192)
    attn_fused<<<8192, 256, 84480>>>(qkv, att);
    // 4) out = att @ W_proj + b_proj (fp32 out)
    gemm_h<<<dim3(2, 1024), 256, 73728>>>(att, wp, bproj, out, 256, 0);
}

// round 15
// speedup vs baseline: 3.5600x; 1.0159x over previous
#include <cuda_runtime.h>
#include <cuda_fp16.h>
#include <mma.h>
#include <cstdint>
using namespace nvcuda;

// Problem constants: B=8, H=W=128, C=256, NUM_HEADS=8, HD=32, WINDOW=8
#define TOKENS 131072

// Scratch (allocation-free rule: device globals)
__device__ __half g_qkv[100663296u];  // [token][3][head][32] fp16 (q pre-scaled)
__device__ __half g_att[33554432u];   // xt (pre-GEMM1) then att [token][256] fp16
__device__ __half g_wq[196608];       // fp16 W_qkv [256,768] row-major
__device__ __half g_wp[65536];        // fp16 W_proj [256,256] row-major

__device__ __forceinline__ void cp_async16(void* smem, const void* gmem) {
    unsigned s = (unsigned)__cvta_generic_to_shared(smem);
    asm volatile("cp.async.cg.shared.global [%0], [%1], 16;\n" :: "r"(s), "l"(gmem));
}
__device__ __forceinline__ void cp_commit() { asm volatile("cp.async.commit_group;\n"); }
__device__ __forceinline__ void cp_wait1()  { asm volatile("cp.async.wait_group 1;\n"); }
__device__ __forceinline__ void cp_wait0()  { asm volatile("cp.async.wait_group 0;\n"); }

// ---------------------------------------------------------------------------
// Convert inputs to fp16 once: x -> xt, weights -> g_wq/g_wp (same layout).
// ---------------------------------------------------------------------------
__global__ void cvt_inputs(const float* __restrict__ x,
                           const float* __restrict__ wq,
                           const float* __restrict__ wp,
                           __half* __restrict__ xt,
                           __half* __restrict__ wqt,
                           __half* __restrict__ wpt)
{
    const int stride = gridDim.x * blockDim.x;
    const int tid0 = blockIdx.x * blockDim.x + threadIdx.x;
    for (int i = tid0; i < 33554432 / 4; i += stride) {
        float4 v = ((const float4*)x)[i];
        __half2 h0 = __floats2half2_rn(v.x, v.y);
        __half2 h1 = __floats2half2_rn(v.z, v.w);
        ((__half2*)xt)[i * 2]     = h0;
        ((__half2*)xt)[i * 2 + 1] = h1;
    }
    for (int i = tid0; i < 196608 + 65536; i += stride) {
        if (i < 196608) wqt[i] = __float2half_rn(wq[i]);
        else            wpt[i - 196608] = __float2half_rn(wp[i - 196608]);
    }
}

// ---------------------------------------------------------------------------
// FP16 GEMM: C[M,N] = A[M,256] @ B[256,N] (+bias). fp32 accumulate.
// BM=BN=128, BK=64, 2-stage cp.async, 8 warps (2x4), warp tile 64x32.
// half_out=1: emit fp16; q columns (gcol<256, i.e. blockIdx.x<2) are
// pre-multiplied by scale*log2(e) so attention can use bare exp2.
// ---------------------------------------------------------------------------
__global__ __launch_bounds__(256, 2) void gemm_h(
    const __half* __restrict__ A, const __half* __restrict__ B,
    const float* __restrict__ bias, void* Cout, int N, int half_out)
{
    extern __shared__ __half smh[];
    const int tid  = threadIdx.x;
    const int warp = tid >> 5;
    const int lane = tid & 31;
    const int wm = warp >> 2, wn = warp & 3;
    const int bn = blockIdx.x * 128;   // fast dim = cols -> A L2 reuse
    const int bm = blockIdx.y * 128;
    // scale * log2(e) = (1/sqrt(32)) * 1.4426950408889634
    const float qmul = (half_out && bn < 256) ? 0.25503482f : 1.0f;

    wmma::fragment<wmma::accumulator, 16, 16, 16, float> acc[4][2];
#pragma unroll
    for (int i = 0; i < 4; i++)
#pragma unroll
        for (int j = 0; j < 2; j++) wmma::fill_fragment(acc[i][j], 0.f);

    auto load_tile = [&](int s, int k0) {
        __half* As = smh + s * 17920;
        __half* Bs = As + 9216;
#pragma unroll
        for (int t = 0; t < 4; t++) {
            int idx = tid + t * 256;                 // 0..1023
            int ar = idx >> 3, ac = (idx & 7) * 8;   // A: 128 x 64 halfs
            cp_async16(&As[ar * 72 + ac], A + (size_t)(bm + ar) * 256 + k0 + ac);
            int br = idx >> 4, bc = (idx & 15) * 8;  // B: 64 x 128 halfs
            cp_async16(&Bs[br * 136 + bc], B + (size_t)(k0 + br) * N + bn + bc);
        }
        cp_commit();
    };

    load_tile(0, 0);
    const int NK = 4;  // 256/64
    for (int kt = 0; kt < NK; kt++) {
        if (kt + 1 < NK) { load_tile((kt + 1) & 1, (kt + 1) * 64); cp_wait1(); }
        else             { cp_wait0(); }
        __syncthreads();
        const __half* As = smh + (kt & 1) * 17920;
        const __half* Bs = As + 9216;
#pragma unroll
        for (int kk = 0; kk < 64; kk += 16) {
            wmma::fragment<wmma::matrix_a, 16, 16, 16, __half, wmma::row_major> af[4];
            wmma::fragment<wmma::matrix_b, 16, 16, 16, __half, wmma::row_major> bf[2];
#pragma unroll
            for (int i = 0; i < 4; i++)
                wmma::load_matrix_sync(af[i], &As[(wm * 64 + i * 16) * 72 + kk], 72);
#pragma unroll
            for (int j = 0; j < 2; j++)
                wmma::load_matrix_sync(bf[j], &Bs[kk * 136 + wn * 32 + j * 16], 136);
#pragma unroll
            for (int i = 0; i < 4; i++)
#pragma unroll
                for (int j = 0; j < 2; j++)
                    wmma::mma_sync(acc[i][j], af[i], bf[j], acc[i][j]);
        }
        __syncthreads();
    }

    // Epilogue: per-warp 64x36 fp32 strip, bulk coalesced writeout
    float* wb = (float*)smh + warp * 2304;
#pragma unroll
    for (int i = 0; i < 4; i++)
#pragma unroll
        for (int j = 0; j < 2; j++)
            wmma::store_matrix_sync(&wb[(i * 16) * 36 + j * 16], acc[i][j], 36,
                                    wmma::mem_row_major);
    __syncwarp();
#pragma unroll
    for (int it = 0; it < 16; it++) {
        int idx = lane + it * 32;      // 0..511
        int r = idx >> 3;
        int c = (idx & 7) * 4;
        float4 v = *(float4*)&wb[r * 36 + c];
        int grow = bm + wm * 64 + r;
        int gcol = bn + wn * 32 + c;
        if (bias) {
            v.x += bias[gcol + 0]; v.y += bias[gcol + 1];
            v.z += bias[gcol + 2]; v.w += bias[gcol + 3];
        }
        if (half_out) {
            v.x *= qmul; v.y *= qmul; v.z *= qmul; v.w *= qmul;
            __half* Ch = (__half*)Cout;
            __half2* d = (__half2*)&Ch[(size_t)grow * N + gcol];
            d[0] = __floats2half2_rn(v.x, v.y);
            d[1] = __floats2half2_rn(v.z, v.w);
        } else {
            float* Cf = (float*)Cout;
            *(float4*)&Cf[(size_t)grow * N + gcol] = v;
        }
    }
}

// ---------------------------------------------------------------------------
// FUSED attention v3 (fp16, exp2-based softmax, q pre-scaled by GEMM):
//   blocks [0,4096) = grid heads 4..7 (2 qtiles/CTA),
//   blocks [4096,8192) = local windows heads 0..3.
// Shared smem layout (halfs), total 42240 h = 84480 B, 2 CTA/SM.
// ---------------------------------------------------------------------------
__global__ __launch_bounds__(256, 2) void attn_fused(
    const __half* __restrict__ qkv, __half* __restrict__ att)
{
    extern __shared__ __half smh[];
    const int tid = threadIdx.x;
    const int warp = tid >> 5;
    const int lane = tid & 31;
    float* strip = (float*)(smh + 24576) + warp * 1088;   // 16x68 fp32
    float* l = (float*)(smh + 41984);                     // 128 fp32

    if (blockIdx.x < 4096) {
        // ================= GRID (dilated), 2 query tiles per CTA ============
        const int bid = blockIdx.x;
        const int low = bid & 7, cid = bid >> 3;
        const int b = cid >> 6, s1 = (cid >> 3) & 7, s2 = cid & 7;
        const int h = 4 + (low >> 1), qtp = low & 1;   // query rows qtp*128..+127
        const int qh = warp >> 2;      // 0..1 : query tile within pair
        const int wl = warp & 3;       // row tile

        auto stage = [&](int ck) {
            __half* Kd = smh + 5120  + (ck & 1) * 2560;
            __half* Vd = smh + 10240 + (ck & 1) * 2560;
            int rk = tid >> 2, seg = (tid & 3) * 8;     // 64 rows x 4 chunks
            int kk = ck * 64 + rk;
            size_t ktok = ((size_t)(b * 128 + (kk >> 4) * 8 + s1)) * 128 + (kk & 15) * 8 + s2;
            const __half* base = qkv + ktok * 768 + h * 32 + seg;
            cp_async16(&Kd[rk * 40 + seg], base + 256);
            cp_async16(&Vd[rk * 40 + seg], base + 512);
            cp_commit();
        };

        // Stage both Q tiles (128 rows) + first K/V chunk
#pragma unroll
        for (int i = 0; i < 2; i++) {
            int idx = tid + i * 256;           // 0..511
            int qrow = idx >> 2, seg = (idx & 3) * 8;
            int qq = qtp * 128 + qrow;
            size_t token = ((size_t)(b * 128 + (qq >> 4) * 8 + s1)) * 128 + (qq & 15) * 8 + s2;
            cp_async16(&smh[qrow * 40 + seg], qkv + token * 768 + h * 32 + seg);
        }
        if (tid < 128) l[tid] = 0.f;
        stage(0);

        wmma::fragment<wmma::accumulator, 16, 16, 16, float> accO[2];
#pragma unroll
        for (int j = 0; j < 2; j++) wmma::fill_fragment(accO[j], 0.f);

        for (int ck = 0; ck < 4; ck++) {
            cp_wait0();
            __syncthreads();
            if (ck < 3) stage(ck + 1);

            const __half* K = smh + 5120  + (ck & 1) * 2560;
            const __half* V = smh + 10240 + (ck & 1) * 2560;

            {   // S = Q@K^T (q pre-scaled); exp2 applied during fp16 convert
                wmma::fragment<wmma::matrix_a, 16, 16, 16, __half, wmma::row_major> af[2];
#pragma unroll
                for (int ki = 0; ki < 2; ki++)
                    wmma::load_matrix_sync(af[ki],
                        &smh[qh * 2560 + (wl * 16) * 40 + ki * 16], 40);
#pragma unroll
                for (int j = 0; j < 4; j++) {
                    wmma::fragment<wmma::accumulator, 16, 16, 16, float> accS;
                    wmma::fill_fragment(accS, 0.f);
#pragma unroll
                    for (int ki = 0; ki < 2; ki++) {
                        wmma::fragment<wmma::matrix_b, 16, 16, 16, __half, wmma::col_major> bf;
                        wmma::load_matrix_sync(bf, &K[(j * 16) * 40 + ki * 16], 40);
                        wmma::mma_sync(accS, af[ki], bf, accS);
                    }
                    wmma::store_matrix_sync(&strip[j * 16], accS, 68, wmma::mem_row_major);
                }
                __syncwarp();
                // convert strip (16x64 fp32 scores) -> P = exp2(s) in fp16
                int r = lane >> 1, cs = (lane & 1) * 32;
                const float* sp = strip + r * 68 + cs;
                __half2 hv[16];
#pragma unroll
                for (int e = 0; e < 16; e++)
                    hv[e] = h2exp2(__floats2half2_rn(sp[2 * e], sp[2 * e + 1]));
                uint4* dst = (uint4*)&smh[15360 + qh * 4608 + (wl * 16 + r) * 72 + cs];
#pragma unroll
                for (int u = 0; u < 4; u++) dst[u] = ((uint4*)hv)[u];
            }
            __syncthreads();

            {   // row-sum from Sh (does NOT gate PV): 2 thr/row over 128 rows
                int row = tid >> 1, hf = tid & 1;
                const __half2* sp = (const __half2*)
                    &smh[15360 + (row >> 6) * 4608 + (row & 63) * 72 + hf * 32];
                float s = 0.f;
#pragma unroll
                for (int e = 0; e < 16; e++) {
                    float2 f = __half22float2(sp[e]);
                    s += f.x + f.y;
                }
                s += __shfl_xor_sync(0xffffffffu, s, 1);
                if (hf == 0) l[row] += s;
            }

            // O += P @ V (both 16-col tiles per warp)
#pragma unroll
            for (int ks = 0; ks < 4; ks++) {
                int kk = ks * 16;
                wmma::fragment<wmma::matrix_a, 16, 16, 16, __half, wmma::row_major> af;
                wmma::load_matrix_sync(af,
                    &smh[15360 + qh * 4608 + (wl * 16) * 72 + kk], 72);
#pragma unroll
                for (int j = 0; j < 2; j++) {
                    wmma::fragment<wmma::matrix_b, 16, 16, 16, __half, wmma::row_major> bf;
                    wmma::load_matrix_sync(bf, &V[kk * 40 + j * 16], 40);
                    wmma::mma_sync(accO[j], af, bf, accO[j]);
                }
            }
        }

        // Store O to own strip; final sync for l; per-warp writeout
#pragma unroll
        for (int j = 0; j < 2; j++)
            wmma::store_matrix_sync(&strip[j * 16], accO[j], 68, wmma::mem_row_major);
        __syncthreads();
        {
            int r = lane >> 1, c0 = (lane & 1) * 16;
            float inv = 1.f / l[qh * 64 + wl * 16 + r];
            const float* sp = strip + r * 68 + c0;
            int qq = qtp * 128 + qh * 64 + wl * 16 + r;
            size_t token = ((size_t)(b * 128 + (qq >> 4) * 8 + s1)) * 128 + (qq & 15) * 8 + s2;
            __half2 o[8];
#pragma unroll
            for (int e = 0; e < 8; e++)
                o[e] = __floats2half2_rn(sp[2 * e] * inv, sp[2 * e + 1] * inv);
            uint4* d = (uint4*)&att[token * 256 + h * 32 + c0];
            d[0] = ((uint4*)o)[0];
            d[1] = ((uint4*)o)[1];
        }
    } else {
        // ================= LOCAL window attention (2 heads per CTA) =========
        const int lb = blockIdx.x - 4096;
        const int wid = lb >> 1, hp = lb & 1;
        const int b = wid >> 8, wy = (wid >> 4) & 15, wx = wid & 15;
        const int hh = warp >> 2, wl = warp & 3;

#pragma unroll
        for (int i = 0; i < 2; i++) {
            int idx = tid + i * 256;            // 0..511
            int h2 = idx >> 8;
            int r  = (idx >> 2) & 63;
            int seg = (idx & 3) * 8;
            int hg = hp * 2 + h2;
            size_t token = ((size_t)(b * 128 + wy * 8 + (r >> 3))) * 128 + wx * 8 + (r & 7);
            const __half* base = qkv + token * 768 + hg * 32 + seg;
            __half* hb = smh + h2 * 7680;
            cp_async16(&hb[r * 40 + seg], base);                // Q (pre-scaled)
            cp_async16(&hb[2560 + r * 40 + seg], base + 256);   // K
            cp_async16(&hb[5120 + r * 40 + seg], base + 512);   // V
        }
        cp_commit();
        cp_wait0();
        __syncthreads();

        const __half* Qh = smh + hh * 7680;
        const __half* Kh = Qh + 2560;
        const __half* Vh = Qh + 5120;

        {   // S = Q@K^T; exp2 in convert. 16 rows x 64 cols per warp -> Sh
            wmma::fragment<wmma::matrix_a, 16, 16, 16, __half, wmma::row_major> af[2];
#pragma unroll
            for (int ki = 0; ki < 2; ki++)
                wmma::load_matrix_sync(af[ki], &Qh[(wl * 16) * 40 + ki * 16], 40);
#pragma unroll
            for (int j = 0; j < 4; j++) {
                wmma::fragment<wmma::accumulator, 16, 16, 16, float> accS;
                wmma::fill_fragment(accS, 0.f);
#pragma unroll
                for (int ki = 0; ki < 2; ki++) {
                    wmma::fragment<wmma::matrix_b, 16, 16, 16, __half, wmma::col_major> bf;
                    wmma::load_matrix_sync(bf, &Kh[(j * 16) * 40 + ki * 16], 40);
                    wmma::mma_sync(accS, af[ki], bf, accS);
                }
                wmma::store_matrix_sync(&strip[j * 16], accS, 68, wmma::mem_row_major);
            }
            __syncwarp();
            int r = lane >> 1, cs = (lane & 1) * 32;
            const float* sp = strip + r * 68 + cs;
            __half2 hv[16];
#pragma unroll
            for (int e = 0; e < 16; e++)
                hv[e] = h2exp2(__floats2half2_rn(sp[2 * e], sp[2 * e + 1]));
            uint4* dst = (uint4*)&smh[15360 + hh * 4608 + (wl * 16 + r) * 72 + cs];
#pragma unroll
            for (int u = 0; u < 4; u++) dst[u] = ((uint4*)hv)[u];
        }
        __syncthreads();

        {   // row inv-sum from Sh: 2 thr/row over 128 rows (2 heads x 64)
            int row = tid >> 1, hf = tid & 1;
            const __half2* sp = (const __half2*)
                &smh[15360 + (row >> 6) * 4608 + (row & 63) * 72 + hf * 32];
            float s = 0.f;
#pragma unroll
            for (int e = 0; e < 16; e++) {
                float2 f = __half22float2(sp[e]);
                s += f.x + f.y;
            }
            s += __shfl_xor_sync(0xffffffffu, s, 1);
            if (hf == 0) l[row] = 1.f / s;
        }

        {   // O = P @ V -> own strip
            wmma::fragment<wmma::accumulator, 16, 16, 16, float> accO[2];
#pragma unroll
            for (int j = 0; j < 2; j++) wmma::fill_fragment(accO[j], 0.f);
#pragma unroll
            for (int ks = 0; ks < 4; ks++) {
                int kk = ks * 16;
                wmma::fragment<wmma::matrix_a, 16, 16, 16, __half, wmma::row_major> af;
                wmma::load_matrix_sync(af,
                    &smh[15360 + hh * 4608 + (wl * 16) * 72 + kk], 72);
#pragma unroll
                for (int j = 0; j < 2; j++) {
                    wmma::fragment<wmma::matrix_b, 16, 16, 16, __half, wmma::row_major> bf;
                    wmma::load_matrix_sync(bf, &Vh[kk * 40 + j * 16], 40);
                    wmma::mma_sync(accO[j], af, bf, accO[j]);
                }
            }
#pragma unroll
            for (int j = 0; j < 2; j++)
                wmma::store_matrix_sync(&strip[j * 16], accO[j], 68, wmma::mem_row_major);
        }
        __syncthreads();

        {   // per-warp writeout of its 16x32 block
            int r = lane >> 1, c0 = (lane & 1) * 16;
            float inv = l[hh * 64 + wl * 16 + r];
            const float* sp = strip + r * 68 + c0;
            int rg = wl * 16 + r;
            int hg = hp * 2 + hh;
            size_t token = ((size_t)(b * 128 + wy * 8 + (rg >> 3))) * 128 + wx * 8 + (rg & 7);
            __half2 o[8];
#pragma unroll
            for (int e = 0; e < 8; e++)
                o[e] = __floats2half2_rn(sp[2 * e] * inv, sp[2 * e + 1] * inv);
            uint4* d = (uint4*)&att[token * 256 + hg * 32 + c0];
            d[0] = ((uint4*)o)[0];
            d[1] = ((uint4*)o)[1];
        }
    }
}

// ---------------------------------------------------------------------------
extern "C" void kernel_launch(void* const* d_in, const int* in_sizes, int n_in,
                              void* d_out, int out_size)
{
    (void)in_sizes; (void)n_in; (void)out_size;
    const float* x     = (const float*)d_in[0];
    const float* Wqkv  = (const float*)d_in[1];
    const float* Wproj = (const float*)d_in[2];
    const float* bproj = (const float*)d_in[3];
    float* out = (float*)d_out;

    __half *qkv = nullptr, *att = nullptr, *wq = nullptr, *wp = nullptr;
    cudaGetSymbolAddress((void**)&qkv, g_qkv);
    cudaGetSymbolAddress((void**)&att, g_att);
    cudaGetSymbolAddress((void**)&wq,  g_wq);
    cudaGetSymbolAddress((void**)&wp,  g_wp);

    cudaFuncSetAttribute(gemm_h, cudaFuncAttributeMaxDynamicSharedMemorySize, 73728);
    cudaFuncSetAttribute(attn_fused, cudaFuncAttributeMaxDynamicSharedMemorySize, 84480);

    // 0) convert x (into g_att, free until attention) and weights to fp16
    cvt_inputs<<<4096, 256>>>(x, Wqkv, Wproj, att, wq, wp);
    // 1) QKV = xt @ W_qkv  (fp16 out; q columns pre-scaled by scale*log2e)
    gemm_h<<<dim3(6, 1024), 256, 73728>>>(att, wq, nullptr, qkv, 768, 1);
    // 2+3) fused attention v3: grid [0,4096) + local [4096,8192)
    attn_fused<<<8192, 256, 84480>>>(qkv, att);
    // 4) out = att @ W_proj + b_proj (fp32 out)
    gemm_h<<<dim3(2, 1024), 256, 73728>>>(att, wp, bproj, out, 256, 0);
}

// round 16
// speedup vs baseline: 3.6495x; 1.0251x over previous
#include <cuda_runtime.h>
#include <cuda_fp16.h>
#include <mma.h>
#include <cstdint>
using namespace nvcuda;

// Problem constants: B=8, H=W=128, C=256, NUM_HEADS=8, HD=32, WINDOW=8
#define TOKENS 131072

// Scratch (allocation-free rule: device globals)
__device__ __half g_qkv[100663296u];  // [token][3][head][32] fp16 (q pre-scaled)
__device__ __half g_att[33554432u];   // att [token][256] fp16
__device__ __half g_wq[196608];       // fp16 W_qkv [256,768] row-major
__device__ __half g_wp[65536];        // fp16 W_proj [256,256] row-major

__device__ __forceinline__ void cp_async16(void* smem, const void* gmem) {
    unsigned s = (unsigned)__cvta_generic_to_shared(smem);
    asm volatile("cp.async.cg.shared.global [%0], [%1], 16;\n" :: "r"(s), "l"(gmem));
}
__device__ __forceinline__ void cp_commit() { asm volatile("cp.async.commit_group;\n"); }
__device__ __forceinline__ void cp_wait1()  { asm volatile("cp.async.wait_group 1;\n"); }
__device__ __forceinline__ void cp_wait0()  { asm volatile("cp.async.wait_group 0;\n"); }

// ---------------------------------------------------------------------------
// Convert WEIGHTS only to fp16 (x is converted inside the QKV GEMM staging).
// 262144 threads, one element each.
// ---------------------------------------------------------------------------
__global__ void cvt_w(const float* __restrict__ wq, const float* __restrict__ wp,
                      __half* __restrict__ wqt, __half* __restrict__ wpt)
{
    int i = blockIdx.x * blockDim.x + threadIdx.x;
    if (i < 196608) wqt[i] = __float2half_rn(wq[i]);
    else            wpt[i - 196608] = __float2half_rn(wp[i - 196608]);
}

// ---------------------------------------------------------------------------
// QKV GEMM: qkv[M,768] = x(fp32)[M,256] @ Wq(fp16)[256,768], fp16 out.
// A staged via LDG.128 + convert + STS (fused cvt); B via cp.async.
// BM=BN=128, BK=64, 2-stage. q columns (bn<256) pre-scaled by scale*log2e.
// ---------------------------------------------------------------------------
__global__ __launch_bounds__(256, 2) void gemm_qkv(
    const float* __restrict__ A, const __half* __restrict__ B,
    __half* __restrict__ C, int N)
{
    extern __shared__ __half smh[];
    const int tid  = threadIdx.x;
    const int warp = tid >> 5;
    const int lane = tid & 31;
    const int wm = warp >> 2, wn = warp & 3;
    const int bn = blockIdx.x * 128;   // fast dim = cols -> A L2 reuse
    const int bm = blockIdx.y * 128;
    const float qmul = (bn < 256) ? 0.25503482f : 1.0f;  // scale*log2(e)

    wmma::fragment<wmma::accumulator, 16, 16, 16, float> acc[4][2];
#pragma unroll
    for (int i = 0; i < 4; i++)
#pragma unroll
        for (int j = 0; j < 2; j++) wmma::fill_fragment(acc[i][j], 0.f);

    auto cp_B = [&](int s, int k0) {
        __half* Bs = smh + s * 17920 + 9216;
#pragma unroll
        for (int t = 0; t < 4; t++) {
            int idx = tid + t * 256;                 // 0..1023
            int br = idx >> 4, bc = (idx & 15) * 8;  // B: 64 x 128 halfs
            cp_async16(&Bs[br * 136 + bc], B + (size_t)(k0 + br) * N + bn + bc);
        }
        cp_commit();
    };
    auto ldg_sts_A = [&](int s, int k0) {
        __half* As = smh + s * 17920;
#pragma unroll
        for (int bq = 0; bq < 2; bq++) {
            float4 t[4];
#pragma unroll
            for (int i = 0; i < 4; i++) {
                int idx = tid + (bq * 4 + i) * 256;  // 0..2047
                int r = idx >> 4, c4 = (idx & 15) * 4;
                t[i] = *(const float4*)(A + (size_t)(bm + r) * 256 + k0 + c4);
            }
#pragma unroll
            for (int i = 0; i < 4; i++) {
                int idx = tid + (bq * 4 + i) * 256;
                int r = idx >> 4, c4 = (idx & 15) * 4;
                *(__half2*)&As[r * 72 + c4]     = __floats2half2_rn(t[i].x, t[i].y);
                *(__half2*)&As[r * 72 + c4 + 2] = __floats2half2_rn(t[i].z, t[i].w);
            }
        }
    };

    cp_B(0, 0);
    cp_B(1, 64);
    ldg_sts_A(0, 0);
    ldg_sts_A(1, 64);

    const int NK = 4;  // 256/64
    for (int kt = 0; kt < NK; kt++) {
        if (kt == NK - 1) cp_wait0(); else cp_wait1();
        __syncthreads();
        const __half* As = smh + (kt & 1) * 17920;
        const __half* Bs = As + 9216;
#pragma unroll
        for (int kk = 0; kk < 64; kk += 16) {
            wmma::fragment<wmma::matrix_a, 16, 16, 16, __half, wmma::row_major> af[4];
            wmma::fragment<wmma::matrix_b, 16, 16, 16, __half, wmma::row_major> bf[2];
#pragma unroll
            for (int i = 0; i < 4; i++)
                wmma::load_matrix_sync(af[i], &As[(wm * 64 + i * 16) * 72 + kk], 72);
#pragma unroll
            for (int j = 0; j < 2; j++)
                wmma::load_matrix_sync(bf[j], &Bs[kk * 136 + wn * 32 + j * 16], 136);
#pragma unroll
            for (int i = 0; i < 4; i++)
#pragma unroll
                for (int j = 0; j < 2; j++)
                    wmma::mma_sync(acc[i][j], af[i], bf[j], acc[i][j]);
        }
        __syncthreads();
        if (kt + 2 < NK) {
            cp_B(kt & 1, (kt + 2) * 64);
            ldg_sts_A(kt & 1, (kt + 2) * 64);
        }
    }

    // Epilogue: per-warp 64x36 fp32 strip, fp16 writeout with qmul
    float* wb = (float*)smh + warp * 2304;
#pragma unroll
    for (int i = 0; i < 4; i++)
#pragma unroll
        for (int j = 0; j < 2; j++)
            wmma::store_matrix_sync(&wb[(i * 16) * 36 + j * 16], acc[i][j], 36,
                                    wmma::mem_row_major);
    __syncwarp();
#pragma unroll
    for (int it = 0; it < 16; it++) {
        int idx = lane + it * 32;
        int r = idx >> 3;
        int c = (idx & 7) * 4;
        float4 v = *(float4*)&wb[r * 36 + c];
        int grow = bm + wm * 64 + r;
        int gcol = bn + wn * 32 + c;
        v.x *= qmul; v.y *= qmul; v.z *= qmul; v.w *= qmul;
        __half2* d = (__half2*)&C[(size_t)grow * N + gcol];
        d[0] = __floats2half2_rn(v.x, v.y);
        d[1] = __floats2half2_rn(v.z, v.w);
    }
}

// ---------------------------------------------------------------------------
// Proj GEMM (fp16 A, fp32 out + bias). Unchanged from round 14/15.
// ---------------------------------------------------------------------------
__global__ __launch_bounds__(256, 2) void gemm_h(
    const __half* __restrict__ A, const __half* __restrict__ B,
    const float* __restrict__ bias, float* __restrict__ C, int N)
{
    extern __shared__ __half smh[];
    const int tid  = threadIdx.x;
    const int warp = tid >> 5;
    const int lane = tid & 31;
    const int wm = warp >> 2, wn = warp & 3;
    const int bn = blockIdx.x * 128;
    const int bm = blockIdx.y * 128;

    wmma::fragment<wmma::accumulator, 16, 16, 16, float> acc[4][2];
#pragma unroll
    for (int i = 0; i < 4; i++)
#pragma unroll
        for (int j = 0; j < 2; j++) wmma::fill_fragment(acc[i][j], 0.f);

    auto load_tile = [&](int s, int k0) {
        __half* As = smh + s * 17920;
        __half* Bs = As + 9216;
#pragma unroll
        for (int t = 0; t < 4; t++) {
            int idx = tid + t * 256;
            int ar = idx >> 3, ac = (idx & 7) * 8;
            cp_async16(&As[ar * 72 + ac], A + (size_t)(bm + ar) * 256 + k0 + ac);
            int br = idx >> 4, bc = (idx & 15) * 8;
            cp_async16(&Bs[br * 136 + bc], B + (size_t)(k0 + br) * N + bn + bc);
        }
        cp_commit();
    };

    load_tile(0, 0);
    const int NK = 4;
    for (int kt = 0; kt < NK; kt++) {
        if (kt + 1 < NK) { load_tile((kt + 1) & 1, (kt + 1) * 64); cp_wait1(); }
        else             { cp_wait0(); }
        __syncthreads();
        const __half* As = smh + (kt & 1) * 17920;
        const __half* Bs = As + 9216;
#pragma unroll
        for (int kk = 0; kk < 64; kk += 16) {
            wmma::fragment<wmma::matrix_a, 16, 16, 16, __half, wmma::row_major> af[4];
            wmma::fragment<wmma::matrix_b, 16, 16, 16, __half, wmma::row_major> bf[2];
#pragma unroll
            for (int i = 0; i < 4; i++)
                wmma::load_matrix_sync(af[i], &As[(wm * 64 + i * 16) * 72 + kk], 72);
#pragma unroll
            for (int j = 0; j < 2; j++)
                wmma::load_matrix_sync(bf[j], &Bs[kk * 136 + wn * 32 + j * 16], 136);
#pragma unroll
            for (int i = 0; i < 4; i++)
#pragma unroll
                for (int j = 0; j < 2; j++)
                    wmma::mma_sync(acc[i][j], af[i], bf[j], acc[i][j]);
        }
        __syncthreads();
    }

    float* wb = (float*)smh + warp * 2304;
#pragma unroll
    for (int i = 0; i < 4; i++)
#pragma unroll
        for (int j = 0; j < 2; j++)
            wmma::store_matrix_sync(&wb[(i * 16) * 36 + j * 16], acc[i][j], 36,
                                    wmma::mem_row_major);
    __syncwarp();
#pragma unroll
    for (int it = 0; it < 16; it++) {
        int idx = lane + it * 32;
        int r = idx >> 3;
        int c = (idx & 7) * 4;
        float4 v = *(float4*)&wb[r * 36 + c];
        int grow = bm + wm * 64 + r;
        int gcol = bn + wn * 32 + c;
        v.x += bias[gcol + 0]; v.y += bias[gcol + 1];
        v.z += bias[gcol + 2]; v.w += bias[gcol + 3];
        *(float4*)&C[(size_t)grow * N + gcol] = v;
    }
}

// ---------------------------------------------------------------------------
// FUSED attention v4: warp-owned softmax (row-sum fused into convert, block
// barriers only around K/V staging). exp2 softmax, q pre-scaled by GEMM.
//   blocks [0,4096) = grid heads 4..7 (2 qtiles/CTA),
//   blocks [4096,8192) = local windows heads 0..3.  smem 84480B, 2 CTA/SM.
// ---------------------------------------------------------------------------
__global__ __launch_bounds__(256, 2) void attn_fused(
    const __half* __restrict__ qkv, __half* __restrict__ att)
{
    extern __shared__ __half smh[];
    const int tid = threadIdx.x;
    const int warp = tid >> 5;
    const int lane = tid & 31;
    float* strip = (float*)(smh + 24576) + warp * 1088;   // 16x68 fp32 (private)
    float* l = (float*)(smh + 41984);                     // 128 fp32

    if (blockIdx.x < 4096) {
        // ================= GRID (dilated), 2 query tiles per CTA ============
        const int bid = blockIdx.x;
        const int low = bid & 7, cid = bid >> 3;
        const int b = cid >> 6, s1 = (cid >> 3) & 7, s2 = cid & 7;
        const int h = 4 + (low >> 1), qtp = low & 1;
        const int qh = warp >> 2;      // 0..1 : query tile within pair
        const int wl = warp & 3;       // row tile

        auto stage = [&](int ck) {
            __half* Kd = smh + 5120  + (ck & 1) * 2560;
            __half* Vd = smh + 10240 + (ck & 1) * 2560;
            int rk = tid >> 2, seg = (tid & 3) * 8;
            int kk = ck * 64 + rk;
            size_t ktok = ((size_t)(b * 128 + (kk >> 4) * 8 + s1)) * 128 + (kk & 15) * 8 + s2;
            const __half* base = qkv + ktok * 768 + h * 32 + seg;
            cp_async16(&Kd[rk * 40 + seg], base + 256);
            cp_async16(&Vd[rk * 40 + seg], base + 512);
            cp_commit();
        };

#pragma unroll
        for (int i = 0; i < 2; i++) {
            int idx = tid + i * 256;
            int qrow = idx >> 2, seg = (idx & 3) * 8;
            int qq = qtp * 128 + qrow;
            size_t token = ((size_t)(b * 128 + (qq >> 4) * 8 + s1)) * 128 + (qq & 15) * 8 + s2;
            cp_async16(&smh[qrow * 40 + seg], qkv + token * 768 + h * 32 + seg);
        }
        stage(0);

        wmma::fragment<wmma::accumulator, 16, 16, 16, float> accO[2];
#pragma unroll
        for (int j = 0; j < 2; j++) wmma::fill_fragment(accO[j], 0.f);

        for (int ck = 0; ck < 4; ck++) {
            cp_wait0();
            __syncthreads();
            if (ck < 3) stage(ck + 1);

            const __half* K = smh + 5120  + (ck & 1) * 2560;
            const __half* V = smh + 10240 + (ck & 1) * 2560;

            // S = Q@K^T -> own strip
            {
                wmma::fragment<wmma::matrix_a, 16, 16, 16, __half, wmma::row_major> af[2];
#pragma unroll
                for (int ki = 0; ki < 2; ki++)
                    wmma::load_matrix_sync(af[ki],
                        &smh[qh * 2560 + (wl * 16) * 40 + ki * 16], 40);
#pragma unroll
                for (int j = 0; j < 4; j++) {
                    wmma::fragment<wmma::accumulator, 16, 16, 16, float> accS;
                    wmma::fill_fragment(accS, 0.f);
#pragma unroll
                    for (int ki = 0; ki < 2; ki++) {
                        wmma::fragment<wmma::matrix_b, 16, 16, 16, __half, wmma::col_major> bf;
                        wmma::load_matrix_sync(bf, &K[(j * 16) * 40 + ki * 16], 40);
                        wmma::mma_sync(accS, af[ki], bf, accS);
                    }
                    wmma::store_matrix_sync(&strip[j * 16], accS, 68, wmma::mem_row_major);
                }
            }
            __syncwarp();
            // convert (exp2) + fused warp-local row-sum
            {
                int r = lane >> 1, cs = (lane & 1) * 32;
                const float* sp = strip + r * 68 + cs;
                __half2 hv[16];
                float s = 0.f;
#pragma unroll
                for (int e = 0; e < 16; e++) {
                    hv[e] = h2exp2(__floats2half2_rn(sp[2 * e], sp[2 * e + 1]));
                    float2 f = __half22float2(hv[e]);
                    s += f.x + f.y;
                }
                uint4* dst = (uint4*)&smh[15360 + qh * 4608 + (wl * 16 + r) * 72 + cs];
#pragma unroll
                for (int u = 0; u < 4; u++) dst[u] = ((uint4*)hv)[u];
                s += __shfl_xor_sync(0xffffffffu, s, 1);
                if ((lane & 1) == 0) {
                    int row = qh * 64 + wl * 16 + r;
                    l[row] = (ck == 0) ? s : l[row] + s;
                }
            }
            __syncwarp();

            // O += P @ V (own Sh rows)
#pragma unroll
            for (int ks = 0; ks < 4; ks++) {
                int kk = ks * 16;
                wmma::fragment<wmma::matrix_a, 16, 16, 16, __half, wmma::row_major> af;
                wmma::load_matrix_sync(af,
                    &smh[15360 + qh * 4608 + (wl * 16) * 72 + kk], 72);
#pragma unroll
                for (int j = 0; j < 2; j++) {
                    wmma::fragment<wmma::matrix_b, 16, 16, 16, __half, wmma::row_major> bf;
                    wmma::load_matrix_sync(bf, &V[kk * 40 + j * 16], 40);
                    wmma::mma_sync(accO[j], af, bf, accO[j]);
                }
            }
        }

#pragma unroll
        for (int j = 0; j < 2; j++)
            wmma::store_matrix_sync(&strip[j * 16], accO[j], 68, wmma::mem_row_major);
        __syncwarp();
        {
            int r = lane >> 1, c0 = (lane & 1) * 16;
            float inv = 1.f / l[qh * 64 + wl * 16 + r];
            const float* sp = strip + r * 68 + c0;
            int qq = qtp * 128 + qh * 64 + wl * 16 + r;
            size_t token = ((size_t)(b * 128 + (qq >> 4) * 8 + s1)) * 128 + (qq & 15) * 8 + s2;
            __half2 o[8];
#pragma unroll
            for (int e = 0; e < 8; e++)
                o[e] = __floats2half2_rn(sp[2 * e] * inv, sp[2 * e + 1] * inv);
            uint4* d = (uint4*)&att[token * 256 + h * 32 + c0];
            d[0] = ((uint4*)o)[0];
            d[1] = ((uint4*)o)[1];
        }
    } else {
        // ================= LOCAL window attention (2 heads per CTA) =========
        const int lb = blockIdx.x - 4096;
        const int wid = lb >> 1, hp = lb & 1;
        const int b = wid >> 8, wy = (wid >> 4) & 15, wx = wid & 15;
        const int hh = warp >> 2, wl = warp & 3;

#pragma unroll
        for (int i = 0; i < 2; i++) {
            int idx = tid + i * 256;
            int h2 = idx >> 8;
            int r  = (idx >> 2) & 63;
            int seg = (idx & 3) * 8;
            int hg = hp * 2 + h2;
            size_t token = ((size_t)(b * 128 + wy * 8 + (r >> 3))) * 128 + wx * 8 + (r & 7);
            const __half* base = qkv + token * 768 + hg * 32 + seg;
            __half* hb = smh + h2 * 7680;
            cp_async16(&hb[r * 40 + seg], base);
            cp_async16(&hb[2560 + r * 40 + seg], base + 256);
            cp_async16(&hb[5120 + r * 40 + seg], base + 512);
        }
        cp_commit();
        cp_wait0();
        __syncthreads();

        const __half* Qh = smh + hh * 7680;
        const __half* Kh = Qh + 2560;
        const __half* Vh = Qh + 5120;

        {   // S = Q@K^T -> own strip
            wmma::fragment<wmma::matrix_a, 16, 16, 16, __half, wmma::row_major> af[2];
#pragma unroll
            for (int ki = 0; ki < 2; ki++)
                wmma::load_matrix_sync(af[ki], &Qh[(wl * 16) * 40 + ki * 16], 40);
#pragma unroll
            for (int j = 0; j < 4; j++) {
                wmma::fragment<wmma::accumulator, 16, 16, 16, float> accS;
                wmma::fill_fragment(accS, 0.f);
#pragma unroll
                for (int ki = 0; ki < 2; ki++) {
                    wmma::fragment<wmma::matrix_b, 16, 16, 16, __half, wmma::col_major> bf;
                    wmma::load_matrix_sync(bf, &Kh[(j * 16) * 40 + ki * 16], 40);
                    wmma::mma_sync(accS, af[ki], bf, accS);
                }
                wmma::store_matrix_sync(&strip[j * 16], accS, 68, wmma::mem_row_major);
            }
        }
        __syncwarp();
        {   // convert (exp2) + fused warp-local inverse row-sum
            int r = lane >> 1, cs = (lane & 1) * 32;
            const float* sp = strip + r * 68 + cs;
            __half2 hv[16];
            float s = 0.f;
#pragma unroll
            for (int e = 0; e < 16; e++) {
                hv[e] = h2exp2(__floats2half2_rn(sp[2 * e], sp[2 * e + 1]));
                float2 f = __half22float2(hv[e]);
                s += f.x + f.y;
            }
            uint4* dst = (uint4*)&smh[15360 + hh * 4608 + (wl * 16 + r) * 72 + cs];
#pragma unroll
            for (int u = 0; u < 4; u++) dst[u] = ((uint4*)hv)[u];
            s += __shfl_xor_sync(0xffffffffu, s, 1);
            if ((lane & 1) == 0) l[hh * 64 + wl * 16 + r] = 1.f / s;
        }
        __syncwarp();

        {   // O = P @ V (own Sh rows) -> own strip
            wmma::fragment<wmma::accumulator, 16, 16, 16, float> accO[2];
#pragma unroll
            for (int j = 0; j < 2; j++) wmma::fill_fragment(accO[j], 0.f);
#pragma unroll
            for (int ks = 0; ks < 4; ks++) {
                int kk = ks * 16;
                wmma::fragment<wmma::matrix_a, 16, 16, 16, __half, wmma::row_major> af;
                wmma::load_matrix_sync(af,
                    &smh[15360 + hh * 4608 + (wl * 16) * 72 + kk], 72);
#pragma unroll
                for (int j = 0; j < 2; j++) {
                    wmma::fragment<wmma::matrix_b, 16, 16, 16, __half, wmma::row_major> bf;
                    wmma::load_matrix_sync(bf, &Vh[kk * 40 + j * 16], 40);
                    wmma::mma_sync(accO[j], af, bf, accO[j]);
                }
            }
#pragma unroll
            for (int j = 0; j < 2; j++)
                wmma::store_matrix_sync(&strip[j * 16], accO[j], 68, wmma::mem_row_major);
        }
        __syncwarp();

        {   // per-warp writeout of its 16x32 block
            int r = lane >> 1, c0 = (lane & 1) * 16;
            float inv = l[hh * 64 + wl * 16 + r];
            const float* sp = strip + r * 68 + c0;
            int rg = wl * 16 + r;
            int hg = hp * 2 + hh;
            size_t token = ((size_t)(b * 128 + wy * 8 + (rg >> 3))) * 128 + wx * 8 + (rg & 7);
            __half2 o[8];
#pragma unroll
            for (int e = 0; e < 8; e++)
                o[e] = __floats2half2_rn(sp[2 * e] * inv, sp[2 * e + 1] * inv);
            uint4* d = (uint4*)&att[token * 256 + hg * 32 + c0];
            d[0] = ((uint4*)o)[0];
            d[1] = ((uint4*)o)[1];
        }
    }
}

// ---------------------------------------------------------------------------
extern "C" void kernel_launch(void* const* d_in, const int* in_sizes, int n_in,
                              void* d_out, int out_size)
{
    (void)in_sizes; (void)n_in; (void)out_size;
    const float* x     = (const float*)d_in[0];
    const float* Wqkv  = (const float*)d_in[1];
    const float* Wproj = (const float*)d_in[2];
    const float* bproj = (const float*)d_in[3];
    float* out = (float*)d_out;

    __half *qkv = nullptr, *att = nullptr, *wq = nullptr, *wp = nullptr;
    cudaGetSymbolAddress((void**)&qkv, g_qkv);
    cudaGetSymbolAddress((void**)&att, g_att);
    cudaGetSymbolAddress((void**)&wq,  g_wq);
    cudaGetSymbolAddress((void**)&wp,  g_wp);

    cudaFuncSetAttribute(gemm_qkv, cudaFuncAttributeMaxDynamicSharedMemorySize, 73728);
    cudaFuncSetAttribute(gemm_h, cudaFuncAttributeMaxDynamicSharedMemorySize, 73728);
    cudaFuncSetAttribute(attn_fused, cudaFuncAttributeMaxDynamicSharedMemorySize, 84480);

    // 0) convert weights to fp16 (x converted inside gemm_qkv staging)
    cvt_w<<<1024, 256>>>(Wqkv, Wproj, wq, wp);
    // 1) QKV = x @ W_qkv  (fp32 A fused-convert; q cols pre-scaled; fp16 out)
    gemm_qkv<<<dim3(6, 1024), 256, 73728>>>(x, wq, qkv, 768);
    // 2+3) fused attention v4: grid [0,4096) + local [4096,8192)
    attn_fused<<<8192, 256, 84480>>>(qkv, att);
    // 4) out = att @ W_proj + b_proj (fp32 out)
    gemm_h<<<dim3(2, 1024), 256, 73728>>>(att, wp, bproj, out, 256);
}

// round 17
// speedup vs baseline: 3.6617x; 1.0033x over previous
#include <cuda_runtime.h>
#include <cuda_fp16.h>
#include <mma.h>
#include <cstdint>
using namespace nvcuda;

// Problem constants: B=8, H=W=128, C=256, NUM_HEADS=8, HD=32, WINDOW=8
#define TOKENS 131072

// Scratch (allocation-free rule: device globals)
__device__ __half g_qkv[100663296u];  // [token][3][head][32] fp16 (q pre-scaled)
__device__ __half g_att[33554432u];   // att [token][256] fp16
__device__ __half g_wq[196608];       // fp16 W_qkv [256,768] row-major
__device__ __half g_wp[65536];        // fp16 W_proj [256,256] row-major

__device__ __forceinline__ void cp_async16(void* smem, const void* gmem) {
    unsigned s = (unsigned)__cvta_generic_to_shared(smem);
    asm volatile("cp.async.cg.shared.global [%0], [%1], 16;\n" :: "r"(s), "l"(gmem));
}
__device__ __forceinline__ void cp_commit() { asm volatile("cp.async.commit_group;\n"); }
__device__ __forceinline__ void cp_wait1()  { asm volatile("cp.async.wait_group 1;\n"); }
__device__ __forceinline__ void cp_wait0()  { asm volatile("cp.async.wait_group 0;\n"); }

// ---------------------------------------------------------------------------
// Convert WEIGHTS only to fp16 (x is converted inside the QKV GEMM staging).
// ---------------------------------------------------------------------------
__global__ void cvt_w(const float* __restrict__ wq, const float* __restrict__ wp,
                      __half* __restrict__ wqt, __half* __restrict__ wpt)
{
    int i = blockIdx.x * blockDim.x + threadIdx.x;
    if (i < 196608) wqt[i] = __float2half_rn(wq[i]);
    else            wpt[i - 196608] = __float2half_rn(wp[i - 196608]);
}

// ---------------------------------------------------------------------------
// QKV GEMM: qkv[M,768] = x(fp32)[M,256] @ Wq(fp16)[256,768], fp16 out.
// A staged via LDG.128 + convert + STS (fused cvt); B via cp.async.
// BM=BN=128, BK=64, 2-stage. q columns (bn<256) pre-scaled by scale*log2e.
// ---------------------------------------------------------------------------
__global__ __launch_bounds__(256, 2) void gemm_qkv(
    const float* __restrict__ A, const __half* __restrict__ B,
    __half* __restrict__ C, int N)
{
    extern __shared__ __half smh[];
    const int tid  = threadIdx.x;
    const int warp = tid >> 5;
    const int lane = tid & 31;
    const int wm = warp >> 2, wn = warp & 3;
    const int bn = blockIdx.x * 128;   // fast dim = cols -> A L2 reuse
    const int bm = blockIdx.y * 128;
    const float qmul = (bn < 256) ? 0.25503482f : 1.0f;  // scale*log2(e)

    wmma::fragment<wmma::accumulator, 16, 16, 16, float> acc[4][2];
#pragma unroll
    for (int i = 0; i < 4; i++)
#pragma unroll
        for (int j = 0; j < 2; j++) wmma::fill_fragment(acc[i][j], 0.f);

    auto cp_B = [&](int s, int k0) {
        __half* Bs = smh + s * 17920 + 9216;
#pragma unroll
        for (int t = 0; t < 4; t++) {
            int idx = tid + t * 256;
            int br = idx >> 4, bc = (idx & 15) * 8;
            cp_async16(&Bs[br * 136 + bc], B + (size_t)(k0 + br) * N + bn + bc);
        }
        cp_commit();
    };
    auto ldg_sts_A = [&](int s, int k0) {
        __half* As = smh + s * 17920;
#pragma unroll
        for (int bq = 0; bq < 2; bq++) {
            float4 t[4];
#pragma unroll
            for (int i = 0; i < 4; i++) {
                int idx = tid + (bq * 4 + i) * 256;
                int r = idx >> 4, c4 = (idx & 15) * 4;
                t[i] = *(const float4*)(A + (size_t)(bm + r) * 256 + k0 + c4);
            }
#pragma unroll
            for (int i = 0; i < 4; i++) {
                int idx = tid + (bq * 4 + i) * 256;
                int r = idx >> 4, c4 = (idx & 15) * 4;
                *(__half2*)&As[r * 72 + c4]     = __floats2half2_rn(t[i].x, t[i].y);
                *(__half2*)&As[r * 72 + c4 + 2] = __floats2half2_rn(t[i].z, t[i].w);
            }
        }
    };

    cp_B(0, 0);
    cp_B(1, 64);
    ldg_sts_A(0, 0);
    ldg_sts_A(1, 64);

    const int NK = 4;
    for (int kt = 0; kt < NK; kt++) {
        if (kt == NK - 1) cp_wait0(); else cp_wait1();
        __syncthreads();
        const __half* As = smh + (kt & 1) * 17920;
        const __half* Bs = As + 9216;
#pragma unroll
        for (int kk = 0; kk < 64; kk += 16) {
            wmma::fragment<wmma::matrix_a, 16, 16, 16, __half, wmma::row_major> af[4];
            wmma::fragment<wmma::matrix_b, 16, 16, 16, __half, wmma::row_major> bf[2];
#pragma unroll
            for (int i = 0; i < 4; i++)
                wmma::load_matrix_sync(af[i], &As[(wm * 64 + i * 16) * 72 + kk], 72);
#pragma unroll
            for (int j = 0; j < 2; j++)
                wmma::load_matrix_sync(bf[j], &Bs[kk * 136 + wn * 32 + j * 16], 136);
#pragma unroll
            for (int i = 0; i < 4; i++)
#pragma unroll
                for (int j = 0; j < 2; j++)
                    wmma::mma_sync(acc[i][j], af[i], bf[j], acc[i][j]);
        }
        __syncthreads();
        if (kt + 2 < NK) {
            cp_B(kt & 1, (kt + 2) * 64);
            ldg_sts_A(kt & 1, (kt + 2) * 64);
        }
    }

    float* wb = (float*)smh + warp * 2304;
#pragma unroll
    for (int i = 0; i < 4; i++)
#pragma unroll
        for (int j = 0; j < 2; j++)
            wmma::store_matrix_sync(&wb[(i * 16) * 36 + j * 16], acc[i][j], 36,
                                    wmma::mem_row_major);
    __syncwarp();
#pragma unroll
    for (int it = 0; it < 16; it++) {
        int idx = lane + it * 32;
        int r = idx >> 3;
        int c = (idx & 7) * 4;
        float4 v = *(float4*)&wb[r * 36 + c];
        int grow = bm + wm * 64 + r;
        int gcol = bn + wn * 32 + c;
        v.x *= qmul; v.y *= qmul; v.z *= qmul; v.w *= qmul;
        __half2* d = (__half2*)&C[(size_t)grow * N + gcol];
        d[0] = __floats2half2_rn(v.x, v.y);
        d[1] = __floats2half2_rn(v.z, v.w);
    }
}

// ---------------------------------------------------------------------------
// Proj GEMM (fp16 A, fp32 out + bias).
// ---------------------------------------------------------------------------
__global__ __launch_bounds__(256, 2) void gemm_h(
    const __half* __restrict__ A, const __half* __restrict__ B,
    const float* __restrict__ bias, float* __restrict__ C, int N)
{
    extern __shared__ __half smh[];
    const int tid  = threadIdx.x;
    const int warp = tid >> 5;
    const int lane = tid & 31;
    const int wm = warp >> 2, wn = warp & 3;
    const int bn = blockIdx.x * 128;
    const int bm = blockIdx.y * 128;

    wmma::fragment<wmma::accumulator, 16, 16, 16, float> acc[4][2];
#pragma unroll
    for (int i = 0; i < 4; i++)
#pragma unroll
        for (int j = 0; j < 2; j++) wmma::fill_fragment(acc[i][j], 0.f);

    auto load_tile = [&](int s, int k0) {
        __half* As = smh + s * 17920;
        __half* Bs = As + 9216;
#pragma unroll
        for (int t = 0; t < 4; t++) {
            int idx = tid + t * 256;
            int ar = idx >> 3, ac = (idx & 7) * 8;
            cp_async16(&As[ar * 72 + ac], A + (size_t)(bm + ar) * 256 + k0 + ac);
            int br = idx >> 4, bc = (idx & 15) * 8;
            cp_async16(&Bs[br * 136 + bc], B + (size_t)(k0 + br) * N + bn + bc);
        }
        cp_commit();
    };

    load_tile(0, 0);
    const int NK = 4;
    for (int kt = 0; kt < NK; kt++) {
        if (kt + 1 < NK) { load_tile((kt + 1) & 1, (kt + 1) * 64); cp_wait1(); }
        else             { cp_wait0(); }
        __syncthreads();
        const __half* As = smh + (kt & 1) * 17920;
        const __half* Bs = As + 9216;
#pragma unroll
        for (int kk = 0; kk < 64; kk += 16) {
            wmma::fragment<wmma::matrix_a, 16, 16, 16, __half, wmma::row_major> af[4];
            wmma::fragment<wmma::matrix_b, 16, 16, 16, __half, wmma::row_major> bf[2];
#pragma unroll
            for (int i = 0; i < 4; i++)
                wmma::load_matrix_sync(af[i], &As[(wm * 64 + i * 16) * 72 + kk], 72);
#pragma unroll
            for (int j = 0; j < 2; j++)
                wmma::load_matrix_sync(bf[j], &Bs[kk * 136 + wn * 32 + j * 16], 136);
#pragma unroll
            for (int i = 0; i < 4; i++)
#pragma unroll
                for (int j = 0; j < 2; j++)
                    wmma::mma_sync(acc[i][j], af[i], bf[j], acc[i][j]);
        }
        __syncthreads();
    }

    float* wb = (float*)smh + warp * 2304;
#pragma unroll
    for (int i = 0; i < 4; i++)
#pragma unroll
        for (int j = 0; j < 2; j++)
            wmma::store_matrix_sync(&wb[(i * 16) * 36 + j * 16], acc[i][j], 36,
                                    wmma::mem_row_major);
    __syncwarp();
#pragma unroll
    for (int it = 0; it < 16; it++) {
        int idx = lane + it * 32;
        int r = idx >> 3;
        int c = (idx & 7) * 4;
        float4 v = *(float4*)&wb[r * 36 + c];
        int grow = bm + wm * 64 + r;
        int gcol = bn + wn * 32 + c;
        v.x += bias[gcol + 0]; v.y += bias[gcol + 1];
        v.z += bias[gcol + 2]; v.w += bias[gcol + 3];
        *(float4*)&C[(size_t)grow * N + gcol] = v;
    }
}

// ---------------------------------------------------------------------------
// FUSED attention v5: grid path stages ALL K/V once (40KB) -> barrier-free
// mainloop (warp-owned strips/Sh/O, register row-sums). exp2 softmax,
// q pre-scaled by GEMM.
//   blocks [0,4096) = grid heads 4..7 (2 qtiles/CTA),
//   blocks [4096,8192) = local windows heads 0..3.
// Grid smem (halfs): Q[128][40]@0, K[256][40]@5120, V[256][40]@15360,
//   Sh[2][64][72]@25600, strips 8x[16][68]f @34816 -> 104448 B, 2 CTA/SM.
// ---------------------------------------------------------------------------
__global__ __launch_bounds__(256, 2) void attn_fused(
    const __half* __restrict__ qkv, __half* __restrict__ att)
{
    extern __shared__ __half smh[];
    const int tid = threadIdx.x;
    const int warp = tid >> 5;
    const int lane = tid & 31;

    if (blockIdx.x < 4096) {
        // ================= GRID (dilated), 2 query tiles per CTA ============
        const int bid = blockIdx.x;
        const int low = bid & 7, cid = bid >> 3;
        const int b = cid >> 6, s1 = (cid >> 3) & 7, s2 = cid & 7;
        const int h = 4 + (low >> 1), qtp = low & 1;
        const int qh = warp >> 2;      // query tile within pair
        const int wl = warp & 3;       // row tile
        float* strip = (float*)(smh + 34816) + warp * 1088;

        // Stage Q (128 rows) + ALL K/V (256 rows each), one commit
#pragma unroll
        for (int i = 0; i < 2; i++) {
            int idx = tid + i * 256;
            int qrow = idx >> 2, seg = (idx & 3) * 8;
            int qq = qtp * 128 + qrow;
            size_t token = ((size_t)(b * 128 + (qq >> 4) * 8 + s1)) * 128 + (qq & 15) * 8 + s2;
            cp_async16(&smh[qrow * 40 + seg], qkv + token * 768 + h * 32 + seg);
        }
#pragma unroll
        for (int i = 0; i < 4; i++) {
            int idx = tid + i * 256;           // 0..1023
            int rk = idx >> 2, seg = (idx & 3) * 8;
            size_t ktok = ((size_t)(b * 128 + (rk >> 4) * 8 + s1)) * 128 + (rk & 15) * 8 + s2;
            const __half* base = qkv + ktok * 768 + h * 32 + seg;
            cp_async16(&smh[5120  + rk * 40 + seg], base + 256);
            cp_async16(&smh[15360 + rk * 40 + seg], base + 512);
        }
        cp_commit();
        cp_wait0();
        __syncthreads();   // the ONLY block barrier

        wmma::fragment<wmma::accumulator, 16, 16, 16, float> accO[2];
#pragma unroll
        for (int j = 0; j < 2; j++) wmma::fill_fragment(accO[j], 0.f);
        float ltot = 0.f;

        for (int ck = 0; ck < 4; ck++) {
            const __half* Kc = smh + 5120  + ck * 2560;
            const __half* Vc = smh + 15360 + ck * 2560;

            // S = Q@K^T -> own strip
            {
                wmma::fragment<wmma::matrix_a, 16, 16, 16, __half, wmma::row_major> af[2];
#pragma unroll
                for (int ki = 0; ki < 2; ki++)
                    wmma::load_matrix_sync(af[ki],
                        &smh[qh * 2560 + (wl * 16) * 40 + ki * 16], 40);
#pragma unroll
                for (int j = 0; j < 4; j++) {
                    wmma::fragment<wmma::accumulator, 16, 16, 16, float> accS;
                    wmma::fill_fragment(accS, 0.f);
#pragma unroll
                    for (int ki = 0; ki < 2; ki++) {
                        wmma::fragment<wmma::matrix_b, 16, 16, 16, __half, wmma::col_major> bf;
                        wmma::load_matrix_sync(bf, &Kc[(j * 16) * 40 + ki * 16], 40);
                        wmma::mma_sync(accS, af[ki], bf, accS);
                    }
                    wmma::store_matrix_sync(&strip[j * 16], accS, 68, wmma::mem_row_major);
                }
            }
            __syncwarp();
            // convert (exp2) + register row-sum (both lanes of pair keep it)
            {
                int r = lane >> 1, cs = (lane & 1) * 32;
                const float* sp = strip + r * 68 + cs;
                __half2 hv[16];
                float s = 0.f;
#pragma unroll
                for (int e = 0; e < 16; e++) {
                    hv[e] = h2exp2(__floats2half2_rn(sp[2 * e], sp[2 * e + 1]));
                    float2 f = __half22float2(hv[e]);
                    s += f.x + f.y;
                }
                uint4* dst = (uint4*)&smh[25600 + qh * 4608 + (wl * 16 + r) * 72 + cs];
#pragma unroll
                for (int u = 0; u < 4; u++) dst[u] = ((uint4*)hv)[u];
                s += __shfl_xor_sync(0xffffffffu, s, 1);
                ltot += s;
            }
            __syncwarp();

            // O += P @ V (own Sh rows)
#pragma unroll
            for (int ks = 0; ks < 4; ks++) {
                int kk = ks * 16;
                wmma::fragment<wmma::matrix_a, 16, 16, 16, __half, wmma::row_major> af;
                wmma::load_matrix_sync(af,
                    &smh[25600 + qh * 4608 + (wl * 16) * 72 + kk], 72);
#pragma unroll
                for (int j = 0; j < 2; j++) {
                    wmma::fragment<wmma::matrix_b, 16, 16, 16, __half, wmma::row_major> bf;
                    wmma::load_matrix_sync(bf, &Vc[kk * 40 + j * 16], 40);
                    wmma::mma_sync(accO[j], af, bf, accO[j]);
                }
            }
            __syncwarp();
        }

#pragma unroll
        for (int j = 0; j < 2; j++)
            wmma::store_matrix_sync(&strip[j * 16], accO[j], 68, wmma::mem_row_major);
        __syncwarp();
        {
            int r = lane >> 1, c0 = (lane & 1) * 16;
            float inv = 1.f / ltot;
            const float* sp = strip + r * 68 + c0;
            int qq = qtp * 128 + qh * 64 + wl * 16 + r;
            size_t token = ((size_t)(b * 128 + (qq >> 4) * 8 + s1)) * 128 + (qq & 15) * 8 + s2;
            __half2 o[8];
#pragma unroll
            for (int e = 0; e < 8; e++)
                o[e] = __floats2half2_rn(sp[2 * e] * inv, sp[2 * e + 1] * inv);
            uint4* d = (uint4*)&att[token * 256 + h * 32 + c0];
            d[0] = ((uint4*)o)[0];
            d[1] = ((uint4*)o)[1];
        }
    } else {
        // ================= LOCAL window attention (2 heads per CTA) =========
        const int lb = blockIdx.x - 4096;
        const int wid = lb >> 1, hp = lb & 1;
        const int b = wid >> 8, wy = (wid >> 4) & 15, wx = wid & 15;
        const int hh = warp >> 2, wl = warp & 3;
        float* strip = (float*)(smh + 24576) + warp * 1088;

#pragma unroll
        for (int i = 0; i < 2; i++) {
            int idx = tid + i * 256;
            int h2 = idx >> 8;
            int r  = (idx >> 2) & 63;
            int seg = (idx & 3) * 8;
            int hg = hp * 2 + h2;
            size_t token = ((size_t)(b * 128 + wy * 8 + (r >> 3))) * 128 + wx * 8 + (r & 7);
            const __half* base = qkv + token * 768 + hg * 32 + seg;
            __half* hb = smh + h2 * 7680;
            cp_async16(&hb[r * 40 + seg], base);
            cp_async16(&hb[2560 + r * 40 + seg], base + 256);
            cp_async16(&hb[5120 + r * 40 + seg], base + 512);
        }
        cp_commit();
        cp_wait0();
        __syncthreads();   // the ONLY block barrier

        const __half* Qh = smh + hh * 7680;
        const __half* Kh = Qh + 2560;
        const __half* Vh = Qh + 5120;
        float ltot;

        {   // S = Q@K^T -> own strip
            wmma::fragment<wmma::matrix_a, 16, 16, 16, __half, wmma::row_major> af[2];
#pragma unroll
            for (int ki = 0; ki < 2; ki++)
                wmma::load_matrix_sync(af[ki], &Qh[(wl * 16) * 40 + ki * 16], 40);
#pragma unroll
            for (int j = 0; j < 4; j++) {
                wmma::fragment<wmma::accumulator, 16, 16, 16, float> accS;
                wmma::fill_fragment(accS, 0.f);
#pragma unroll
                for (int ki = 0; ki < 2; ki++) {
                    wmma::fragment<wmma::matrix_b, 16, 16, 16, __half, wmma::col_major> bf;
                    wmma::load_matrix_sync(bf, &Kh[(j * 16) * 40 + ki * 16], 40);
                    wmma::mma_sync(accS, af[ki], bf, accS);
                }
                wmma::store_matrix_sync(&strip[j * 16], accS, 68, wmma::mem_row_major);
            }
        }
        __syncwarp();
        {   // convert (exp2) + register row-sum
            int r = lane >> 1, cs = (lane & 1) * 32;
            const float* sp = strip + r * 68 + cs;
            __half2 hv[16];
            float s = 0.f;
#pragma unroll
            for (int e = 0; e < 16; e++) {
                hv[e] = h2exp2(__floats2half2_rn(sp[2 * e], sp[2 * e + 1]));
                float2 f = __half22float2(hv[e]);
                s += f.x + f.y;
            }
            uint4* dst = (uint4*)&smh[15360 + hh * 4608 + (wl * 16 + r) * 72 + cs];
#pragma unroll
            for (int u = 0; u < 4; u++) dst[u] = ((uint4*)hv)[u];
            s += __shfl_xor_sync(0xffffffffu, s, 1);
            ltot = s;
        }
        __syncwarp();

        {   // O = P @ V (own Sh rows) -> own strip
            wmma::fragment<wmma::accumulator, 16, 16, 16, float> accO[2];
#pragma unroll
            for (int j = 0; j < 2; j++) wmma::fill_fragment(accO[j], 0.f);
#pragma unroll
            for (int ks = 0; ks < 4; ks++) {
                int kk = ks * 16;
                wmma::fragment<wmma::matrix_a, 16, 16, 16, __half, wmma::row_major> af;
                wmma::load_matrix_sync(af,
                    &smh[15360 + hh * 4608 + (wl * 16) * 72 + kk], 72);
#pragma unroll
                for (int j = 0; j < 2; j++) {
                    wmma::fragment<wmma::matrix_b, 16, 16, 16, __half, wmma::row_major> bf;
                    wmma::load_matrix_sync(bf, &Vh[kk * 40 + j * 16], 40);
                    wmma::mma_sync(accO[j], af, bf, accO[j]);
                }
            }
#pragma unroll
            for (int j = 0; j < 2; j++)
                wmma::store_matrix_sync(&strip[j * 16], accO[j], 68, wmma::mem_row_major);
        }
        __syncwarp();

        {   // per-warp writeout of its 16x32 block
            int r = lane >> 1, c0 = (lane & 1) * 16;
            float inv = 1.f / ltot;
            const float* sp = strip + r * 68 + c0;
            int rg = wl * 16 + r;
            int hg = hp * 2 + hh;
            size_t token = ((size_t)(b * 128 + wy * 8 + (rg >> 3))) * 128 + wx * 8 + (rg & 7);
            __half2 o[8];
#pragma unroll
            for (int e = 0; e < 8; e++)
                o[e] = __floats2half2_rn(sp[2 * e] * inv, sp[2 * e + 1] * inv);
            uint4* d = (uint4*)&att[token * 256 + hg * 32 + c0];
            d[0] = ((uint4*)o)[0];
            d[1] = ((uint4*)o)[1];
        }
    }
}

// ---------------------------------------------------------------------------
extern "C" void kernel_launch(void* const* d_in, const int* in_sizes, int n_in,
                              void* d_out, int out_size)
{
    (void)in_sizes; (void)n_in; (void)out_size;
    const float* x     = (const float*)d_in[0];
    const float* Wqkv  = (const float*)d_in[1];
    const float* Wproj = (const float*)d_in[2];
    const float* bproj = (const float*)d_in[3];
    float* out = (float*)d_out;

    __half *qkv = nullptr, *att = nullptr, *wq = nullptr, *wp = nullptr;
    cudaGetSymbolAddress((void**)&qkv, g_qkv);
    cudaGetSymbolAddress((void**)&att, g_att);
    cudaGetSymbolAddress((void**)&wq,  g_wq);
    cudaGetSymbolAddress((void**)&wp,  g_wp);

    cudaFuncSetAttribute(gemm_qkv, cudaFuncAttributeMaxDynamicSharedMemorySize, 73728);
    cudaFuncSetAttribute(gemm_h, cudaFuncAttributeMaxDynamicSharedMemorySize, 73728);
    cudaFuncSetAttribute(attn_fused, cudaFuncAttributeMaxDynamicSharedMemorySize, 104448);

    // 0) convert weights to fp16 (x converted inside gemm_qkv staging)
    cvt_w<<<1024, 256>>>(Wqkv, Wproj, wq, wp);
    // 1) QKV = x @ W_qkv  (fp32 A fused-convert; q cols pre-scaled; fp16 out)
    gemm_qkv<<<dim3(6, 1024), 256, 73728>>>(x, wq, qkv, 768);
    // 2+3) fused attention v5: grid [0,4096) + local [4096,8192)
    attn_fused<<<8192, 256, 104448>>>(qkv, att);
    // 4) out = att @ W_proj + b_proj (fp32 out)
    gemm_h<<<dim3(2, 1024), 256, 73728>>>(att, wp, bproj, out, 256);
}